// round 6
// baseline (speedup 1.0000x reference)
#include <cuda_runtime.h>
#include <cuda_bf16.h>
#include <cstdint>

// ---------------------------------------------------------------------------
// GLACrossAttention: B=2 QL=1024 KL=4096 HID=2048 H=16 HD=128 RD=64
//                    G=4 HPG=4 QLR=512 LAT=256 EPS=1e-6
// Round 5: resubmit of round 4 (round-5 bench died to broker infra failure,
//          no kernel signal). tcgen05 GEMMs guarded by arch-feature macros;
//          FFMA SIMT fallback for non-'a' targets. fp32 flash attention.
// ---------------------------------------------------------------------------

#if defined(__CUDA_ARCH__)
#  if defined(__CUDA_ARCH_FEAT_SM103_ALL) || defined(__CUDA_ARCH_FEAT_SM100_ALL)
#    define HAS_TCGEN05 1
#  elif defined(__CUDA_ARCH_SPECIFIC__) && (__CUDA_ARCH_SPECIFIC__ == 1030 || __CUDA_ARCH_SPECIFIC__ == 1000)
#    define HAS_TCGEN05 1
#  else
#    define HAS_TCGEN05 0
#  endif
#else
#  define HAS_TCGEN05 0
#endif

#define B_    2
#define QL_   1024
#define KL_   4096
#define HID_  2048
#define H_    16
#define HD_   128
#define RD_   64
#define G_    4
#define QLR_  512
#define LAT_  256
#define EPS_  1e-6f

// ---------------------------------------------------------------------------
// PTX helpers
// ---------------------------------------------------------------------------
__device__ __forceinline__ uint32_t smem_u32(const void* p) {
    uint32_t a;
    asm("{ .reg .u64 t; cvta.to.shared.u64 t, %1; cvt.u32.u64 %0, t; }"
        : "=r"(a) : "l"(p));
    return a;
}
__device__ __forceinline__ uint32_t elect_one_pred() {
    uint32_t pred;
    asm volatile("{\n\t.reg .pred p;\n\telect.sync _|p, 0xFFFFFFFF;\n\t"
                 "selp.b32 %0, 1, 0, p;\n\t}" : "=r"(pred));
    return pred;
}
#define MBARRIER_INIT(addr, cnt) \
    asm volatile("mbarrier.init.shared.b64 [%0], %1;" :: "r"((uint32_t)(addr)), "r"((uint32_t)(cnt)) : "memory")
#define MBARRIER_INVAL(addr) \
    asm volatile("mbarrier.inval.shared.b64 [%0];" :: "r"((uint32_t)(addr)) : "memory")
#define MBARRIER_WAIT_PARITY(mbar_smem_addr, phase_parity) do { \
    uint32_t _mbar = (uint32_t)(mbar_smem_addr); \
    uint32_t _parity = (uint32_t)(phase_parity); \
    uint32_t _done; \
    asm volatile("{\n\t.reg .pred p;\n\t" \
        "mbarrier.try_wait.parity.acquire.cta.shared::cta.b64 p, [%1], %2;\n\t" \
        "selp.b32 %0, 1, 0, p;\n\t}" \
        : "=r"(_done) : "r"(_mbar), "r"(_parity) : "memory"); \
    if (!_done) { \
        asm volatile("{\n\t.reg .pred P1;\n\t" \
            "WAIT_LOOP_%=:\n\t" \
            "mbarrier.try_wait.parity.acquire.cta.shared::cta.b64 P1, [%0], %1, 0x989680;\n\t" \
            "@P1 bra.uni WAIT_DONE_%=;\n\t" \
            "bra.uni WAIT_LOOP_%=;\n\t" \
            "WAIT_DONE_%=:\n\t}" \
            :: "r"(_mbar), "r"(_parity) : "memory"); \
    } \
} while(0)

#if HAS_TCGEN05
#define TCGEN05_ALLOC(smem_result_addr, nCols) \
    asm volatile("tcgen05.alloc.cta_group::1.sync.aligned.shared::cta.b32 [%0], %1;" \
        :: "r"((uint32_t)(smem_result_addr)), "r"((uint32_t)(nCols)) : "memory")
#define TCGEN05_DEALLOC(tmem_addr, nCols) \
    asm volatile("tcgen05.dealloc.cta_group::1.sync.aligned.b32 %0, %1;" \
        :: "r"(tmem_addr), "r"((uint32_t)(nCols)))
#define TCGEN05_RELINQUISH() \
    asm volatile("tcgen05.relinquish_alloc_permit.cta_group::1.sync.aligned;")
#define TCGEN05_COMMIT(mbar_smem_addr) \
    asm volatile("tcgen05.commit.cta_group::1.mbarrier::arrive::one.shared::cluster.b64 [%0];" \
        :: "r"((uint32_t)(mbar_smem_addr)) : "memory")
#define TCGEN05_FENCE_AFTER() \
    asm volatile("tcgen05.fence::after_thread_sync;" ::: "memory")
#define TCGEN05_FENCE_BEFORE() \
    asm volatile("tcgen05.fence::before_thread_sync;" ::: "memory")
#define TCGEN05_WAIT_LD() \
    asm volatile("tcgen05.wait::ld.sync.aligned;" ::: "memory")
#define TCGEN05_LD_32X32B_X32(r, tmem_addr) \
    asm volatile("tcgen05.ld.sync.aligned.32x32b.x32.b32 " \
        "{%0, %1, %2, %3, %4, %5, %6, %7, " \
        " %8, %9, %10, %11, %12, %13, %14, %15, " \
        " %16, %17, %18, %19, %20, %21, %22, %23, " \
        " %24, %25, %26, %27, %28, %29, %30, %31}, [%32];" \
        : "=r"((r)[0]),  "=r"((r)[1]),  "=r"((r)[2]),  "=r"((r)[3]), \
          "=r"((r)[4]),  "=r"((r)[5]),  "=r"((r)[6]),  "=r"((r)[7]), \
          "=r"((r)[8]),  "=r"((r)[9]),  "=r"((r)[10]), "=r"((r)[11]), \
          "=r"((r)[12]), "=r"((r)[13]), "=r"((r)[14]), "=r"((r)[15]), \
          "=r"((r)[16]), "=r"((r)[17]), "=r"((r)[18]), "=r"((r)[19]), \
          "=r"((r)[20]), "=r"((r)[21]), "=r"((r)[22]), "=r"((r)[23]), \
          "=r"((r)[24]), "=r"((r)[25]), "=r"((r)[26]), "=r"((r)[27]), \
          "=r"((r)[28]), "=r"((r)[29]), "=r"((r)[30]), "=r"((r)[31]) \
        : "r"(tmem_addr))

// cg1 kind::f16 SS MMA (bf16 operands in SMEM, fp32 acc in TMEM)
__device__ __forceinline__ void mma_bf16_ss(uint32_t d, uint64_t a_desc, uint64_t b_desc,
                                            uint32_t idesc, bool acc) {
    uint32_t en = acc ? 1u : 0u;
    asm volatile("{\n\t.reg .pred p;\n\tsetp.ne.u32 p, %5, 0;\n\t"
        "tcgen05.mma.cta_group::1.kind::f16 [%0], %1, %2, %3, {%4, %4, %4, %4}, p;\n\t}"
        :: "r"(d), "l"(a_desc), "l"(b_desc), "r"(idesc), "r"(0u), "r"(en) : "memory");
}
#endif  // HAS_TCGEN05

// SW128 K-major smem descriptor (verified constants from examples)
static constexpr uint64_t SMEM_DESC_BASE_SW128 =
    (uint64_t(2)  << 61) | (uint64_t(1) << 46) | (uint64_t(64) << 32) | (uint64_t(1) << 16);
#define MAKE_SMEM_DESC(base_addr) \
    (SMEM_DESC_BASE_SW128 | ((uint64_t)((base_addr) >> 4) & 0x3FFF))
#define SW128(o) ((o) ^ (((o) >> 3) & 0x70))

__device__ __forceinline__ void cpa16(uint32_t dst, const void* src) {
    asm volatile("cp.async.cg.shared.global [%0], [%1], 16;\n" :: "r"(dst), "l"(src));
}
__device__ __forceinline__ void cpa_commit_wait() {
    asm volatile("cp.async.commit_group;\n" ::: "memory");
    asm volatile("cp.async.wait_group 0;\n" ::: "memory");
}

// ---------------------------------------------------------------------------
// Scratch (device globals; allocation-free contract)
// ---------------------------------------------------------------------------
__device__ float g_qlat [B_*QL_*QLR_];
__device__ float g_qfull[B_*QL_*H_*(HD_+RD_)];
__device__ float g_ckv  [B_*KL_*G_*LAT_];
__device__ float g_kv   [(size_t)B_*KL_*H_*2*HD_];
__device__ float g_attn [B_*QL_*H_*HD_];

// split-bf16 activations
__device__ __nv_bfloat16 g_xq_h [B_*QL_*HID_],   g_xq_l [B_*QL_*HID_];
__device__ __nv_bfloat16 g_xkv_h[B_*KL_*HID_],   g_xkv_l[B_*KL_*HID_];
__device__ __nv_bfloat16 g_qn_h [B_*QL_*QLR_],   g_qn_l [B_*QL_*QLR_];
__device__ __nv_bfloat16 g_ckvn_h[B_*KL_*G_*LAT_], g_ckvn_l[B_*KL_*G_*LAT_];
__device__ __nv_bfloat16 g_at_h [B_*QL_*H_*HD_], g_at_l [B_*QL_*H_*HD_];
// split-bf16 transposed weights  (B operand must be [N rows][K cols])
__device__ __nv_bfloat16 g_wdq_h [QLR_*HID_],     g_wdq_l [QLR_*HID_];
__device__ __nv_bfloat16 g_wuq_h [3072*QLR_],     g_wuq_l [3072*QLR_];
__device__ __nv_bfloat16 g_wdkv_h[1024*HID_],     g_wdkv_l[1024*HID_];
__device__ __nv_bfloat16 g_wukv_h[G_*1024*LAT_],  g_wukv_l[G_*1024*LAT_];
__device__ __nv_bfloat16 g_wo_h  [HID_*HID_],     g_wo_l  [HID_*HID_];

// ---------------------------------------------------------------------------
// split fp32 -> (hi, lo) bf16, vectorized by 4
// ---------------------------------------------------------------------------
__global__ __launch_bounds__(256) void split_f32(
    const float* __restrict__ src, __nv_bfloat16* __restrict__ h,
    __nv_bfloat16* __restrict__ l, int n4)
{
    int i = blockIdx.x * 256 + threadIdx.x;
    if (i >= n4) return;
    float4 v = ((const float4*)src)[i];
    __nv_bfloat16 h0 = __float2bfloat16(v.x), h1 = __float2bfloat16(v.y);
    __nv_bfloat16 h2 = __float2bfloat16(v.z), h3 = __float2bfloat16(v.w);
    __nv_bfloat16 l0 = __float2bfloat16(v.x - __bfloat162float(h0));
    __nv_bfloat16 l1 = __float2bfloat16(v.y - __bfloat162float(h1));
    __nv_bfloat16 l2 = __float2bfloat16(v.z - __bfloat162float(h2));
    __nv_bfloat16 l3 = __float2bfloat16(v.w - __bfloat162float(h3));
    ((__nv_bfloat162*)h)[2*i]   = __nv_bfloat162(h0, h1);
    ((__nv_bfloat162*)h)[2*i+1] = __nv_bfloat162(h2, h3);
    ((__nv_bfloat162*)l)[2*i]   = __nv_bfloat162(l0, l1);
    ((__nv_bfloat162*)l)[2*i+1] = __nv_bfloat162(l2, l3);
}

// ---------------------------------------------------------------------------
// transpose + split: src fp32 [R, >=C] (ldS) -> dst bf16 [C, R] hi/lo (ldD=R)
// grid (C/32, R/32, batches), block (32, 8)
// ---------------------------------------------------------------------------
__global__ __launch_bounds__(256) void transpose_split(
    const float* __restrict__ src, int ldS, long sBatch,
    __nv_bfloat16* __restrict__ dh, __nv_bfloat16* __restrict__ dl,
    int ldD, long dBatch)
{
    src += (long)blockIdx.z * sBatch;
    dh  += (long)blockIdx.z * dBatch;
    dl  += (long)blockIdx.z * dBatch;
    __shared__ float t[32][33];
    const int tx = threadIdx.x, ty = threadIdx.y;
    const int c0 = blockIdx.x * 32, r0 = blockIdx.y * 32;
#pragma unroll
    for (int i = 0; i < 4; i++)
        t[ty + i * 8][tx] = src[(long)(r0 + ty + i * 8) * ldS + c0 + tx];
    __syncthreads();
#pragma unroll
    for (int i = 0; i < 4; i++) {
        float v = t[tx][ty + i * 8];
        __nv_bfloat16 hi = __float2bfloat16(v);
        __nv_bfloat16 lo = __float2bfloat16(v - __bfloat162float(hi));
        long o = (long)(c0 + ty + i * 8) * ldD + r0 + tx;
        dh[o] = hi; dl[o] = lo;
    }
}

// ---------------------------------------------------------------------------
// split-bf16 GEMM: C[M,N] fp32 = A[M,K] @ B^T[N,K]
// A hi/lo bf16 [M,K] (rows K-contig), B hi/lo bf16 [N,K].
// Tile 128(M) x 256(N). grid: (N/256, M/128, batches), block 256.
// HAS_TCGEN05: K-chunk 64, double-buffered cp.async, SS MMA, fp32 acc in TMEM.
// else:        FFMA SIMT fallback (two 128x128 halves, 8x8 microtile).
// ---------------------------------------------------------------------------
#define TM 128
#define TN 256
#define KC 64
#define SM_TMEM  0
#define SM_MBAR  8           // two mbarriers: +8, +16
#define SM_DATA  1024
#define OFF_AH   0
#define OFF_AL   (16*1024)
#define OFF_BH   (32*1024)
#define OFF_BL   (64*1024)
#define STAGE_BYTES (96*1024)
#define GEMM_SMEM (1024 + 2*STAGE_BYTES)
static constexpr uint32_t GEMM_IDESC =
    (1u << 4) | (1u << 7) | (1u << 10) | ((TN / 8) << 17) | ((TM / 16) << 24);

__global__ __launch_bounds__(256)
void gemm_tc(const __nv_bfloat16* __restrict__ Ah, const __nv_bfloat16* __restrict__ Al,
             int lda, long aBatch,
             const __nv_bfloat16* __restrict__ Bh, const __nv_bfloat16* __restrict__ Bl,
             int ldb, long bBatch,
             float* __restrict__ C, int ldc, long cBatch,
             int K)
{
    extern __shared__ __align__(1024) char smem_dyn[];
    const int tid = threadIdx.x;

    Ah += (long)blockIdx.z * aBatch;  Al += (long)blockIdx.z * aBatch;
    Bh += (long)blockIdx.z * bBatch;  Bl += (long)blockIdx.z * bBatch;
    C  += (long)blockIdx.z * cBatch;
    const int rowBase = blockIdx.y * TM;
    const int colBase = blockIdx.x * TN;

#if HAS_TCGEN05
    const int wid = tid >> 5;
    uint32_t sb = smem_u32(smem_dyn);
    if (wid == 0) TCGEN05_ALLOC(sb + SM_TMEM, 256);
    if (tid == 0) { MBARRIER_INIT(sb + SM_MBAR, 1); MBARRIER_INIT(sb + SM_MBAR + 8, 1); }
    __syncthreads();
    uint32_t tmem;
    asm volatile("ld.shared.b32 %0, [%1];" : "=r"(tmem) : "r"(sb + SM_TMEM));

    int pc0 = 0, pc1 = 0;
    const int nChunks = K / KC;

    for (int c = 0; c < nChunks; c++) {
        const int s = c & 1;
        const uint32_t stage = sb + SM_DATA + s * STAGE_BYTES;
        if (c >= 2) {
            if (s == 0) { MBARRIER_WAIT_PARITY(sb + SM_MBAR,     pc0 & 1); pc0++; }
            else        { MBARRIER_WAIT_PARITY(sb + SM_MBAR + 8, pc1 & 1); pc1++; }
        }
        const int k0 = c * KC;
        // A tiles: 128 rows x 128B (hi & lo)
#pragma unroll
        for (int i = 0; i < 4; i++) {
            int idx = tid + i * 256;
            int r = idx >> 3, c16 = idx & 7;
            uint32_t sw = SW128((uint32_t)(r * 128 + c16 * 16));
            size_t go = (size_t)(rowBase + r) * lda + k0 + c16 * 8;
            cpa16(stage + OFF_AH + sw, Ah + go);
            cpa16(stage + OFF_AL + sw, Al + go);
        }
        // B tiles: 256 rows x 128B (hi & lo)
#pragma unroll
        for (int i = 0; i < 8; i++) {
            int idx = tid + i * 256;
            int r = idx >> 3, c16 = idx & 7;
            uint32_t sw = SW128((uint32_t)(r * 128 + c16 * 16));
            size_t go = (size_t)(colBase + r) * ldb + k0 + c16 * 8;
            cpa16(stage + OFF_BH + sw, Bh + go);
            cpa16(stage + OFF_BL + sw, Bl + go);
        }
        cpa_commit_wait();
        asm volatile("fence.proxy.async.shared::cta;" ::: "memory");
        __syncthreads();

        if (wid == 0) {
            if (elect_one_pred()) {
                uint64_t adh = MAKE_SMEM_DESC(stage + OFF_AH);
                uint64_t adl = MAKE_SMEM_DESC(stage + OFF_AL);
                uint64_t bdh = MAKE_SMEM_DESC(stage + OFF_BH);
                uint64_t bdl = MAKE_SMEM_DESC(stage + OFF_BL);
#pragma unroll
                for (int ks = 0; ks < 4; ks++)      // hi * hi
                    mma_bf16_ss(tmem, adh + ks * 2, bdh + ks * 2, GEMM_IDESC,
                                !(c == 0 && ks == 0));
#pragma unroll
                for (int ks = 0; ks < 4; ks++)      // hi * lo
                    mma_bf16_ss(tmem, adh + ks * 2, bdl + ks * 2, GEMM_IDESC, true);
#pragma unroll
                for (int ks = 0; ks < 4; ks++)      // lo * hi
                    mma_bf16_ss(tmem, adl + ks * 2, bdh + ks * 2, GEMM_IDESC, true);
                TCGEN05_COMMIT(sb + SM_MBAR + 8 * s);
            }
        }
    }
    // wait for final chunk's commit (covers all prior MMAs)
    {
        const int s = (nChunks - 1) & 1;
        if (s == 0) MBARRIER_WAIT_PARITY(sb + SM_MBAR,     pc0 & 1);
        else        MBARRIER_WAIT_PARITY(sb + SM_MBAR + 8, pc1 & 1);
    }
    TCGEN05_FENCE_AFTER();

    // epilogue: warps 0-3 read their 32-lane subpartition (row = wid*32+lane)
    if (wid < 4) {
        const int row = rowBase + wid * 32 + (tid & 31);
#pragma unroll
        for (int cc = 0; cc < 8; cc++) {
            uint32_t regs[32];
            TCGEN05_LD_32X32B_X32(regs, tmem + cc * 32);
            TCGEN05_WAIT_LD();
            float4* dst = (float4*)(C + (size_t)row * ldc + colBase + cc * 32);
            const float4* srcv = (const float4*)regs;
#pragma unroll
            for (int j = 0; j < 8; j++) dst[j] = srcv[j];
        }
        TCGEN05_FENCE_BEFORE();
    }
    __syncthreads();
    if (tid == 0) { MBARRIER_INVAL(sb + SM_MBAR); MBARRIER_INVAL(sb + SM_MBAR + 8); }
    if (wid == 0) {
        TCGEN05_RELINQUISH();
        TCGEN05_DEALLOC(tmem, 256);
    }

#else  // ----------------- FFMA SIMT fallback ------------------------------
    float* As = (float*)smem_dyn;            // [128][17]
    float* Bs = As + 128 * 17;               // [128][17]
    const int tx = tid & 15;
    const int ty = tid >> 4;

    for (int half = 0; half < 2; half++) {
        const int colB2 = colBase + half * 128;
        float acc[8][8];
#pragma unroll
        for (int i = 0; i < 8; i++)
#pragma unroll
            for (int j = 0; j < 8; j++) acc[i][j] = 0.f;

        for (int k0 = 0; k0 < K; k0 += 16) {
            __syncthreads();
#pragma unroll
            for (int i = 0; i < 8; i++) {
                int idx = tid + i * 256;
                int r = idx >> 4, kk = idx & 15;
                size_t goA = (size_t)(rowBase + r) * lda + k0 + kk;
                As[r * 17 + kk] = __bfloat162float(Ah[goA]) + __bfloat162float(Al[goA]);
                size_t goB = (size_t)(colB2 + r) * ldb + k0 + kk;
                Bs[r * 17 + kk] = __bfloat162float(Bh[goB]) + __bfloat162float(Bl[goB]);
            }
            __syncthreads();
#pragma unroll
            for (int k = 0; k < 16; k++) {
                float a[8], b[8];
#pragma unroll
                for (int i = 0; i < 8; i++) a[i] = As[(ty * 8 + i) * 17 + k];
#pragma unroll
                for (int j = 0; j < 8; j++) b[j] = Bs[(tx * 8 + j) * 17 + k];
#pragma unroll
                for (int i = 0; i < 8; i++)
#pragma unroll
                    for (int j = 0; j < 8; j++)
                        acc[i][j] = fmaf(a[i], b[j], acc[i][j]);
            }
        }
#pragma unroll
        for (int i = 0; i < 8; i++)
#pragma unroll
            for (int j = 0; j < 8; j++)
                C[(size_t)(rowBase + ty * 8 + i) * ldc + colB2 + tx * 8 + j] = acc[i][j];
    }
#endif
}

// ---------------------------------------------------------------------------
// RMSNorm over 512 cols (q path) -> split bf16. grid = B*QL, block 256.
// ---------------------------------------------------------------------------
__global__ __launch_bounds__(256) void rmsnorm_q_split(
    const float* __restrict__ x, const float* __restrict__ w,
    __nv_bfloat16* __restrict__ oh, __nv_bfloat16* __restrict__ ol)
{
    const float* p = x + (long)blockIdx.x * QLR_;
    const int t = threadIdx.x;
    float v0 = p[t], v1 = p[t + 256];
    __shared__ float red[256];
    red[t] = v0 * v0 + v1 * v1;
    __syncthreads();
    for (int s = 128; s > 0; s >>= 1) {
        if (t < s) red[t] += red[t + s];
        __syncthreads();
    }
    float inv = rsqrtf(red[0] * (1.f / QLR_) + EPS_);
    long base = (long)blockIdx.x * QLR_;
    float y0 = v0 * inv * w[t], y1 = v1 * inv * w[t + 256];
    __nv_bfloat16 h0 = __float2bfloat16(y0), h1 = __float2bfloat16(y1);
    oh[base + t]       = h0;
    oh[base + t + 256] = h1;
    ol[base + t]       = __float2bfloat16(y0 - __bfloat162float(h0));
    ol[base + t + 256] = __float2bfloat16(y1 - __bfloat162float(h1));
}

// ---------------------------------------------------------------------------
// RMSNorm over LAT=256 per (row, group) -> split bf16. grid = B*KL*G, block 256.
// ---------------------------------------------------------------------------
__global__ __launch_bounds__(256) void rmsnorm_kv_split(
    const float* __restrict__ x, const float* __restrict__ w,
    __nv_bfloat16* __restrict__ oh, __nv_bfloat16* __restrict__ ol)
{
    const int row = blockIdx.x >> 2;
    const int g   = blockIdx.x & 3;
    const long base = (long)row * (G_ * LAT_) + g * LAT_;
    const int t = threadIdx.x;
    float v = x[base + t];
    __shared__ float red[256];
    red[t] = v * v;
    __syncthreads();
    for (int s = 128; s > 0; s >>= 1) {
        if (t < s) red[t] += red[t + s];
        __syncthreads();
    }
    float inv = rsqrtf(red[0] * (1.f / LAT_) + EPS_);
    float y = v * inv * w[g * LAT_ + t];
    __nv_bfloat16 h = __float2bfloat16(y);
    oh[base + t] = h;
    ol[base + t] = __float2bfloat16(y - __bfloat162float(h));
}

// ---------------------------------------------------------------------------
// Flash attention, fp32, online softmax (unchanged from passing baseline).
// ---------------------------------------------------------------------------
#define QT 64
#define KT 64
#define RSTR 129
#define PSTR 65
#define FLASH_SMEM ((3 * QT * RSTR + QT * PSTR) * 4)

__global__ __launch_bounds__(256) void flash_attn(
    const float* __restrict__ qfull,
    const float* __restrict__ kv,
    float* __restrict__ out)
{
    extern __shared__ float sm[];
    float* Qs = sm;
    float* Ks = Qs + QT * RSTR;
    float* Vs = Ks + KT * RSTR;
    float* Ps = Vs + KT * RSTR;

    const int tid = threadIdx.x;
    const int tx = tid & 15;
    const int ty = tid >> 4;
    const int b = blockIdx.y >> 4;
    const int h = blockIdx.y & 15;
    const int q0 = blockIdx.x * QT;

    for (int i = tid; i < QT * HD_; i += 256) {
        int r = i >> 7, d = i & 127;
        Qs[r * RSTR + d] =
            qfull[(long)(b * QL_ + q0 + r) * (H_ * (HD_ + RD_)) + h * (HD_ + RD_) + d];
    }

    float acc[4][8];
#pragma unroll
    for (int i = 0; i < 4; i++)
#pragma unroll
        for (int j = 0; j < 8; j++) acc[i][j] = 0.f;
    float mrow[4], lrow[4];
#pragma unroll
    for (int i = 0; i < 4; i++) { mrow[i] = -1e30f; lrow[i] = 0.f; }

    const float scale = 0.08838834764831845f;

    for (int kt = 0; kt < KL_ / KT; kt++) {
        __syncthreads();
        for (int i = tid; i < KT * HD_; i += 256) {
            int c = i >> 7, d = i & 127;
            long base = (long)(b * KL_ + kt * KT + c) * (H_ * 2 * HD_) + h * (2 * HD_);
            Ks[c * RSTR + d] = kv[base + d];
            Vs[c * RSTR + d] = kv[base + HD_ + d];
        }
        __syncthreads();

        float s[4][4];
#pragma unroll
        for (int i = 0; i < 4; i++)
#pragma unroll
            for (int j = 0; j < 4; j++) s[i][j] = 0.f;
        for (int d = 0; d < HD_; d++) {
            float qv[4], kk[4];
#pragma unroll
            for (int i = 0; i < 4; i++) qv[i] = Qs[(ty * 4 + i) * RSTR + d];
#pragma unroll
            for (int j = 0; j < 4; j++) kk[j] = Ks[(tx * 4 + j) * RSTR + d];
#pragma unroll
            for (int i = 0; i < 4; i++)
#pragma unroll
                for (int j = 0; j < 4; j++) s[i][j] = fmaf(qv[i], kk[j], s[i][j]);
        }

#pragma unroll
        for (int i = 0; i < 4; i++) {
            float mt = -1e30f;
#pragma unroll
            for (int j = 0; j < 4; j++) { s[i][j] *= scale; mt = fmaxf(mt, s[i][j]); }
            for (int off = 1; off < 16; off <<= 1)
                mt = fmaxf(mt, __shfl_xor_sync(0xffffffffu, mt, off));
            float mnew = fmaxf(mrow[i], mt);
            float corr = __expf(mrow[i] - mnew);
            mrow[i] = mnew;
            float ps = 0.f;
#pragma unroll
            for (int j = 0; j < 4; j++) {
                float p = __expf(s[i][j] - mnew);
                s[i][j] = p; ps += p;
            }
            for (int off = 1; off < 16; off <<= 1)
                ps += __shfl_xor_sync(0xffffffffu, ps, off);
            lrow[i] = lrow[i] * corr + ps;
#pragma unroll
            for (int j = 0; j < 8; j++) acc[i][j] *= corr;
#pragma unroll
            for (int j = 0; j < 4; j++)
                Ps[(ty * 4 + i) * PSTR + tx * 4 + j] = s[i][j];
        }
        __syncthreads();

        for (int kc = 0; kc < KT; kc++) {
            float vv[8];
#pragma unroll
            for (int j = 0; j < 8; j++) vv[j] = Vs[kc * RSTR + tx * 8 + j];
#pragma unroll
            for (int i = 0; i < 4; i++) {
                float p = Ps[(ty * 4 + i) * PSTR + kc];
#pragma unroll
                for (int j = 0; j < 8; j++) acc[i][j] = fmaf(p, vv[j], acc[i][j]);
            }
        }
    }

#pragma unroll
    for (int i = 0; i < 4; i++) {
        float inv = 1.f / lrow[i];
#pragma unroll
        for (int j = 0; j < 8; j++)
            out[(long)(b * QL_ + q0 + ty * 4 + i) * (H_ * HD_) + h * HD_ + tx * 8 + j]
                = acc[i][j] * inv;
    }
}

// ---------------------------------------------------------------------------
// Launch
// ---------------------------------------------------------------------------
extern "C" void kernel_launch(void* const* d_in, const int* in_sizes, int n_in,
                              void* d_out, int out_size)
{
    const float* x_q       = (const float*)d_in[0];
    const float* x_kv      = (const float*)d_in[1];
    const float* W_dQ      = (const float*)d_in[2];
    const float* q_norm_w  = (const float*)d_in[3];
    const float* W_uQ      = (const float*)d_in[4];
    const float* W_dKV     = (const float*)d_in[5];
    const float* kv_norm_w = (const float*)d_in[6];
    const float* W_ukv     = (const float*)d_in[7];
    const float* W_o       = (const float*)d_in[8];
    float* out = (float*)d_out;

    float *qlat, *qfull, *ckv, *kv, *attn;
    cudaGetSymbolAddress((void**)&qlat,  g_qlat);
    cudaGetSymbolAddress((void**)&qfull, g_qfull);
    cudaGetSymbolAddress((void**)&ckv,   g_ckv);
    cudaGetSymbolAddress((void**)&kv,    g_kv);
    cudaGetSymbolAddress((void**)&attn,  g_attn);

    __nv_bfloat16 *xqh,*xql,*xkvh,*xkvl,*qnh,*qnl,*ckvh,*ckvl,*ath,*atl;
    __nv_bfloat16 *wdqh,*wdql,*wuqh,*wuql,*wdkvh,*wdkvl,*wukvh,*wukvl,*woh,*wol;
    cudaGetSymbolAddress((void**)&xqh,  g_xq_h);   cudaGetSymbolAddress((void**)&xql,  g_xq_l);
    cudaGetSymbolAddress((void**)&xkvh, g_xkv_h);  cudaGetSymbolAddress((void**)&xkvl, g_xkv_l);
    cudaGetSymbolAddress((void**)&qnh,  g_qn_h);   cudaGetSymbolAddress((void**)&qnl,  g_qn_l);
    cudaGetSymbolAddress((void**)&ckvh, g_ckvn_h); cudaGetSymbolAddress((void**)&ckvl, g_ckvn_l);
    cudaGetSymbolAddress((void**)&ath,  g_at_h);   cudaGetSymbolAddress((void**)&atl,  g_at_l);
    cudaGetSymbolAddress((void**)&wdqh, g_wdq_h);  cudaGetSymbolAddress((void**)&wdql, g_wdq_l);
    cudaGetSymbolAddress((void**)&wuqh, g_wuq_h);  cudaGetSymbolAddress((void**)&wuql, g_wuq_l);
    cudaGetSymbolAddress((void**)&wdkvh,g_wdkv_h); cudaGetSymbolAddress((void**)&wdkvl,g_wdkv_l);
    cudaGetSymbolAddress((void**)&wukvh,g_wukv_h); cudaGetSymbolAddress((void**)&wukvl,g_wukv_l);
    cudaGetSymbolAddress((void**)&woh,  g_wo_h);   cudaGetSymbolAddress((void**)&wol,  g_wo_l);

    cudaFuncSetAttribute(gemm_tc, cudaFuncAttributeMaxDynamicSharedMemorySize, GEMM_SMEM);
    cudaFuncSetAttribute(flash_attn, cudaFuncAttributeMaxDynamicSharedMemorySize, FLASH_SMEM);

    const int M_q  = B_ * QL_;   // 2048
    const int M_kv = B_ * KL_;   // 8192
    dim3 t32x8(32, 8);

    // --- input splits + weight transpose/splits ---
    { int n4 = (M_q * HID_) / 4;  split_f32<<<(n4+255)/256, 256>>>(x_q,  xqh,  xql,  n4); }
    { int n4 = (M_kv * HID_) / 4; split_f32<<<(n4+255)/256, 256>>>(x_kv, xkvh, xkvl, n4); }
    transpose_split<<<dim3(QLR_/32, HID_/32), t32x8>>>(W_dQ, QLR_, 0, wdqh, wdql, HID_, 0);
    transpose_split<<<dim3(3072/32, QLR_/32), t32x8>>>(W_uQ, 3072, 0, wuqh, wuql, QLR_, 0);
    transpose_split<<<dim3(1024/32, HID_/32), t32x8>>>(W_dKV, 1088, 0, wdkvh, wdkvl, HID_, 0);
    transpose_split<<<dim3(1024/32, LAT_/32, G_), t32x8>>>(
        W_ukv, 1024, (long)LAT_*1024, wukvh, wukvl, LAT_, (long)1024*LAT_);
    transpose_split<<<dim3(HID_/32, HID_/32), t32x8>>>(W_o, HID_, 0, woh, wol, HID_, 0);

    // 1) q_lat = x_q @ W_dQ    [2048,2048] x [2048,512]
    gemm_tc<<<dim3(QLR_/TN, M_q/TM, 1), 256, GEMM_SMEM>>>(
        xqh, xql, HID_, 0, wdqh, wdql, HID_, 0, qlat, QLR_, 0, HID_);
    // 2) rmsnorm + split
    rmsnorm_q_split<<<M_q, 256>>>(qlat, q_norm_w, qnh, qnl);
    // 3) q_full = qn @ W_uQ    [2048,512] x [512,3072]
    gemm_tc<<<dim3(3072/TN, M_q/TM, 1), 256, GEMM_SMEM>>>(
        qnh, qnl, QLR_, 0, wuqh, wuql, QLR_, 0, qfull, 3072, 0, QLR_);
    // 4) ckv = (x_kv @ W_dKV)[:, :1024]
    gemm_tc<<<dim3(1024/TN, M_kv/TM, 1), 256, GEMM_SMEM>>>(
        xkvh, xkvl, HID_, 0, wdkvh, wdkvl, HID_, 0, ckv, 1024, 0, HID_);
    // 5) rmsnorm per (row, group) + split
    rmsnorm_kv_split<<<M_kv * G_, 256>>>(ckv, kv_norm_w, ckvh, ckvl);
    // 6) kv[:, g*1024 : (g+1)*1024] = ckvn[:, g] @ W_ukv[g]   (batched over g)
    gemm_tc<<<dim3(1024/TN, M_kv/TM, G_), 256, GEMM_SMEM>>>(
        ckvh, ckvl, G_*LAT_, LAT_,
        wukvh, wukvl, LAT_, (long)1024*LAT_,
        kv, H_*2*HD_, 1024, LAT_);
    // 7) flash attention (fp32)
    flash_attn<<<dim3(QL_/QT, B_*H_), 256, FLASH_SMEM>>>(qfull, kv, attn);
    // 8) split attn, then out = attn @ W_o
    { int n4 = (M_q * H_ * HD_) / 4; split_f32<<<(n4+255)/256, 256>>>(attn, ath, atl, n4); }
    gemm_tc<<<dim3(HID_/TN, M_q/TM, 1), 256, GEMM_SMEM>>>(
        ath, atl, H_*HD_, 0, woh, wol, HID_, 0, out, HID_, 0, H_*HD_);
}

// round 11
// speedup vs baseline: 3.3201x; 3.3201x over previous
#include <cuda_runtime.h>
#include <cuda_bf16.h>
#include <cstdint>

// ---------------------------------------------------------------------------
// GLACrossAttention: B=2 QL=1024 KL=4096 HID=2048 H=16 HD=128 RD=64
//                    G=4 HPG=4 QLR=512 LAT=256 EPS=1e-6
// Round 9: round-8 failed at rel_err 1.75e-3 == exactly the bf16-rounding
//          level of QK^T and P (near-uniform attention over 4096 keys means
//          the usual averaging does NOT damp operand rounding).
//          Fix: split-bf16 (hi/lo, 3-MMA) for QK^T and for P@V as well.
//          All matmuls on mma.sync.m16n8k16 (-> HMMA on sm_103a).
// ---------------------------------------------------------------------------

#define B_    2
#define QL_   1024
#define KL_   4096
#define HID_  2048
#define H_    16
#define HD_   128
#define RD_   64
#define G_    4
#define QLR_  512
#define LAT_  256
#define EPS_  1e-6f

// ---------------------------------------------------------------------------
// PTX helpers (all baseline PTX, legal on compute_103)
// ---------------------------------------------------------------------------
__device__ __forceinline__ uint32_t smem_u32(const void* p) {
    uint32_t a;
    asm("{ .reg .u64 t; cvta.to.shared.u64 t, %1; cvt.u32.u64 %0, t; }"
        : "=r"(a) : "l"(p));
    return a;
}
__device__ __forceinline__ void cpa16(uint32_t dst, const void* src) {
    asm volatile("cp.async.cg.shared.global [%0], [%1], 16;\n" :: "r"(dst), "l"(src));
}
__device__ __forceinline__ void cpa_commit() {
    asm volatile("cp.async.commit_group;\n" ::: "memory");
}
__device__ __forceinline__ void cpa_wait1() {
    asm volatile("cp.async.wait_group 1;\n" ::: "memory");
}
__device__ __forceinline__ void cpa_wait0() {
    asm volatile("cp.async.wait_group 0;\n" ::: "memory");
}
__device__ __forceinline__ void ldsm4(uint32_t& r0, uint32_t& r1, uint32_t& r2,
                                      uint32_t& r3, uint32_t addr) {
    asm volatile("ldmatrix.sync.aligned.m8n8.x4.shared.b16 {%0,%1,%2,%3}, [%4];"
        : "=r"(r0), "=r"(r1), "=r"(r2), "=r"(r3) : "r"(addr));
}
__device__ __forceinline__ void ldsm2(uint32_t& r0, uint32_t& r1, uint32_t addr) {
    asm volatile("ldmatrix.sync.aligned.m8n8.x2.shared.b16 {%0,%1}, [%2];"
        : "=r"(r0), "=r"(r1) : "r"(addr));
}
// D(16x8,f32) += A(16x16 bf16, row) * B(16x8 bf16, col)
__device__ __forceinline__ void mma16816(float* c, uint32_t a0, uint32_t a1,
                                         uint32_t a2, uint32_t a3,
                                         uint32_t b0, uint32_t b1) {
    asm volatile("mma.sync.aligned.m16n8k16.row.col.f32.bf16.bf16.f32 "
        "{%0,%1,%2,%3}, {%4,%5,%6,%7}, {%8,%9}, {%0,%1,%2,%3};"
        : "+f"(c[0]), "+f"(c[1]), "+f"(c[2]), "+f"(c[3])
        : "r"(a0), "r"(a1), "r"(a2), "r"(a3), "r"(b0), "r"(b1));
}

// ---------------------------------------------------------------------------
// Scratch (device globals; allocation-free contract)
// ---------------------------------------------------------------------------
__device__ float g_qlat [B_*QL_*QLR_];
__device__ float g_qfull[B_*QL_*H_*(HD_+RD_)];
__device__ float g_ckv  [B_*KL_*G_*LAT_];
__device__ float g_kv   [(size_t)B_*KL_*H_*2*HD_];
__device__ float g_attn [B_*QL_*H_*HD_];

// split-bf16 activations
__device__ __nv_bfloat16 g_xq_h [B_*QL_*HID_],   g_xq_l [B_*QL_*HID_];
__device__ __nv_bfloat16 g_xkv_h[B_*KL_*HID_],   g_xkv_l[B_*KL_*HID_];
__device__ __nv_bfloat16 g_qn_h [B_*QL_*QLR_],   g_qn_l [B_*QL_*QLR_];
__device__ __nv_bfloat16 g_ckvn_h[B_*KL_*G_*LAT_], g_ckvn_l[B_*KL_*G_*LAT_];
__device__ __nv_bfloat16 g_at_h [B_*QL_*H_*HD_], g_at_l [B_*QL_*H_*HD_];
// split-bf16 transposed weights  (B operand must be [N rows][K cols])
__device__ __nv_bfloat16 g_wdq_h [QLR_*HID_],     g_wdq_l [QLR_*HID_];
__device__ __nv_bfloat16 g_wuq_h [3072*QLR_],     g_wuq_l [3072*QLR_];
__device__ __nv_bfloat16 g_wdkv_h[1024*HID_],     g_wdkv_l[1024*HID_];
__device__ __nv_bfloat16 g_wukv_h[G_*1024*LAT_],  g_wukv_l[G_*1024*LAT_];
__device__ __nv_bfloat16 g_wo_h  [HID_*HID_],     g_wo_l  [HID_*HID_];
// attention operands (all split hi/lo)
__device__ __nv_bfloat16 g_qbh [(size_t)B_*H_*QL_*HD_];   // [bh][q][d], scale folded
__device__ __nv_bfloat16 g_qbl [(size_t)B_*H_*QL_*HD_];
__device__ __nv_bfloat16 g_kbh [(size_t)B_*H_*KL_*HD_];   // [bh][key][d]
__device__ __nv_bfloat16 g_kbl [(size_t)B_*H_*KL_*HD_];
__device__ __nv_bfloat16 g_vh  [(size_t)B_*H_*HD_*KL_];   // [bh][d][key] (transposed)
__device__ __nv_bfloat16 g_vl  [(size_t)B_*H_*HD_*KL_];

// ---------------------------------------------------------------------------
// split fp32 -> (hi, lo) bf16, vectorized by 4
// ---------------------------------------------------------------------------
__global__ __launch_bounds__(256) void split_f32(
    const float* __restrict__ src, __nv_bfloat16* __restrict__ h,
    __nv_bfloat16* __restrict__ l, int n4)
{
    int i = blockIdx.x * 256 + threadIdx.x;
    if (i >= n4) return;
    float4 v = ((const float4*)src)[i];
    __nv_bfloat16 h0 = __float2bfloat16(v.x), h1 = __float2bfloat16(v.y);
    __nv_bfloat16 h2 = __float2bfloat16(v.z), h3 = __float2bfloat16(v.w);
    __nv_bfloat16 l0 = __float2bfloat16(v.x - __bfloat162float(h0));
    __nv_bfloat16 l1 = __float2bfloat16(v.y - __bfloat162float(h1));
    __nv_bfloat16 l2 = __float2bfloat16(v.z - __bfloat162float(h2));
    __nv_bfloat16 l3 = __float2bfloat16(v.w - __bfloat162float(h3));
    ((__nv_bfloat162*)h)[2*i]   = __nv_bfloat162(h0, h1);
    ((__nv_bfloat162*)h)[2*i+1] = __nv_bfloat162(h2, h3);
    ((__nv_bfloat162*)l)[2*i]   = __nv_bfloat162(l0, l1);
    ((__nv_bfloat162*)l)[2*i+1] = __nv_bfloat162(l2, l3);
}

// ---------------------------------------------------------------------------
// transpose + split: src fp32 [R, >=C] (ldS) -> dst bf16 [C, R] hi/lo (ldD=R)
// ---------------------------------------------------------------------------
__global__ __launch_bounds__(256) void transpose_split(
    const float* __restrict__ src, int ldS, long sBatch,
    __nv_bfloat16* __restrict__ dh, __nv_bfloat16* __restrict__ dl,
    int ldD, long dBatch)
{
    src += (long)blockIdx.z * sBatch;
    dh  += (long)blockIdx.z * dBatch;
    dl  += (long)blockIdx.z * dBatch;
    __shared__ float t[32][33];
    const int tx = threadIdx.x, ty = threadIdx.y;
    const int c0 = blockIdx.x * 32, r0 = blockIdx.y * 32;
#pragma unroll
    for (int i = 0; i < 4; i++)
        t[ty + i * 8][tx] = src[(long)(r0 + ty + i * 8) * ldS + c0 + tx];
    __syncthreads();
#pragma unroll
    for (int i = 0; i < 4; i++) {
        float v = t[tx][ty + i * 8];
        __nv_bfloat16 hi = __float2bfloat16(v);
        __nv_bfloat16 lo = __float2bfloat16(v - __bfloat162float(hi));
        long o = (long)(c0 + ty + i * 8) * ldD + r0 + tx;
        dh[o] = hi; dl[o] = lo;
    }
}

// ---------------------------------------------------------------------------
// mma.sync split-bf16 GEMM: C[M,N] fp32 = A[M,K] @ B^T[N,K]
// Block 128x128, 8 warps (2m x 4n, warp tile 64x32), KC=32, 2-stage cp.async.
// Per 16-k step: 3 MMAs per tile (AhBh + AhBl + AlBh).
// ---------------------------------------------------------------------------
#define GSTR   40                    // smem row stride in bf16 (32 data + 8 pad)
#define G_OPB  (128*GSTR*2)          // 10240 B per operand tile
#define G_STG  (4*G_OPB)             // 40960 B per stage
#define GEMM_SMEM (2*G_STG)          // 81920 B

__global__ __launch_bounds__(256)
void gemm_mma(const __nv_bfloat16* __restrict__ Ah, const __nv_bfloat16* __restrict__ Al,
              int lda, long aBatch,
              const __nv_bfloat16* __restrict__ Bh, const __nv_bfloat16* __restrict__ Bl,
              int ldb, long bBatch,
              float* __restrict__ C, int ldc, long cBatch, int K)
{
    extern __shared__ __align__(16) char smem[];
    uint32_t sb = smem_u32(smem);
    const int tid = threadIdx.x;
    const int lane = tid & 31, wid = tid >> 5;
    const int wm = wid >> 2, wn = wid & 3;           // 2 x 4 warp grid
    const int m0 = wm * 64, n0 = wn * 32;

    Ah += (long)blockIdx.z * aBatch;  Al += (long)blockIdx.z * aBatch;
    Bh += (long)blockIdx.z * bBatch;  Bl += (long)blockIdx.z * bBatch;
    C  += (long)blockIdx.z * cBatch;
    const int rowBase = blockIdx.y * 128;
    const int colBase = blockIdx.x * 128;

    const uint32_t aLane = (uint32_t)(((lane & 15) * GSTR + (lane >> 4) * 8) * 2);
    const uint32_t bLane = (uint32_t)(((lane & 7) * GSTR + ((lane >> 3) & 1) * 8) * 2);

    float acc[4][4][4];
#pragma unroll
    for (int i = 0; i < 4; i++)
#pragma unroll
        for (int j = 0; j < 4; j++)
#pragma unroll
            for (int k = 0; k < 4; k++) acc[i][j][k] = 0.f;

    const int nIter = K / 32;

    auto load_stage = [&](int it, int s) {
        uint32_t st = sb + s * G_STG;
        int k0 = it * 32;
#pragma unroll
        for (int i = 0; i < 2; i++) {
            int idx = tid + i * 256;
            int r = idx >> 2, c = idx & 3;
            uint32_t so = (uint32_t)(r * (GSTR*2) + c * 16);
            size_t ga = (size_t)(rowBase + r) * lda + k0 + c * 8;
            size_t gb = (size_t)(colBase + r) * ldb + k0 + c * 8;
            cpa16(st + so,             Ah + ga);
            cpa16(st + G_OPB + so,     Al + ga);
            cpa16(st + 2*G_OPB + so,   Bh + gb);
            cpa16(st + 3*G_OPB + so,   Bl + gb);
        }
        cpa_commit();
    };

    load_stage(0, 0);
    for (int it = 0; it < nIter; it++) {
        int s = it & 1;
        if (it + 1 < nIter) { load_stage(it + 1, s ^ 1); cpa_wait1(); }
        else                { cpa_wait0(); }
        __syncthreads();
        uint32_t st = sb + s * G_STG;
#pragma unroll
        for (int kk = 0; kk < 2; kk++) {
            const int kof = kk * 16;
            uint32_t ah[4][4], al[4][4];
#pragma unroll
            for (int i = 0; i < 4; i++) {
                uint32_t base = (uint32_t)(((m0 + i * 16) * GSTR + kof) * 2);
                ldsm4(ah[i][0], ah[i][1], ah[i][2], ah[i][3], st + base + aLane);
                ldsm4(al[i][0], al[i][1], al[i][2], al[i][3], st + G_OPB + base + aLane);
            }
#pragma unroll
            for (int j = 0; j < 4; j++) {
                uint32_t base = (uint32_t)(((n0 + j * 8) * GSTR + kof) * 2);
                uint32_t bh0, bh1, bl0, bl1;
                ldsm2(bh0, bh1, st + 2*G_OPB + base + bLane);
                ldsm2(bl0, bl1, st + 3*G_OPB + base + bLane);
#pragma unroll
                for (int i = 0; i < 4; i++) {
                    mma16816(acc[i][j], ah[i][0], ah[i][1], ah[i][2], ah[i][3], bh0, bh1);
                    mma16816(acc[i][j], ah[i][0], ah[i][1], ah[i][2], ah[i][3], bl0, bl1);
                    mma16816(acc[i][j], al[i][0], al[i][1], al[i][2], al[i][3], bh0, bh1);
                }
            }
        }
        __syncthreads();
    }

    // epilogue: c-frag rows g, g+8; cols 2*tg,+1
#pragma unroll
    for (int i = 0; i < 4; i++) {
        int r0 = rowBase + m0 + i * 16 + (lane >> 2);
#pragma unroll
        for (int j = 0; j < 4; j++) {
            int col = colBase + n0 + j * 8 + (lane & 3) * 2;
            *(float2*)&C[(size_t)r0 * ldc + col]       = make_float2(acc[i][j][0], acc[i][j][1]);
            *(float2*)&C[(size_t)(r0 + 8) * ldc + col] = make_float2(acc[i][j][2], acc[i][j][3]);
        }
    }
}

// ---------------------------------------------------------------------------
// RMSNorm over 512 cols (q path) -> split bf16. grid = B*QL, block 256.
// ---------------------------------------------------------------------------
__global__ __launch_bounds__(256) void rmsnorm_q_split(
    const float* __restrict__ x, const float* __restrict__ w,
    __nv_bfloat16* __restrict__ oh, __nv_bfloat16* __restrict__ ol)
{
    const float* p = x + (long)blockIdx.x * QLR_;
    const int t = threadIdx.x;
    float v0 = p[t], v1 = p[t + 256];
    __shared__ float red[256];
    red[t] = v0 * v0 + v1 * v1;
    __syncthreads();
    for (int s = 128; s > 0; s >>= 1) {
        if (t < s) red[t] += red[t + s];
        __syncthreads();
    }
    float inv = rsqrtf(red[0] * (1.f / QLR_) + EPS_);
    long base = (long)blockIdx.x * QLR_;
    float y0 = v0 * inv * w[t], y1 = v1 * inv * w[t + 256];
    __nv_bfloat16 h0 = __float2bfloat16(y0), h1 = __float2bfloat16(y1);
    oh[base + t]       = h0;
    oh[base + t + 256] = h1;
    ol[base + t]       = __float2bfloat16(y0 - __bfloat162float(h0));
    ol[base + t + 256] = __float2bfloat16(y1 - __bfloat162float(h1));
}

// ---------------------------------------------------------------------------
// RMSNorm over LAT=256 per (row, group) -> split bf16. grid = B*KL*G, block 256.
// ---------------------------------------------------------------------------
__global__ __launch_bounds__(256) void rmsnorm_kv_split(
    const float* __restrict__ x, const float* __restrict__ w,
    __nv_bfloat16* __restrict__ oh, __nv_bfloat16* __restrict__ ol)
{
    const int row = blockIdx.x >> 2;
    const int g   = blockIdx.x & 3;
    const long base = (long)row * (G_ * LAT_) + g * LAT_;
    const int t = threadIdx.x;
    float v = x[base + t];
    __shared__ float red[256];
    red[t] = v * v;
    __syncthreads();
    for (int s = 128; s > 0; s >>= 1) {
        if (t < s) red[t] += red[t + s];
        __syncthreads();
    }
    float inv = rsqrtf(red[0] * (1.f / LAT_) + EPS_);
    float y = v * inv * w[g * LAT_ + t];
    __nv_bfloat16 h = __float2bfloat16(y);
    oh[base + t] = h;
    ol[base + t] = __float2bfloat16(y - __bfloat162float(h));
}

// ---------------------------------------------------------------------------
// prep_q: qfull fp32 [b,q, h*192+d] -> Qh/Ql [bh][q][d] bf16 split, scale folded.
// threads = B*H*QL*32 (4 d's each)
// ---------------------------------------------------------------------------
__global__ __launch_bounds__(256) void prep_q(
    const float* __restrict__ qfull,
    __nv_bfloat16* __restrict__ Qh, __nv_bfloat16* __restrict__ Ql)
{
    const float scale = 0.08838834764831845f;   // 1/sqrt(128)
    size_t i = (size_t)blockIdx.x * 256 + threadIdx.x;
    int d = (int)(i & 31) * 4;
    size_t rest = i >> 5;
    int q = (int)(rest & (QL_ - 1));
    rest >>= 10;
    int h = (int)(rest & 15);
    int b = (int)(rest >> 4);
    float4 v = *(const float4*)&qfull[((size_t)(b * QL_ + q)) * 3072 + h * 192 + d];
    float f[4] = {v.x * scale, v.y * scale, v.z * scale, v.w * scale};
    size_t o = ((size_t)(b * H_ + h) * QL_ + q) * HD_ + d;
    __nv_bfloat16 hh[4], ll[4];
#pragma unroll
    for (int k = 0; k < 4; k++) {
        hh[k] = __float2bfloat16(f[k]);
        ll[k] = __float2bfloat16(f[k] - __bfloat162float(hh[k]));
    }
    ((__nv_bfloat162*)(Qh + o))[0] = __nv_bfloat162(hh[0], hh[1]);
    ((__nv_bfloat162*)(Qh + o))[1] = __nv_bfloat162(hh[2], hh[3]);
    ((__nv_bfloat162*)(Ql + o))[0] = __nv_bfloat162(ll[0], ll[1]);
    ((__nv_bfloat162*)(Ql + o))[1] = __nv_bfloat162(ll[2], ll[3]);
}

// ---------------------------------------------------------------------------
// prep_k: kv fp32 [b,s,h, d(0..127)] -> Kh/Kl [bh][s][d] bf16 split
// threads = B*H*KL*32 (4 d's each)
// ---------------------------------------------------------------------------
__global__ __launch_bounds__(256) void prep_k(
    const float* __restrict__ kv,
    __nv_bfloat16* __restrict__ Kh, __nv_bfloat16* __restrict__ Kl)
{
    size_t i = (size_t)blockIdx.x * 256 + threadIdx.x;
    int d = (int)(i & 31) * 4;
    size_t rest = i >> 5;
    int s = (int)(rest & (KL_ - 1));
    rest >>= 12;
    int h = (int)(rest & 15);
    int b = (int)(rest >> 4);
    float4 v = *(const float4*)&kv[((size_t)(b * KL_ + s) * H_ + h) * 256 + d];
    float f[4] = {v.x, v.y, v.z, v.w};
    size_t o = ((size_t)(b * H_ + h) * KL_ + s) * HD_ + d;
    __nv_bfloat16 hh[4], ll[4];
#pragma unroll
    for (int k = 0; k < 4; k++) {
        hh[k] = __float2bfloat16(f[k]);
        ll[k] = __float2bfloat16(f[k] - __bfloat162float(hh[k]));
    }
    ((__nv_bfloat162*)(Kh + o))[0] = __nv_bfloat162(hh[0], hh[1]);
    ((__nv_bfloat162*)(Kh + o))[1] = __nv_bfloat162(hh[2], hh[3]);
    ((__nv_bfloat162*)(Kl + o))[0] = __nv_bfloat162(ll[0], ll[1]);
    ((__nv_bfloat162*)(Kl + o))[1] = __nv_bfloat162(ll[2], ll[3]);
}

// ---------------------------------------------------------------------------
// prep_v: kv fp32 [b,s,h, 128+d] -> Vh/Vl [bh][d][s] bf16 (transposed + split)
// grid (KL/32, HD/32, B*H), block (32, 8)
// ---------------------------------------------------------------------------
__global__ __launch_bounds__(256) void prep_v(
    const float* __restrict__ kv,
    __nv_bfloat16* __restrict__ Vh, __nv_bfloat16* __restrict__ Vl)
{
    __shared__ float t[32][33];
    const int bh = blockIdx.z;
    const int b = bh >> 4, h = bh & 15;
    const int s0 = blockIdx.x * 32, d0 = blockIdx.y * 32;
    const int tx = threadIdx.x, ty = threadIdx.y;
#pragma unroll
    for (int i = 0; i < 4; i++)
        t[ty + i * 8][tx] =
            kv[((size_t)(b * KL_ + s0 + ty + i * 8) * H_ + h) * 256 + 128 + d0 + tx];
    __syncthreads();
#pragma unroll
    for (int i = 0; i < 4; i++) {
        float v = t[tx][ty + i * 8];
        __nv_bfloat16 hi = __float2bfloat16(v);
        __nv_bfloat16 lo = __float2bfloat16(v - __bfloat162float(hi));
        size_t o = ((size_t)bh * HD_ + d0 + ty + i * 8) * KL_ + s0 + tx;
        Vh[o] = hi; Vl[o] = lo;
    }
}

// ---------------------------------------------------------------------------
// flash_mma: tensor-core flash attention, split-bf16 everywhere.
// grid (QL/64, B*H), 256 threads (8 warps).
// Qh/Ql [bh][q][d] (pre-scaled); Kh/Kl [bh][key][d]; Vh/Vl [bh][d][key].
// Per 64-key iter: S = QhKh+QhKl+QlKh (3 MMA) -> fp32 online softmax ->
// P split hi/lo -> O += PhVh+PhVl+PlVh (3 MMA). l summed over Ph+Pl.
// ---------------------------------------------------------------------------
#define FQ_OFF   0            // Qh  bf16 [64][136]      17408 B
#define FQL_OFF  17408        // Ql  bf16 [64][136]      17408 B
#define FK_OFF   34816        // Kh  bf16 [2][64][136]   34816 B
#define FKL_OFF  69632        // Kl  bf16 [2][64][136]   34816 B
#define FVH_OFF  104448       // Vh  bf16 [2][128][72]   36864 B
#define FVL_OFF  141312       // Vl  bf16 [2][128][72]   36864 B
#define FS_OFF   178176       // Ss  f32  [64][68]       17408 B
#define FPH_OFF  195584       // Ph  bf16 [64][72]        9216 B
#define FPL_OFF  204800       // Pl  bf16 [64][72]        9216 B
#define FST_OFF  214016       // m,l,corr f32 [3][64]      768 B
#define FLASH_SMEM 214784

__global__ __launch_bounds__(256)
void flash_mma(const __nv_bfloat16* __restrict__ Qhg,
               const __nv_bfloat16* __restrict__ Qlg,
               const __nv_bfloat16* __restrict__ Khg,
               const __nv_bfloat16* __restrict__ Klg,
               const __nv_bfloat16* __restrict__ Vhg,
               const __nv_bfloat16* __restrict__ Vlg,
               float* __restrict__ outg)
{
    extern __shared__ __align__(16) char smem[];
    uint32_t sb = smem_u32(smem);
    float* Ss  = (float*)(smem + FS_OFF);
    float* m_s = (float*)(smem + FST_OFF);
    float* l_s = m_s + 64;
    float* c_s = l_s + 64;

    const int tid = threadIdx.x, lane = tid & 31, wid = tid >> 5;
    const int bh = blockIdx.y;
    const int b = bh >> 4, h = bh & 15;
    const int q0 = blockIdx.x * 64;

    const __nv_bfloat16* Qhp = Qhg + ((size_t)bh * QL_ + q0) * HD_;
    const __nv_bfloat16* Qlp = Qlg + ((size_t)bh * QL_ + q0) * HD_;
    const __nv_bfloat16* Khp = Khg + (size_t)bh * KL_ * HD_;
    const __nv_bfloat16* Klp = Klg + (size_t)bh * KL_ * HD_;
    const __nv_bfloat16* Vhp = Vhg + (size_t)bh * HD_ * KL_;
    const __nv_bfloat16* Vlp = Vlg + (size_t)bh * HD_ * KL_;

    if (tid < 64) { m_s[tid] = -1e30f; l_s[tid] = 0.f; }

    // Q tiles (hi+lo) 64x128 bf16, row stride 136
#pragma unroll
    for (int i = 0; i < 4; i++) {
        int idx = tid + i * 256;
        int r = idx >> 4, c = idx & 15;
        cpa16(sb + FQ_OFF  + r * 272 + c * 16, Qhp + (size_t)r * HD_ + c * 8);
        cpa16(sb + FQL_OFF + r * 272 + c * 16, Qlp + (size_t)r * HD_ + c * 8);
    }

    auto load_kv = [&](int it, int s) {
        int key0 = it * 64;
#pragma unroll
        for (int i = 0; i < 4; i++) {
            int idx = tid + i * 256;
            int r = idx >> 4, c = idx & 15;
            uint32_t so = (uint32_t)(s * 17408 + r * 272 + c * 16);
            size_t go = (size_t)(key0 + r) * HD_ + c * 8;
            cpa16(sb + FK_OFF  + so, Khp + go);
            cpa16(sb + FKL_OFF + so, Klp + go);
        }
#pragma unroll
        for (int i = 0; i < 4; i++) {
            int idx = tid + i * 256;
            int r = idx >> 3, c = idx & 7;
            uint32_t so = (uint32_t)(s * 18432 + r * 144 + c * 16);
            size_t go = (size_t)r * KL_ + key0 + c * 8;
            cpa16(sb + FVH_OFF + so, Vhp + go);
            cpa16(sb + FVL_OFF + so, Vlp + go);
        }
        cpa_commit();
    };

    load_kv(0, 0);   // one group: Q + K/V stage 0

    const int wm16 = (wid >> 1) * 16;       // row strip (S rows / O rows)
    const int sn0  = (wid & 1) * 32;        // S col strip (QK)
    const int on0  = (wid & 1) * 64;        // O col strip (PV)
    const uint32_t aLaneQ = (uint32_t)(((lane & 15) * 136 + (lane >> 4) * 8) * 2);
    const uint32_t bLaneK = (uint32_t)(((lane & 7) * 136 + ((lane >> 3) & 1) * 8) * 2);
    const uint32_t aLaneP = (uint32_t)(((lane & 15) * 72 + (lane >> 4) * 8) * 2);
    const uint32_t bLaneV = (uint32_t)(((lane & 7) * 72 + ((lane >> 3) & 1) * 8) * 2);

    uint32_t qah[8][4], qal[8][4];
    float oacc[8][4];
#pragma unroll
    for (int j = 0; j < 8; j++)
#pragma unroll
        for (int k = 0; k < 4; k++) oacc[j][k] = 0.f;

    const int nIter = KL_ / 64;
    for (int it = 0; it < nIter; it++) {
        int s = it & 1;
        if (it + 1 < nIter) { load_kv(it + 1, s ^ 1); cpa_wait1(); }
        else                { cpa_wait0(); }
        __syncthreads();

        if (it == 0) {   // Q frags persist across iterations
#pragma unroll
            for (int kd = 0; kd < 8; kd++) {
                uint32_t off = (uint32_t)((wm16 * 136 + kd * 16) * 2) + aLaneQ;
                ldsm4(qah[kd][0], qah[kd][1], qah[kd][2], qah[kd][3], sb + FQ_OFF + off);
                ldsm4(qal[kd][0], qal[kd][1], qal[kd][2], qal[kd][3], sb + FQL_OFF + off);
            }
        }

        // ---- S = Qh@Kh^T + Qh@Kl^T + Ql@Kh^T  (warp: 16 x 32) ----
        float sacc[4][4];
#pragma unroll
        for (int j = 0; j < 4; j++)
#pragma unroll
            for (int k = 0; k < 4; k++) sacc[j][k] = 0.f;
#pragma unroll
        for (int kd = 0; kd < 8; kd++) {
#pragma unroll
            for (int j = 0; j < 4; j++) {
                uint32_t boff = (uint32_t)(s * 17408) +
                    (uint32_t)(((sn0 + j * 8) * 136 + kd * 16) * 2) + bLaneK;
                uint32_t bh0, bh1, bl0, bl1;
                ldsm2(bh0, bh1, sb + FK_OFF  + boff);
                ldsm2(bl0, bl1, sb + FKL_OFF + boff);
                mma16816(sacc[j], qah[kd][0], qah[kd][1], qah[kd][2], qah[kd][3], bh0, bh1);
                mma16816(sacc[j], qah[kd][0], qah[kd][1], qah[kd][2], qah[kd][3], bl0, bl1);
                mma16816(sacc[j], qal[kd][0], qal[kd][1], qal[kd][2], qal[kd][3], bh0, bh1);
            }
        }
#pragma unroll
        for (int j = 0; j < 4; j++) {
            int r = wm16 + (lane >> 2);
            int cidx = sn0 + j * 8 + (lane & 3) * 2;
            *(float2*)&Ss[r * 68 + cidx]       = make_float2(sacc[j][0], sacc[j][1]);
            *(float2*)&Ss[(r + 8) * 68 + cidx] = make_float2(sacc[j][2], sacc[j][3]);
        }
        __syncthreads();

        // ---- online softmax (4 threads per row), P split hi/lo ----
        {
            int row = tid >> 2, seg = tid & 3;
            float* sr = Ss + row * 68 + seg * 16;
            float tmax = sr[0];
#pragma unroll
            for (int c = 1; c < 16; c++) tmax = fmaxf(tmax, sr[c]);
            tmax = fmaxf(tmax, __shfl_xor_sync(0xffffffffu, tmax, 1));
            tmax = fmaxf(tmax, __shfl_xor_sync(0xffffffffu, tmax, 2));
            float mold = m_s[row];
            float mnew = fmaxf(mold, tmax);
            float corr = __expf(mold - mnew);
            __nv_bfloat16* ph = (__nv_bfloat16*)(smem + FPH_OFF) + row * 72 + seg * 16;
            __nv_bfloat16* pl = (__nv_bfloat16*)(smem + FPL_OFF) + row * 72 + seg * 16;
            float sum = 0.f;
#pragma unroll
            for (int c = 0; c < 16; c++) {
                float p = __expf(sr[c] - mnew);
                __nv_bfloat16 pb = __float2bfloat16(p);
                float prem = p - __bfloat162float(pb);
                __nv_bfloat16 pr = __float2bfloat16(prem);
                ph[c] = pb;
                pl[c] = pr;
                sum += __bfloat162float(pb) + __bfloat162float(pr);
            }
            sum += __shfl_xor_sync(0xffffffffu, sum, 1);
            sum += __shfl_xor_sync(0xffffffffu, sum, 2);
            if (seg == 0) {
                m_s[row] = mnew;
                l_s[row] = l_s[row] * corr + sum;
                c_s[row] = corr;
            }
        }
        __syncthreads();

        // ---- O = O*corr + Ph@Vh + Ph@Vl + Pl@Vh  (warp: 16 x 64) ----
        {
            float clo = c_s[wm16 + (lane >> 2)];
            float chi = c_s[wm16 + 8 + (lane >> 2)];
#pragma unroll
            for (int j = 0; j < 8; j++) {
                oacc[j][0] *= clo; oacc[j][1] *= clo;
                oacc[j][2] *= chi; oacc[j][3] *= chi;
            }
#pragma unroll
            for (int kk = 0; kk < 4; kk++) {
                uint32_t poff = (uint32_t)((wm16 * 72 + kk * 16) * 2) + aLaneP;
                uint32_t ah0, ah1, ah2, ah3, al0, al1, al2, al3;
                ldsm4(ah0, ah1, ah2, ah3, sb + FPH_OFF + poff);
                ldsm4(al0, al1, al2, al3, sb + FPL_OFF + poff);
#pragma unroll
                for (int j = 0; j < 8; j++) {
                    uint32_t boff = (uint32_t)(s * 18432) +
                        (uint32_t)(((on0 + j * 8) * 72 + kk * 16) * 2) + bLaneV;
                    uint32_t b0, b1, c0, c1;
                    ldsm2(b0, b1, sb + FVH_OFF + boff);
                    ldsm2(c0, c1, sb + FVL_OFF + boff);
                    mma16816(oacc[j], ah0, ah1, ah2, ah3, b0, b1);
                    mma16816(oacc[j], ah0, ah1, ah2, ah3, c0, c1);
                    mma16816(oacc[j], al0, al1, al2, al3, b0, b1);
                }
            }
        }
        __syncthreads();
    }

    // epilogue: normalize, write attn fp32 [b, q, h*128 + d]
    {
        float ilo = 1.f / l_s[wm16 + (lane >> 2)];
        float ihi = 1.f / l_s[wm16 + 8 + (lane >> 2)];
        int r = q0 + wm16 + (lane >> 2);
#pragma unroll
        for (int j = 0; j < 8; j++) {
            int col = h * HD_ + on0 + j * 8 + (lane & 3) * 2;
            *(float2*)&outg[(size_t)(b * QL_ + r) * (H_ * HD_) + col] =
                make_float2(oacc[j][0] * ilo, oacc[j][1] * ilo);
            *(float2*)&outg[(size_t)(b * QL_ + r + 8) * (H_ * HD_) + col] =
                make_float2(oacc[j][2] * ihi, oacc[j][3] * ihi);
        }
    }
}

// ---------------------------------------------------------------------------
// Launch
// ---------------------------------------------------------------------------
extern "C" void kernel_launch(void* const* d_in, const int* in_sizes, int n_in,
                              void* d_out, int out_size)
{
    const float* x_q       = (const float*)d_in[0];
    const float* x_kv      = (const float*)d_in[1];
    const float* W_dQ      = (const float*)d_in[2];
    const float* q_norm_w  = (const float*)d_in[3];
    const float* W_uQ      = (const float*)d_in[4];
    const float* W_dKV     = (const float*)d_in[5];
    const float* kv_norm_w = (const float*)d_in[6];
    const float* W_ukv     = (const float*)d_in[7];
    const float* W_o       = (const float*)d_in[8];
    float* out = (float*)d_out;

    float *qlat, *qfull, *ckv, *kv, *attn;
    cudaGetSymbolAddress((void**)&qlat,  g_qlat);
    cudaGetSymbolAddress((void**)&qfull, g_qfull);
    cudaGetSymbolAddress((void**)&ckv,   g_ckv);
    cudaGetSymbolAddress((void**)&kv,    g_kv);
    cudaGetSymbolAddress((void**)&attn,  g_attn);

    __nv_bfloat16 *xqh,*xql,*xkvh,*xkvl,*qnh,*qnl,*ckvh,*ckvl,*ath,*atl;
    __nv_bfloat16 *wdqh,*wdql,*wuqh,*wuql,*wdkvh,*wdkvl,*wukvh,*wukvl,*woh,*wol;
    __nv_bfloat16 *qbh,*qbl,*kbh,*kbl,*vh,*vl;
    cudaGetSymbolAddress((void**)&xqh,  g_xq_h);   cudaGetSymbolAddress((void**)&xql,  g_xq_l);
    cudaGetSymbolAddress((void**)&xkvh, g_xkv_h);  cudaGetSymbolAddress((void**)&xkvl, g_xkv_l);
    cudaGetSymbolAddress((void**)&qnh,  g_qn_h);   cudaGetSymbolAddress((void**)&qnl,  g_qn_l);
    cudaGetSymbolAddress((void**)&ckvh, g_ckvn_h); cudaGetSymbolAddress((void**)&ckvl, g_ckvn_l);
    cudaGetSymbolAddress((void**)&ath,  g_at_h);   cudaGetSymbolAddress((void**)&atl,  g_at_l);
    cudaGetSymbolAddress((void**)&wdqh, g_wdq_h);  cudaGetSymbolAddress((void**)&wdql, g_wdq_l);
    cudaGetSymbolAddress((void**)&wuqh, g_wuq_h);  cudaGetSymbolAddress((void**)&wuql, g_wuq_l);
    cudaGetSymbolAddress((void**)&wdkvh,g_wdkv_h); cudaGetSymbolAddress((void**)&wdkvl,g_wdkv_l);
    cudaGetSymbolAddress((void**)&wukvh,g_wukv_h); cudaGetSymbolAddress((void**)&wukvl,g_wukv_l);
    cudaGetSymbolAddress((void**)&woh,  g_wo_h);   cudaGetSymbolAddress((void**)&wol,  g_wo_l);
    cudaGetSymbolAddress((void**)&qbh,  g_qbh);    cudaGetSymbolAddress((void**)&qbl,  g_qbl);
    cudaGetSymbolAddress((void**)&kbh,  g_kbh);    cudaGetSymbolAddress((void**)&kbl,  g_kbl);
    cudaGetSymbolAddress((void**)&vh,   g_vh);     cudaGetSymbolAddress((void**)&vl,   g_vl);

    cudaFuncSetAttribute(gemm_mma,  cudaFuncAttributeMaxDynamicSharedMemorySize, GEMM_SMEM);
    cudaFuncSetAttribute(flash_mma, cudaFuncAttributeMaxDynamicSharedMemorySize, FLASH_SMEM);

    const int M_q  = B_ * QL_;   // 2048
    const int M_kv = B_ * KL_;   // 8192
    dim3 t32x8(32, 8);

    // --- input splits + weight transpose/splits ---
    { int n4 = (M_q * HID_) / 4;  split_f32<<<(n4+255)/256, 256>>>(x_q,  xqh,  xql,  n4); }
    { int n4 = (M_kv * HID_) / 4; split_f32<<<(n4+255)/256, 256>>>(x_kv, xkvh, xkvl, n4); }
    transpose_split<<<dim3(QLR_/32, HID_/32), t32x8>>>(W_dQ, QLR_, 0, wdqh, wdql, HID_, 0);
    transpose_split<<<dim3(3072/32, QLR_/32), t32x8>>>(W_uQ, 3072, 0, wuqh, wuql, QLR_, 0);
    transpose_split<<<dim3(1024/32, HID_/32), t32x8>>>(W_dKV, 1088, 0, wdkvh, wdkvl, HID_, 0);
    transpose_split<<<dim3(1024/32, LAT_/32, G_), t32x8>>>(
        W_ukv, 1024, (long)LAT_*1024, wukvh, wukvl, LAT_, (long)1024*LAT_);
    transpose_split<<<dim3(HID_/32, HID_/32), t32x8>>>(W_o, HID_, 0, woh, wol, HID_, 0);

    // 1) q_lat = x_q @ W_dQ    [2048x2048] x [512x2048]^T
    gemm_mma<<<dim3(QLR_/128, M_q/128, 1), 256, GEMM_SMEM>>>(
        xqh, xql, HID_, 0, wdqh, wdql, HID_, 0, qlat, QLR_, 0, HID_);
    // 2) rmsnorm + split
    rmsnorm_q_split<<<M_q, 256>>>(qlat, q_norm_w, qnh, qnl);
    // 3) q_full = qn @ W_uQ    [2048x512] x [3072x512]^T
    gemm_mma<<<dim3(3072/128, M_q/128, 1), 256, GEMM_SMEM>>>(
        qnh, qnl, QLR_, 0, wuqh, wuql, QLR_, 0, qfull, 3072, 0, QLR_);
    // 4) ckv = (x_kv @ W_dKV)[:, :1024]
    gemm_mma<<<dim3(1024/128, M_kv/128, 1), 256, GEMM_SMEM>>>(
        xkvh, xkvl, HID_, 0, wdkvh, wdkvl, HID_, 0, ckv, 1024, 0, HID_);
    // 5) rmsnorm per (row, group) + split
    rmsnorm_kv_split<<<M_kv * G_, 256>>>(ckv, kv_norm_w, ckvh, ckvl);
    // 6) kv[:, g*1024:(g+1)*1024] = ckvn[:, g] @ W_ukv[g]  (batched over g)
    gemm_mma<<<dim3(1024/128, M_kv/128, G_), 256, GEMM_SMEM>>>(
        ckvh, ckvl, G_*LAT_, LAT_,
        wukvh, wukvl, LAT_, (long)1024*LAT_,
        kv, H_*2*HD_, 1024, LAT_);
    // 7) attention operand prep (all split hi/lo)
    prep_q<<<(B_*H_*QL_*32)/256, 256>>>(qfull, qbh, qbl);
    prep_k<<<(int)(((size_t)B_*H_*KL_*32)/256), 256>>>(kv, kbh, kbl);
    prep_v<<<dim3(KL_/32, HD_/32, B_*H_), t32x8>>>(kv, vh, vl);
    // 8) tensor-core flash attention -> attn fp32
    flash_mma<<<dim3(QL_/64, B_*H_), 256, FLASH_SMEM>>>(qbh, qbl, kbh, kbl, vh, vl, attn);
    // 9) split attn, then out = attn @ W_o
    { int n4 = (M_q * H_ * HD_) / 4; split_f32<<<(n4+255)/256, 256>>>(attn, ath, atl, n4); }
    gemm_mma<<<dim3(HID_/128, M_q/128, 1), 256, GEMM_SMEM>>>(
        ath, atl, H_*HD_, 0, woh, wol, HID_, 0, out, HID_, 0, H_*HD_);
}

// round 13
// speedup vs baseline: 4.5109x; 1.3587x over previous
#include <cuda_runtime.h>
#include <cuda_bf16.h>
#include <cuda_fp16.h>
#include <cstdint>

// ---------------------------------------------------------------------------
// GLACrossAttention: B=2 QL=1024 KL=4096 HID=2048 H=16 HD=128 RD=64
//                    G=4 HPG=4 QLR=512 LAT=256 EPS=1e-6
// Round 12: HMMA-throughput bound (406 GF of split-bf16 MMA). Cut tensor work:
//   - attention QK/PV -> single-pass fp16 mma (eps=2^-11; round-8 anchor says
//     ~1.5e-4 per source) => attention MMA 206->69 GF, flash much simpler
//   - GEMM3 computes only used 2048 cols (gathered W_uQ) and writes q fp16
//     [bh][q][d] with softmax scale folded (kills prep_q + qfull round trip)
//   - flash epilogue writes split-bf16 attn directly (kills split_f32 pass)
//   GEMMs stay split-bf16 3-MMA (convert next round once fp16 error measured).
// ---------------------------------------------------------------------------

#define B_    2
#define QL_   1024
#define KL_   4096
#define HID_  2048
#define H_    16
#define HD_   128
#define RD_   64
#define G_    4
#define QLR_  512
#define LAT_  256
#define EPS_  1e-6f

// ---------------------------------------------------------------------------
// PTX helpers (all baseline PTX, legal on compute_103)
// ---------------------------------------------------------------------------
__device__ __forceinline__ uint32_t smem_u32(const void* p) {
    uint32_t a;
    asm("{ .reg .u64 t; cvta.to.shared.u64 t, %1; cvt.u32.u64 %0, t; }"
        : "=r"(a) : "l"(p));
    return a;
}
__device__ __forceinline__ void cpa16(uint32_t dst, const void* src) {
    asm volatile("cp.async.cg.shared.global [%0], [%1], 16;\n" :: "r"(dst), "l"(src));
}
__device__ __forceinline__ void cpa_commit() {
    asm volatile("cp.async.commit_group;\n" ::: "memory");
}
__device__ __forceinline__ void cpa_wait1() {
    asm volatile("cp.async.wait_group 1;\n" ::: "memory");
}
__device__ __forceinline__ void cpa_wait0() {
    asm volatile("cp.async.wait_group 0;\n" ::: "memory");
}
__device__ __forceinline__ void ldsm4(uint32_t& r0, uint32_t& r1, uint32_t& r2,
                                      uint32_t& r3, uint32_t addr) {
    asm volatile("ldmatrix.sync.aligned.m8n8.x4.shared.b16 {%0,%1,%2,%3}, [%4];"
        : "=r"(r0), "=r"(r1), "=r"(r2), "=r"(r3) : "r"(addr));
}
__device__ __forceinline__ void ldsm2(uint32_t& r0, uint32_t& r1, uint32_t addr) {
    asm volatile("ldmatrix.sync.aligned.m8n8.x2.shared.b16 {%0,%1}, [%2];"
        : "=r"(r0), "=r"(r1) : "r"(addr));
}
// D(16x8,f32) += A(16x16 bf16, row) * B(16x8 bf16, col)
__device__ __forceinline__ void mma16816(float* c, uint32_t a0, uint32_t a1,
                                         uint32_t a2, uint32_t a3,
                                         uint32_t b0, uint32_t b1) {
    asm volatile("mma.sync.aligned.m16n8k16.row.col.f32.bf16.bf16.f32 "
        "{%0,%1,%2,%3}, {%4,%5,%6,%7}, {%8,%9}, {%0,%1,%2,%3};"
        : "+f"(c[0]), "+f"(c[1]), "+f"(c[2]), "+f"(c[3])
        : "r"(a0), "r"(a1), "r"(a2), "r"(a3), "r"(b0), "r"(b1));
}
// D(16x8,f32) += A(16x16 fp16, row) * B(16x8 fp16, col)
__device__ __forceinline__ void mma16816h(float* c, uint32_t a0, uint32_t a1,
                                          uint32_t a2, uint32_t a3,
                                          uint32_t b0, uint32_t b1) {
    asm volatile("mma.sync.aligned.m16n8k16.row.col.f32.f16.f16.f32 "
        "{%0,%1,%2,%3}, {%4,%5,%6,%7}, {%8,%9}, {%0,%1,%2,%3};"
        : "+f"(c[0]), "+f"(c[1]), "+f"(c[2]), "+f"(c[3])
        : "r"(a0), "r"(a1), "r"(a2), "r"(a3), "r"(b0), "r"(b1));
}

// ---------------------------------------------------------------------------
// Scratch (device globals; allocation-free contract)
// ---------------------------------------------------------------------------
__device__ float g_qlat [B_*QL_*QLR_];
__device__ float g_ckv  [B_*KL_*G_*LAT_];
__device__ float g_kv   [(size_t)B_*KL_*H_*2*HD_];

// split-bf16 activations (GEMM inputs)
__device__ __nv_bfloat16 g_xq_h [B_*QL_*HID_],   g_xq_l [B_*QL_*HID_];
__device__ __nv_bfloat16 g_xkv_h[B_*KL_*HID_],   g_xkv_l[B_*KL_*HID_];
__device__ __nv_bfloat16 g_qn_h [B_*QL_*QLR_],   g_qn_l [B_*QL_*QLR_];
__device__ __nv_bfloat16 g_ckvn_h[B_*KL_*G_*LAT_], g_ckvn_l[B_*KL_*G_*LAT_];
__device__ __nv_bfloat16 g_at_h [B_*QL_*H_*HD_], g_at_l [B_*QL_*H_*HD_];
// split-bf16 transposed weights  (B operand must be [N rows][K cols])
__device__ __nv_bfloat16 g_wdq_h [QLR_*HID_],     g_wdq_l [QLR_*HID_];
__device__ __nv_bfloat16 g_wuq_h [2048*QLR_],     g_wuq_l [2048*QLR_];   // gathered
__device__ __nv_bfloat16 g_wdkv_h[1024*HID_],     g_wdkv_l[1024*HID_];
__device__ __nv_bfloat16 g_wukv_h[G_*1024*LAT_],  g_wukv_l[G_*1024*LAT_];
__device__ __nv_bfloat16 g_wo_h  [HID_*HID_],     g_wo_l  [HID_*HID_];
// fp16 attention operands (single precision pass)
__device__ __half g_qf16[(size_t)B_*H_*QL_*HD_];   // [bh][q][d], scale folded
__device__ __half g_kf16[(size_t)B_*H_*KL_*HD_];   // [bh][key][d]
__device__ __half g_vf16[(size_t)B_*H_*HD_*KL_];   // [bh][d][key] (transposed)

// ---------------------------------------------------------------------------
// split fp32 -> (hi, lo) bf16, vectorized by 4
// ---------------------------------------------------------------------------
__global__ __launch_bounds__(256) void split_f32(
    const float* __restrict__ src, __nv_bfloat16* __restrict__ h,
    __nv_bfloat16* __restrict__ l, int n4)
{
    int i = blockIdx.x * 256 + threadIdx.x;
    if (i >= n4) return;
    float4 v = ((const float4*)src)[i];
    __nv_bfloat16 h0 = __float2bfloat16(v.x), h1 = __float2bfloat16(v.y);
    __nv_bfloat16 h2 = __float2bfloat16(v.z), h3 = __float2bfloat16(v.w);
    __nv_bfloat16 l0 = __float2bfloat16(v.x - __bfloat162float(h0));
    __nv_bfloat16 l1 = __float2bfloat16(v.y - __bfloat162float(h1));
    __nv_bfloat16 l2 = __float2bfloat16(v.z - __bfloat162float(h2));
    __nv_bfloat16 l3 = __float2bfloat16(v.w - __bfloat162float(h3));
    ((__nv_bfloat162*)h)[2*i]   = __nv_bfloat162(h0, h1);
    ((__nv_bfloat162*)h)[2*i+1] = __nv_bfloat162(h2, h3);
    ((__nv_bfloat162*)l)[2*i]   = __nv_bfloat162(l0, l1);
    ((__nv_bfloat162*)l)[2*i+1] = __nv_bfloat162(l2, l3);
}

// ---------------------------------------------------------------------------
// transpose + split: src fp32 [R, >=C] (ldS) -> dst bf16 [C, R] hi/lo (ldD=R)
// ---------------------------------------------------------------------------
__global__ __launch_bounds__(256) void transpose_split(
    const float* __restrict__ src, int ldS, long sBatch,
    __nv_bfloat16* __restrict__ dh, __nv_bfloat16* __restrict__ dl,
    int ldD, long dBatch)
{
    src += (long)blockIdx.z * sBatch;
    dh  += (long)blockIdx.z * dBatch;
    dl  += (long)blockIdx.z * dBatch;
    __shared__ float t[32][33];
    const int tx = threadIdx.x, ty = threadIdx.y;
    const int c0 = blockIdx.x * 32, r0 = blockIdx.y * 32;
#pragma unroll
    for (int i = 0; i < 4; i++)
        t[ty + i * 8][tx] = src[(long)(r0 + ty + i * 8) * ldS + c0 + tx];
    __syncthreads();
#pragma unroll
    for (int i = 0; i < 4; i++) {
        float v = t[tx][ty + i * 8];
        __nv_bfloat16 hi = __float2bfloat16(v);
        __nv_bfloat16 lo = __float2bfloat16(v - __bfloat162float(hi));
        long o = (long)(c0 + ty + i * 8) * ldD + r0 + tx;
        dh[o] = hi; dl[o] = lo;
    }
}

// ---------------------------------------------------------------------------
// transpose+split W_uQ, keeping only used cols: dst row n'=h*128+d <- src col
// h*192+d. src [512][3072] -> dst [2048][512]. grid (2048/32, 512/32).
// ---------------------------------------------------------------------------
__global__ __launch_bounds__(256) void transpose_split_gather(
    const float* __restrict__ src,
    __nv_bfloat16* __restrict__ dh, __nv_bfloat16* __restrict__ dl)
{
    __shared__ float t[32][33];
    const int tx = threadIdx.x, ty = threadIdx.y;
    const int c0 = blockIdx.x * 32, r0 = blockIdx.y * 32;
    const int scol0 = (c0 >> 7) * 192 + (c0 & 127);   // 32-block stays in one h
#pragma unroll
    for (int i = 0; i < 4; i++)
        t[ty + i * 8][tx] = src[(long)(r0 + ty + i * 8) * 3072 + scol0 + tx];
    __syncthreads();
#pragma unroll
    for (int i = 0; i < 4; i++) {
        float v = t[tx][ty + i * 8];
        __nv_bfloat16 hi = __float2bfloat16(v);
        __nv_bfloat16 lo = __float2bfloat16(v - __bfloat162float(hi));
        long o = (long)(c0 + ty + i * 8) * QLR_ + r0 + tx;
        dh[o] = hi; dl[o] = lo;
    }
}

// ---------------------------------------------------------------------------
// mma.sync split-bf16 GEMM: C[M,N] fp32 = A[M,K] @ B^T[N,K]
// Block 128x128, 8 warps (2m x 4n, warp tile 64x32), KC=32, 2-stage cp.async.
// Per 16-k step: 3 MMAs per tile (AhBh + AhBl + AlBh).
// ---------------------------------------------------------------------------
#define GSTR   40                    // smem row stride in bf16 (32 data + 8 pad)
#define G_OPB  (128*GSTR*2)          // 10240 B per operand tile
#define G_STG  (4*G_OPB)             // 40960 B per stage
#define GEMM_SMEM (2*G_STG)          // 81920 B

// shared mainloop body for both epilogues (macro keeps one source of truth)
#define GEMM_MAINLOOP()                                                         \
    const uint32_t aLane = (uint32_t)(((lane & 15) * GSTR + (lane >> 4) * 8) * 2); \
    const uint32_t bLane = (uint32_t)(((lane & 7) * GSTR + ((lane >> 3) & 1) * 8) * 2); \
    float acc[4][4][4];                                                         \
    _Pragma("unroll")                                                           \
    for (int i = 0; i < 4; i++)                                                 \
        _Pragma("unroll")                                                       \
        for (int j = 0; j < 4; j++)                                             \
            _Pragma("unroll")                                                   \
            for (int k = 0; k < 4; k++) acc[i][j][k] = 0.f;                     \
    const int nIter = K / 32;                                                   \
    auto load_stage = [&](int it, int s) {                                      \
        uint32_t st = sb + s * G_STG;                                           \
        int k0 = it * 32;                                                       \
        _Pragma("unroll")                                                       \
        for (int i = 0; i < 2; i++) {                                           \
            int idx = tid + i * 256;                                            \
            int r = idx >> 2, c = idx & 3;                                      \
            uint32_t so = (uint32_t)(r * (GSTR*2) + c * 16);                    \
            size_t ga = (size_t)(rowBase + r) * lda + k0 + c * 8;               \
            size_t gb = (size_t)(colBase + r) * ldb + k0 + c * 8;               \
            cpa16(st + so,           Ah + ga);                                  \
            cpa16(st + G_OPB + so,   Al + ga);                                  \
            cpa16(st + 2*G_OPB + so, Bh + gb);                                  \
            cpa16(st + 3*G_OPB + so, Bl + gb);                                  \
        }                                                                       \
        cpa_commit();                                                           \
    };                                                                          \
    load_stage(0, 0);                                                           \
    for (int it = 0; it < nIter; it++) {                                        \
        int s = it & 1;                                                         \
        if (it + 1 < nIter) { load_stage(it + 1, s ^ 1); cpa_wait1(); }         \
        else                { cpa_wait0(); }                                    \
        __syncthreads();                                                        \
        uint32_t st = sb + s * G_STG;                                           \
        _Pragma("unroll")                                                       \
        for (int kk = 0; kk < 2; kk++) {                                        \
            const int kof = kk * 16;                                            \
            uint32_t ah[4][4], al[4][4];                                        \
            _Pragma("unroll")                                                   \
            for (int i = 0; i < 4; i++) {                                       \
                uint32_t base = (uint32_t)(((m0 + i * 16) * GSTR + kof) * 2);   \
                ldsm4(ah[i][0], ah[i][1], ah[i][2], ah[i][3], st + base + aLane); \
                ldsm4(al[i][0], al[i][1], al[i][2], al[i][3], st + G_OPB + base + aLane); \
            }                                                                   \
            _Pragma("unroll")                                                   \
            for (int j = 0; j < 4; j++) {                                       \
                uint32_t base = (uint32_t)(((n0 + j * 8) * GSTR + kof) * 2);    \
                uint32_t bh0, bh1, bl0, bl1;                                    \
                ldsm2(bh0, bh1, st + 2*G_OPB + base + bLane);                   \
                ldsm2(bl0, bl1, st + 3*G_OPB + base + bLane);                   \
                _Pragma("unroll")                                               \
                for (int i = 0; i < 4; i++) {                                   \
                    mma16816(acc[i][j], ah[i][0], ah[i][1], ah[i][2], ah[i][3], bh0, bh1); \
                    mma16816(acc[i][j], ah[i][0], ah[i][1], ah[i][2], ah[i][3], bl0, bl1); \
                    mma16816(acc[i][j], al[i][0], al[i][1], al[i][2], al[i][3], bh0, bh1); \
                }                                                               \
            }                                                                   \
        }                                                                       \
        __syncthreads();                                                        \
    }

__global__ __launch_bounds__(256)
void gemm_mma(const __nv_bfloat16* __restrict__ Ah, const __nv_bfloat16* __restrict__ Al,
              int lda, long aBatch,
              const __nv_bfloat16* __restrict__ Bh, const __nv_bfloat16* __restrict__ Bl,
              int ldb, long bBatch,
              float* __restrict__ C, int ldc, long cBatch, int K)
{
    extern __shared__ __align__(16) char smem[];
    uint32_t sb = smem_u32(smem);
    const int tid = threadIdx.x;
    const int lane = tid & 31, wid = tid >> 5;
    const int m0 = (wid >> 2) * 64, n0 = (wid & 3) * 32;

    Ah += (long)blockIdx.z * aBatch;  Al += (long)blockIdx.z * aBatch;
    Bh += (long)blockIdx.z * bBatch;  Bl += (long)blockIdx.z * bBatch;
    C  += (long)blockIdx.z * cBatch;
    const int rowBase = blockIdx.y * 128;
    const int colBase = blockIdx.x * 128;

    GEMM_MAINLOOP()

#pragma unroll
    for (int i = 0; i < 4; i++) {
        int r0 = rowBase + m0 + i * 16 + (lane >> 2);
#pragma unroll
        for (int j = 0; j < 4; j++) {
            int col = colBase + n0 + j * 8 + (lane & 3) * 2;
            *(float2*)&C[(size_t)r0 * ldc + col]       = make_float2(acc[i][j][0], acc[i][j][1]);
            *(float2*)&C[(size_t)(r0 + 8) * ldc + col] = make_float2(acc[i][j][2], acc[i][j][3]);
        }
    }
}

// Same GEMM, but epilogue writes q fp16 [bh][q][d] with softmax scale folded.
// C row r = b*1024+q, col n = h*128+d.
__global__ __launch_bounds__(256)
void gemm_mma_q(const __nv_bfloat16* __restrict__ Ah, const __nv_bfloat16* __restrict__ Al,
                int lda,
                const __nv_bfloat16* __restrict__ Bh, const __nv_bfloat16* __restrict__ Bl,
                int ldb,
                __half* __restrict__ Q, int K)
{
    extern __shared__ __align__(16) char smem[];
    uint32_t sb = smem_u32(smem);
    const int tid = threadIdx.x;
    const int lane = tid & 31, wid = tid >> 5;
    const int m0 = (wid >> 2) * 64, n0 = (wid & 3) * 32;
    const int rowBase = blockIdx.y * 128;
    const int colBase = blockIdx.x * 128;

    GEMM_MAINLOOP()

    const float scale = 0.08838834764831845f;   // 1/sqrt(128)
    auto qmap = [](int r, int n) -> size_t {
        return ((size_t)(((r >> 10) << 4) + (n >> 7)) * QL_ + (r & 1023)) * HD_ + (n & 127);
    };
#pragma unroll
    for (int i = 0; i < 4; i++) {
        int r0 = rowBase + m0 + i * 16 + (lane >> 2);
#pragma unroll
        for (int j = 0; j < 4; j++) {
            int col = colBase + n0 + j * 8 + (lane & 3) * 2;
            *(__half2*)&Q[qmap(r0, col)] =
                __floats2half2_rn(acc[i][j][0] * scale, acc[i][j][1] * scale);
            *(__half2*)&Q[qmap(r0 + 8, col)] =
                __floats2half2_rn(acc[i][j][2] * scale, acc[i][j][3] * scale);
        }
    }
}

// ---------------------------------------------------------------------------
// RMSNorm over 512 cols (q path) -> split bf16. grid = B*QL, block 256.
// ---------------------------------------------------------------------------
__global__ __launch_bounds__(256) void rmsnorm_q_split(
    const float* __restrict__ x, const float* __restrict__ w,
    __nv_bfloat16* __restrict__ oh, __nv_bfloat16* __restrict__ ol)
{
    const float* p = x + (long)blockIdx.x * QLR_;
    const int t = threadIdx.x;
    float v0 = p[t], v1 = p[t + 256];
    __shared__ float red[256];
    red[t] = v0 * v0 + v1 * v1;
    __syncthreads();
    for (int s = 128; s > 0; s >>= 1) {
        if (t < s) red[t] += red[t + s];
        __syncthreads();
    }
    float inv = rsqrtf(red[0] * (1.f / QLR_) + EPS_);
    long base = (long)blockIdx.x * QLR_;
    float y0 = v0 * inv * w[t], y1 = v1 * inv * w[t + 256];
    __nv_bfloat16 h0 = __float2bfloat16(y0), h1 = __float2bfloat16(y1);
    oh[base + t]       = h0;
    oh[base + t + 256] = h1;
    ol[base + t]       = __float2bfloat16(y0 - __bfloat162float(h0));
    ol[base + t + 256] = __float2bfloat16(y1 - __bfloat162float(h1));
}

// ---------------------------------------------------------------------------
// RMSNorm over LAT=256 per (row, group) -> split bf16. grid = B*KL*G, block 256.
// ---------------------------------------------------------------------------
__global__ __launch_bounds__(256) void rmsnorm_kv_split(
    const float* __restrict__ x, const float* __restrict__ w,
    __nv_bfloat16* __restrict__ oh, __nv_bfloat16* __restrict__ ol)
{
    const int row = blockIdx.x >> 2;
    const int g   = blockIdx.x & 3;
    const long base = (long)row * (G_ * LAT_) + g * LAT_;
    const int t = threadIdx.x;
    float v = x[base + t];
    __shared__ float red[256];
    red[t] = v * v;
    __syncthreads();
    for (int s = 128; s > 0; s >>= 1) {
        if (t < s) red[t] += red[t + s];
        __syncthreads();
    }
    float inv = rsqrtf(red[0] * (1.f / LAT_) + EPS_);
    float y = v * inv * w[g * LAT_ + t];
    __nv_bfloat16 h = __float2bfloat16(y);
    oh[base + t] = h;
    ol[base + t] = __float2bfloat16(y - __bfloat162float(h));
}

// ---------------------------------------------------------------------------
// prep_k: kv fp32 [b,s,h, d(0..127)] -> K fp16 [bh][s][d]
// ---------------------------------------------------------------------------
__global__ __launch_bounds__(256) void prep_k16(
    const float* __restrict__ kv, __half* __restrict__ K)
{
    size_t i = (size_t)blockIdx.x * 256 + threadIdx.x;
    int d = (int)(i & 31) * 4;
    size_t rest = i >> 5;
    int s = (int)(rest & (KL_ - 1));
    rest >>= 12;
    int h = (int)(rest & 15);
    int b = (int)(rest >> 4);
    float4 v = *(const float4*)&kv[((size_t)(b * KL_ + s) * H_ + h) * 256 + d];
    size_t o = ((size_t)(b * H_ + h) * KL_ + s) * HD_ + d;
    ((__half2*)(K + o))[0] = __floats2half2_rn(v.x, v.y);
    ((__half2*)(K + o))[1] = __floats2half2_rn(v.z, v.w);
}

// ---------------------------------------------------------------------------
// prep_v: kv fp32 [b,s,h, 128+d] -> V fp16 [bh][d][s] (transposed)
// grid (KL/32, HD/32, B*H), block (32, 8)
// ---------------------------------------------------------------------------
__global__ __launch_bounds__(256) void prep_v16(
    const float* __restrict__ kv, __half* __restrict__ V)
{
    __shared__ float t[32][33];
    const int bh = blockIdx.z;
    const int b = bh >> 4, h = bh & 15;
    const int s0 = blockIdx.x * 32, d0 = blockIdx.y * 32;
    const int tx = threadIdx.x, ty = threadIdx.y;
#pragma unroll
    for (int i = 0; i < 4; i++)
        t[ty + i * 8][tx] =
            kv[((size_t)(b * KL_ + s0 + ty + i * 8) * H_ + h) * 256 + 128 + d0 + tx];
    __syncthreads();
#pragma unroll
    for (int i = 0; i < 4; i++) {
        size_t o = ((size_t)bh * HD_ + d0 + ty + i * 8) * KL_ + s0 + tx;
        V[o] = __float2half(t[tx][ty + i * 8]);
    }
}

// ---------------------------------------------------------------------------
// flash_fp16: tensor-core flash attention, single-pass fp16.
// grid (QL/64, B*H), 256 threads (8 warps).
// Q [bh][q][d] fp16 (pre-scaled); K [bh][key][d]; V [bh][d][key].
// Per 64-key iter: S = QK^T (1 MMA/tile) -> fp32 online softmax -> P fp16
// (l summed over rounded P) -> O += P@V (1 MMA/tile).
// Epilogue writes attn as split bf16 (hi/lo) directly for the Wo GEMM.
// ---------------------------------------------------------------------------
#define FQ_OFF   0            // Q  fp16 [64][136]     17408 B
#define FK_OFF   17408        // K  fp16 [2][64][136]  34816 B
#define FV_OFF   52224        // V  fp16 [2][128][72]  36864 B
#define FS_OFF   89088        // S  f32  [64][68]      17408 B
#define FP_OFF   106496       // P  fp16 [64][72]       9216 B
#define FST_OFF  115712       // m,l,corr f32 [3][64]    768 B
#define FLASH_SMEM 116480

__global__ __launch_bounds__(256)
void flash_fp16(const __half* __restrict__ Qg,
                const __half* __restrict__ Kg,
                const __half* __restrict__ Vg,
                __nv_bfloat16* __restrict__ outH,
                __nv_bfloat16* __restrict__ outL)
{
    extern __shared__ __align__(16) char smem[];
    uint32_t sb = smem_u32(smem);
    float* Ss  = (float*)(smem + FS_OFF);
    float* m_s = (float*)(smem + FST_OFF);
    float* l_s = m_s + 64;
    float* c_s = l_s + 64;

    const int tid = threadIdx.x, lane = tid & 31, wid = tid >> 5;
    const int bh = blockIdx.y;
    const int b = bh >> 4, h = bh & 15;
    const int q0 = blockIdx.x * 64;

    const __half* Qp = Qg + ((size_t)bh * QL_ + q0) * HD_;
    const __half* Kp = Kg + (size_t)bh * KL_ * HD_;
    const __half* Vp = Vg + (size_t)bh * HD_ * KL_;

    if (tid < 64) { m_s[tid] = -1e30f; l_s[tid] = 0.f; }

    // Q tile 64x128 fp16, row stride 136
#pragma unroll
    for (int i = 0; i < 4; i++) {
        int idx = tid + i * 256;
        int r = idx >> 4, c = idx & 15;
        cpa16(sb + FQ_OFF + r * 272 + c * 16, Qp + (size_t)r * HD_ + c * 8);
    }

    auto load_kv = [&](int it, int s) {
        int key0 = it * 64;
#pragma unroll
        for (int i = 0; i < 4; i++) {
            int idx = tid + i * 256;
            int r = idx >> 4, c = idx & 15;
            cpa16(sb + FK_OFF + (uint32_t)(s * 17408 + r * 272 + c * 16),
                  Kp + (size_t)(key0 + r) * HD_ + c * 8);
        }
#pragma unroll
        for (int i = 0; i < 4; i++) {
            int idx = tid + i * 256;
            int r = idx >> 3, c = idx & 7;
            cpa16(sb + FV_OFF + (uint32_t)(s * 18432 + r * 144 + c * 16),
                  Vp + (size_t)r * KL_ + key0 + c * 8);
        }
        cpa_commit();
    };

    load_kv(0, 0);   // one group: Q + K/V stage 0

    const int wm16 = (wid >> 1) * 16;       // row strip
    const int sn0  = (wid & 1) * 32;        // S col strip (QK)
    const int on0  = (wid & 1) * 64;        // O col strip (PV)
    const uint32_t aLaneQ = (uint32_t)(((lane & 15) * 136 + (lane >> 4) * 8) * 2);
    const uint32_t bLaneK = (uint32_t)(((lane & 7) * 136 + ((lane >> 3) & 1) * 8) * 2);
    const uint32_t aLaneP = (uint32_t)(((lane & 15) * 72 + (lane >> 4) * 8) * 2);
    const uint32_t bLaneV = (uint32_t)(((lane & 7) * 72 + ((lane >> 3) & 1) * 8) * 2);

    uint32_t qa[8][4];
    float oacc[8][4];
#pragma unroll
    for (int j = 0; j < 8; j++)
#pragma unroll
        for (int k = 0; k < 4; k++) oacc[j][k] = 0.f;

    const int nIter = KL_ / 64;
    for (int it = 0; it < nIter; it++) {
        int s = it & 1;
        if (it + 1 < nIter) { load_kv(it + 1, s ^ 1); cpa_wait1(); }
        else                { cpa_wait0(); }
        __syncthreads();

        if (it == 0) {   // Q frags persist across iterations
#pragma unroll
            for (int kd = 0; kd < 8; kd++)
                ldsm4(qa[kd][0], qa[kd][1], qa[kd][2], qa[kd][3],
                      sb + FQ_OFF + (uint32_t)((wm16 * 136 + kd * 16) * 2) + aLaneQ);
        }

        // ---- S = Q @ K^T  (warp: 16 x 32) ----
        uint32_t kst = sb + FK_OFF + (uint32_t)(s * 17408);
        float sacc[4][4];
#pragma unroll
        for (int j = 0; j < 4; j++)
#pragma unroll
            for (int k = 0; k < 4; k++) sacc[j][k] = 0.f;
#pragma unroll
        for (int kd = 0; kd < 8; kd++) {
#pragma unroll
            for (int j = 0; j < 4; j++) {
                uint32_t b0, b1;
                ldsm2(b0, b1, kst + (uint32_t)(((sn0 + j * 8) * 136 + kd * 16) * 2) + bLaneK);
                mma16816h(sacc[j], qa[kd][0], qa[kd][1], qa[kd][2], qa[kd][3], b0, b1);
            }
        }
#pragma unroll
        for (int j = 0; j < 4; j++) {
            int r = wm16 + (lane >> 2);
            int cidx = sn0 + j * 8 + (lane & 3) * 2;
            *(float2*)&Ss[r * 68 + cidx]       = make_float2(sacc[j][0], sacc[j][1]);
            *(float2*)&Ss[(r + 8) * 68 + cidx] = make_float2(sacc[j][2], sacc[j][3]);
        }
        __syncthreads();

        // ---- online softmax (4 threads per row), P fp16 ----
        {
            int row = tid >> 2, seg = tid & 3;
            float* sr = Ss + row * 68 + seg * 16;
            float tmax = sr[0];
#pragma unroll
            for (int c = 1; c < 16; c++) tmax = fmaxf(tmax, sr[c]);
            tmax = fmaxf(tmax, __shfl_xor_sync(0xffffffffu, tmax, 1));
            tmax = fmaxf(tmax, __shfl_xor_sync(0xffffffffu, tmax, 2));
            float mold = m_s[row];
            float mnew = fmaxf(mold, tmax);
            float corr = __expf(mold - mnew);
            __half* pr = (__half*)(smem + FP_OFF) + row * 72 + seg * 16;
            float sum = 0.f;
#pragma unroll
            for (int c = 0; c < 16; c++) {
                float p = __expf(sr[c] - mnew);
                __half ph = __float2half(p);
                pr[c] = ph;
                sum += __half2float(ph);   // self-normalizing: l over rounded P
            }
            sum += __shfl_xor_sync(0xffffffffu, sum, 1);
            sum += __shfl_xor_sync(0xffffffffu, sum, 2);
            if (seg == 0) {
                m_s[row] = mnew;
                l_s[row] = l_s[row] * corr + sum;
                c_s[row] = corr;
            }
        }
        __syncthreads();

        // ---- O = O*corr + P @ V  (warp: 16 x 64) ----
        {
            float clo = c_s[wm16 + (lane >> 2)];
            float chi = c_s[wm16 + 8 + (lane >> 2)];
#pragma unroll
            for (int j = 0; j < 8; j++) {
                oacc[j][0] *= clo; oacc[j][1] *= clo;
                oacc[j][2] *= chi; oacc[j][3] *= chi;
            }
            uint32_t vst = sb + FV_OFF + (uint32_t)(s * 18432);
#pragma unroll
            for (int kk = 0; kk < 4; kk++) {
                uint32_t a0, a1, a2, a3;
                ldsm4(a0, a1, a2, a3,
                      sb + FP_OFF + (uint32_t)((wm16 * 72 + kk * 16) * 2) + aLaneP);
#pragma unroll
                for (int j = 0; j < 8; j++) {
                    uint32_t b0, b1;
                    ldsm2(b0, b1, vst + (uint32_t)(((on0 + j * 8) * 72 + kk * 16) * 2) + bLaneV);
                    mma16816h(oacc[j], a0, a1, a2, a3, b0, b1);
                }
            }
        }
        __syncthreads();
    }

    // epilogue: normalize, write attn split-bf16 [b, q, h*128 + d]
    {
        float ilo = 1.f / l_s[wm16 + (lane >> 2)];
        float ihi = 1.f / l_s[wm16 + 8 + (lane >> 2)];
        int r = q0 + wm16 + (lane >> 2);
#pragma unroll
        for (int j = 0; j < 8; j++) {
            int col = h * HD_ + on0 + j * 8 + (lane & 3) * 2;
            float a0 = oacc[j][0] * ilo, a1 = oacc[j][1] * ilo;
            float a2 = oacc[j][2] * ihi, a3 = oacc[j][3] * ihi;
            __nv_bfloat16 h0 = __float2bfloat16(a0), h1 = __float2bfloat16(a1);
            __nv_bfloat16 h2 = __float2bfloat16(a2), h3 = __float2bfloat16(a3);
            size_t o0 = (size_t)(b * QL_ + r) * (H_ * HD_) + col;
            size_t o1 = (size_t)(b * QL_ + r + 8) * (H_ * HD_) + col;
            *(__nv_bfloat162*)&outH[o0] = __nv_bfloat162(h0, h1);
            *(__nv_bfloat162*)&outH[o1] = __nv_bfloat162(h2, h3);
            *(__nv_bfloat162*)&outL[o0] = __nv_bfloat162(
                __float2bfloat16(a0 - __bfloat162float(h0)),
                __float2bfloat16(a1 - __bfloat162float(h1)));
            *(__nv_bfloat162*)&outL[o1] = __nv_bfloat162(
                __float2bfloat16(a2 - __bfloat162float(h2)),
                __float2bfloat16(a3 - __bfloat162float(h3)));
        }
    }
}

// ---------------------------------------------------------------------------
// Launch
// ---------------------------------------------------------------------------
extern "C" void kernel_launch(void* const* d_in, const int* in_sizes, int n_in,
                              void* d_out, int out_size)
{
    const float* x_q       = (const float*)d_in[0];
    const float* x_kv      = (const float*)d_in[1];
    const float* W_dQ      = (const float*)d_in[2];
    const float* q_norm_w  = (const float*)d_in[3];
    const float* W_uQ      = (const float*)d_in[4];
    const float* W_dKV     = (const float*)d_in[5];
    const float* kv_norm_w = (const float*)d_in[6];
    const float* W_ukv     = (const float*)d_in[7];
    const float* W_o       = (const float*)d_in[8];
    float* out = (float*)d_out;

    float *qlat, *ckv, *kv;
    cudaGetSymbolAddress((void**)&qlat,  g_qlat);
    cudaGetSymbolAddress((void**)&ckv,   g_ckv);
    cudaGetSymbolAddress((void**)&kv,    g_kv);

    __nv_bfloat16 *xqh,*xql,*xkvh,*xkvl,*qnh,*qnl,*ckvh,*ckvl,*ath,*atl;
    __nv_bfloat16 *wdqh,*wdql,*wuqh,*wuql,*wdkvh,*wdkvl,*wukvh,*wukvl,*woh,*wol;
    __half *qf,*kf,*vf;
    cudaGetSymbolAddress((void**)&xqh,  g_xq_h);   cudaGetSymbolAddress((void**)&xql,  g_xq_l);
    cudaGetSymbolAddress((void**)&xkvh, g_xkv_h);  cudaGetSymbolAddress((void**)&xkvl, g_xkv_l);
    cudaGetSymbolAddress((void**)&qnh,  g_qn_h);   cudaGetSymbolAddress((void**)&qnl,  g_qn_l);
    cudaGetSymbolAddress((void**)&ckvh, g_ckvn_h); cudaGetSymbolAddress((void**)&ckvl, g_ckvn_l);
    cudaGetSymbolAddress((void**)&ath,  g_at_h);   cudaGetSymbolAddress((void**)&atl,  g_at_l);
    cudaGetSymbolAddress((void**)&wdqh, g_wdq_h);  cudaGetSymbolAddress((void**)&wdql, g_wdq_l);
    cudaGetSymbolAddress((void**)&wuqh, g_wuq_h);  cudaGetSymbolAddress((void**)&wuql, g_wuq_l);
    cudaGetSymbolAddress((void**)&wdkvh,g_wdkv_h); cudaGetSymbolAddress((void**)&wdkvl,g_wdkv_l);
    cudaGetSymbolAddress((void**)&wukvh,g_wukv_h); cudaGetSymbolAddress((void**)&wukvl,g_wukv_l);
    cudaGetSymbolAddress((void**)&woh,  g_wo_h);   cudaGetSymbolAddress((void**)&wol,  g_wo_l);
    cudaGetSymbolAddress((void**)&qf,   g_qf16);
    cudaGetSymbolAddress((void**)&kf,   g_kf16);
    cudaGetSymbolAddress((void**)&vf,   g_vf16);

    cudaFuncSetAttribute(gemm_mma,   cudaFuncAttributeMaxDynamicSharedMemorySize, GEMM_SMEM);
    cudaFuncSetAttribute(gemm_mma_q, cudaFuncAttributeMaxDynamicSharedMemorySize, GEMM_SMEM);
    cudaFuncSetAttribute(flash_fp16, cudaFuncAttributeMaxDynamicSharedMemorySize, FLASH_SMEM);

    const int M_q  = B_ * QL_;   // 2048
    const int M_kv = B_ * KL_;   // 8192
    dim3 t32x8(32, 8);

    // --- input splits + weight transpose/splits ---
    { int n4 = (M_q * HID_) / 4;  split_f32<<<(n4+255)/256, 256>>>(x_q,  xqh,  xql,  n4); }
    { int n4 = (M_kv * HID_) / 4; split_f32<<<(n4+255)/256, 256>>>(x_kv, xkvh, xkvl, n4); }
    transpose_split<<<dim3(QLR_/32, HID_/32), t32x8>>>(W_dQ, QLR_, 0, wdqh, wdql, HID_, 0);
    transpose_split_gather<<<dim3(2048/32, QLR_/32), t32x8>>>(W_uQ, wuqh, wuql);
    transpose_split<<<dim3(1024/32, HID_/32), t32x8>>>(W_dKV, 1088, 0, wdkvh, wdkvl, HID_, 0);
    transpose_split<<<dim3(1024/32, LAT_/32, G_), t32x8>>>(
        W_ukv, 1024, (long)LAT_*1024, wukvh, wukvl, LAT_, (long)1024*LAT_);
    transpose_split<<<dim3(HID_/32, HID_/32), t32x8>>>(W_o, HID_, 0, woh, wol, HID_, 0);

    // 1) q_lat = x_q @ W_dQ    [2048x2048] x [512x2048]^T
    gemm_mma<<<dim3(QLR_/128, M_q/128, 1), 256, GEMM_SMEM>>>(
        xqh, xql, HID_, 0, wdqh, wdql, HID_, 0, qlat, QLR_, 0, HID_);
    // 2) rmsnorm + split
    rmsnorm_q_split<<<M_q, 256>>>(qlat, q_norm_w, qnh, qnl);
    // 3) q fp16 = (qn @ W_uQ_gathered) * scale, laid out [bh][q][d]
    gemm_mma_q<<<dim3(2048/128, M_q/128, 1), 256, GEMM_SMEM>>>(
        qnh, qnl, QLR_, wuqh, wuql, QLR_, qf, QLR_);
    // 4) ckv = (x_kv @ W_dKV)[:, :1024]
    gemm_mma<<<dim3(1024/128, M_kv/128, 1), 256, GEMM_SMEM>>>(
        xkvh, xkvl, HID_, 0, wdkvh, wdkvl, HID_, 0, ckv, 1024, 0, HID_);
    // 5) rmsnorm per (row, group) + split
    rmsnorm_kv_split<<<M_kv * G_, 256>>>(ckv, kv_norm_w, ckvh, ckvl);
    // 6) kv[:, g*1024:(g+1)*1024] = ckvn[:, g] @ W_ukv[g]  (batched over g)
    gemm_mma<<<dim3(1024/128, M_kv/128, G_), 256, GEMM_SMEM>>>(
        ckvh, ckvl, G_*LAT_, LAT_,
        wukvh, wukvl, LAT_, (long)1024*LAT_,
        kv, H_*2*HD_, 1024, LAT_);
    // 7) fp16 K/V prep
    prep_k16<<<(int)(((size_t)B_*H_*KL_*32)/256), 256>>>(kv, kf);
    prep_v16<<<dim3(KL_/32, HD_/32, B_*H_), t32x8>>>(kv, vf);
    // 8) fp16 flash attention -> attn split-bf16 (hi/lo)
    flash_fp16<<<dim3(QL_/64, B_*H_), 256, FLASH_SMEM>>>(qf, kf, vf, ath, atl);
    // 9) out = attn @ W_o  (split-bf16)
    gemm_mma<<<dim3(HID_/128, M_q/128, 1), 256, GEMM_SMEM>>>(
        ath, atl, H_*HD_, 0, woh, wol, HID_, 0, out, HID_, 0, H_*HD_);
}

// round 14
// speedup vs baseline: 6.8757x; 1.5242x over previous
#include <cuda_runtime.h>
#include <cuda_bf16.h>
#include <cuda_fp16.h>
#include <cstdint>

// ---------------------------------------------------------------------------
// GLACrossAttention: B=2 QL=1024 KL=4096 HID=2048 H=16 HD=128 RD=64
//                    G=4 HPG=4 QLR=512 LAT=256 EPS=1e-6
// Round 14: everything single-pass fp16 mma (validated error model:
//           0.6*half-ulp per MMA source => ~1.5e-4 per GEMM; 5 GEMMs +
//           attention ~2.8e-4 => ~4.4e-4 total, under 1e-3).
//           kv up-proj epilogue writes K/V fp16 operands DIRECTLY
//           (kills 128MB fp32 g_kv round trip + prep_k + prep_v).
// ---------------------------------------------------------------------------

#define B_    2
#define QL_   1024
#define KL_   4096
#define HID_  2048
#define H_    16
#define HD_   128
#define RD_   64
#define G_    4
#define QLR_  512
#define LAT_  256
#define EPS_  1e-6f

// ---------------------------------------------------------------------------
// PTX helpers (baseline PTX, legal on compute_103)
// ---------------------------------------------------------------------------
__device__ __forceinline__ uint32_t smem_u32(const void* p) {
    uint32_t a;
    asm("{ .reg .u64 t; cvta.to.shared.u64 t, %1; cvt.u32.u64 %0, t; }"
        : "=r"(a) : "l"(p));
    return a;
}
__device__ __forceinline__ void cpa16(uint32_t dst, const void* src) {
    asm volatile("cp.async.cg.shared.global [%0], [%1], 16;\n" :: "r"(dst), "l"(src));
}
__device__ __forceinline__ void cpa_commit() {
    asm volatile("cp.async.commit_group;\n" ::: "memory");
}
__device__ __forceinline__ void cpa_wait1() {
    asm volatile("cp.async.wait_group 1;\n" ::: "memory");
}
__device__ __forceinline__ void cpa_wait0() {
    asm volatile("cp.async.wait_group 0;\n" ::: "memory");
}
__device__ __forceinline__ void ldsm4(uint32_t& r0, uint32_t& r1, uint32_t& r2,
                                      uint32_t& r3, uint32_t addr) {
    asm volatile("ldmatrix.sync.aligned.m8n8.x4.shared.b16 {%0,%1,%2,%3}, [%4];"
        : "=r"(r0), "=r"(r1), "=r"(r2), "=r"(r3) : "r"(addr));
}
__device__ __forceinline__ void ldsm2(uint32_t& r0, uint32_t& r1, uint32_t addr) {
    asm volatile("ldmatrix.sync.aligned.m8n8.x2.shared.b16 {%0,%1}, [%2];"
        : "=r"(r0), "=r"(r1) : "r"(addr));
}
// D(16x8,f32) += A(16x16 fp16, row) * B(16x8 fp16, col)
__device__ __forceinline__ void mma16816h(float* c, uint32_t a0, uint32_t a1,
                                          uint32_t a2, uint32_t a3,
                                          uint32_t b0, uint32_t b1) {
    asm volatile("mma.sync.aligned.m16n8k16.row.col.f32.f16.f16.f32 "
        "{%0,%1,%2,%3}, {%4,%5,%6,%7}, {%8,%9}, {%0,%1,%2,%3};"
        : "+f"(c[0]), "+f"(c[1]), "+f"(c[2]), "+f"(c[3])
        : "r"(a0), "r"(a1), "r"(a2), "r"(a3), "r"(b0), "r"(b1));
}

// ---------------------------------------------------------------------------
// Scratch (device globals; allocation-free contract)
// ---------------------------------------------------------------------------
__device__ float g_qlat [B_*QL_*QLR_];                 // 4 MB
__device__ float g_ckv  [B_*KL_*G_*LAT_];              // 32 MB
// fp16 activations
__device__ __half g_xq16  [B_*QL_*HID_];
__device__ __half g_xkv16 [B_*KL_*HID_];
__device__ __half g_qn16  [B_*QL_*QLR_];
__device__ __half g_ckvn16[B_*KL_*G_*LAT_];
__device__ __half g_at16  [B_*QL_*H_*HD_];
// fp16 transposed weights [N][K]
__device__ __half g_wdq16 [QLR_*HID_];
__device__ __half g_wuq16 [2048*QLR_];                 // gathered (RD cols dropped)
__device__ __half g_wdkv16[1024*HID_];
__device__ __half g_wukv16[G_*1024*LAT_];
__device__ __half g_wo16  [HID_*HID_];
// fp16 attention operands
__device__ __half g_qf16[(size_t)B_*H_*QL_*HD_];       // [bh][q][d], scale folded
__device__ __half g_kf16[(size_t)B_*H_*KL_*HD_];       // [bh][key][d]
__device__ __half g_vf16[(size_t)B_*H_*HD_*KL_];       // [bh][d][key] (transposed)

// ---------------------------------------------------------------------------
// fp32 -> fp16 cast, vectorized by 4
// ---------------------------------------------------------------------------
__global__ __launch_bounds__(256) void conv16(
    const float* __restrict__ src, __half* __restrict__ dst, int n4)
{
    int i = blockIdx.x * 256 + threadIdx.x;
    if (i >= n4) return;
    float4 v = ((const float4*)src)[i];
    ((__half2*)dst)[2*i]   = __floats2half2_rn(v.x, v.y);
    ((__half2*)dst)[2*i+1] = __floats2half2_rn(v.z, v.w);
}

// ---------------------------------------------------------------------------
// transpose: src fp32 [R, >=C] (ldS) -> dst fp16 [C, R] (ldD=R), batched
// ---------------------------------------------------------------------------
__global__ __launch_bounds__(256) void transpose16(
    const float* __restrict__ src, int ldS, long sBatch,
    __half* __restrict__ dst, int ldD, long dBatch)
{
    src += (long)blockIdx.z * sBatch;
    dst += (long)blockIdx.z * dBatch;
    __shared__ float t[32][33];
    const int tx = threadIdx.x, ty = threadIdx.y;
    const int c0 = blockIdx.x * 32, r0 = blockIdx.y * 32;
#pragma unroll
    for (int i = 0; i < 4; i++)
        t[ty + i * 8][tx] = src[(long)(r0 + ty + i * 8) * ldS + c0 + tx];
    __syncthreads();
#pragma unroll
    for (int i = 0; i < 4; i++)
        dst[(long)(c0 + ty + i * 8) * ldD + r0 + tx] = __float2half(t[tx][ty + i * 8]);
}

// ---------------------------------------------------------------------------
// transpose W_uQ keeping only used cols: dst row n'=h*128+d <- src col h*192+d.
// src [512][3072] -> dst [2048][512]. grid (2048/32, 512/32).
// ---------------------------------------------------------------------------
__global__ __launch_bounds__(256) void transpose16_gather(
    const float* __restrict__ src, __half* __restrict__ dst)
{
    __shared__ float t[32][33];
    const int tx = threadIdx.x, ty = threadIdx.y;
    const int c0 = blockIdx.x * 32, r0 = blockIdx.y * 32;
    const int scol0 = (c0 >> 7) * 192 + (c0 & 127);   // 32-block stays in one h
#pragma unroll
    for (int i = 0; i < 4; i++)
        t[ty + i * 8][tx] = src[(long)(r0 + ty + i * 8) * 3072 + scol0 + tx];
    __syncthreads();
#pragma unroll
    for (int i = 0; i < 4; i++)
        dst[(long)(c0 + ty + i * 8) * QLR_ + r0 + tx] = __float2half(t[tx][ty + i * 8]);
}

// ---------------------------------------------------------------------------
// fp16 single-pass GEMM: C[M,N] fp32 = A[M,K] @ B^T[N,K]
// Block 128x128, 8 warps (2m x 4n, warp tile 64x32), KC=32, 2-stage cp.async.
// ---------------------------------------------------------------------------
#define GSTR   40                    // smem row stride in fp16 (32 data + 8 pad)
#define G_OPB  (128*GSTR*2)          // 10240 B per operand tile
#define G_STG  (2*G_OPB)             // 20480 B per stage
#define GEMM_SMEM (2*G_STG)          // 40960 B

#define GEMM16_MAINLOOP()                                                       \
    const uint32_t aLane = (uint32_t)(((lane & 15) * GSTR + (lane >> 4) * 8) * 2); \
    const uint32_t bLane = (uint32_t)(((lane & 7) * GSTR + ((lane >> 3) & 1) * 8) * 2); \
    float acc[4][4][4];                                                         \
    _Pragma("unroll")                                                           \
    for (int i = 0; i < 4; i++)                                                 \
        _Pragma("unroll")                                                       \
        for (int j = 0; j < 4; j++)                                             \
            _Pragma("unroll")                                                   \
            for (int k = 0; k < 4; k++) acc[i][j][k] = 0.f;                     \
    const int nIter = K / 32;                                                   \
    auto load_stage = [&](int it, int s) {                                      \
        uint32_t st = sb + s * G_STG;                                           \
        int k0 = it * 32;                                                       \
        _Pragma("unroll")                                                       \
        for (int i = 0; i < 2; i++) {                                           \
            int idx = tid + i * 256;                                            \
            int r = idx >> 2, c = idx & 3;                                      \
            uint32_t so = (uint32_t)(r * (GSTR*2) + c * 16);                    \
            cpa16(st + so,         A + (size_t)(rowBase + r) * lda + k0 + c * 8); \
            cpa16(st + G_OPB + so, Bm + (size_t)(colBase + r) * ldb + k0 + c * 8); \
        }                                                                       \
        cpa_commit();                                                           \
    };                                                                          \
    load_stage(0, 0);                                                           \
    for (int it = 0; it < nIter; it++) {                                        \
        int s = it & 1;                                                         \
        if (it + 1 < nIter) { load_stage(it + 1, s ^ 1); cpa_wait1(); }         \
        else                { cpa_wait0(); }                                    \
        __syncthreads();                                                        \
        uint32_t st = sb + s * G_STG;                                           \
        _Pragma("unroll")                                                       \
        for (int kk = 0; kk < 2; kk++) {                                        \
            const int kof = kk * 16;                                            \
            uint32_t af[4][4];                                                  \
            _Pragma("unroll")                                                   \
            for (int i = 0; i < 4; i++)                                         \
                ldsm4(af[i][0], af[i][1], af[i][2], af[i][3],                   \
                      st + (uint32_t)(((m0 + i * 16) * GSTR + kof) * 2) + aLane); \
            _Pragma("unroll")                                                   \
            for (int j = 0; j < 4; j++) {                                       \
                uint32_t b0, b1;                                                \
                ldsm2(b0, b1, st + G_OPB +                                      \
                      (uint32_t)(((n0 + j * 8) * GSTR + kof) * 2) + bLane);     \
                _Pragma("unroll")                                               \
                for (int i = 0; i < 4; i++)                                     \
                    mma16816h(acc[i][j], af[i][0], af[i][1], af[i][2], af[i][3], b0, b1); \
            }                                                                   \
        }                                                                       \
        __syncthreads();                                                        \
    }

// --- variant 1: fp32 C output (qlat, ckv, final out) ---
__global__ __launch_bounds__(256)
void gemm16(const __half* __restrict__ A, int lda,
            const __half* __restrict__ Bm, int ldb,
            float* __restrict__ C, int ldc, int K)
{
    extern __shared__ __align__(16) char smem[];
    uint32_t sb = smem_u32(smem);
    const int tid = threadIdx.x, lane = tid & 31, wid = tid >> 5;
    const int m0 = (wid >> 2) * 64, n0 = (wid & 3) * 32;
    const int rowBase = blockIdx.y * 128, colBase = blockIdx.x * 128;

    GEMM16_MAINLOOP()

#pragma unroll
    for (int i = 0; i < 4; i++) {
        int r0 = rowBase + m0 + i * 16 + (lane >> 2);
#pragma unroll
        for (int j = 0; j < 4; j++) {
            int col = colBase + n0 + j * 8 + (lane & 3) * 2;
            *(float2*)&C[(size_t)r0 * ldc + col]       = make_float2(acc[i][j][0], acc[i][j][1]);
            *(float2*)&C[(size_t)(r0 + 8) * ldc + col] = make_float2(acc[i][j][2], acc[i][j][3]);
        }
    }
}

// --- variant 2: q epilogue -> fp16 [bh][q][d], softmax scale folded ---
__global__ __launch_bounds__(256)
void gemm16_q(const __half* __restrict__ A, int lda,
              const __half* __restrict__ Bm, int ldb,
              __half* __restrict__ Q, int K)
{
    extern __shared__ __align__(16) char smem[];
    uint32_t sb = smem_u32(smem);
    const int tid = threadIdx.x, lane = tid & 31, wid = tid >> 5;
    const int m0 = (wid >> 2) * 64, n0 = (wid & 3) * 32;
    const int rowBase = blockIdx.y * 128, colBase = blockIdx.x * 128;

    GEMM16_MAINLOOP()

    const float scale = 0.08838834764831845f;   // 1/sqrt(128)
    auto qmap = [](int r, int n) -> size_t {
        return ((size_t)(((r >> 10) << 4) + (n >> 7)) * QL_ + (r & 1023)) * HD_ + (n & 127);
    };
#pragma unroll
    for (int i = 0; i < 4; i++) {
        int r0 = rowBase + m0 + i * 16 + (lane >> 2);
#pragma unroll
        for (int j = 0; j < 4; j++) {
            int col = colBase + n0 + j * 8 + (lane & 3) * 2;
            *(__half2*)&Q[qmap(r0, col)] =
                __floats2half2_rn(acc[i][j][0] * scale, acc[i][j][1] * scale);
            *(__half2*)&Q[qmap(r0 + 8, col)] =
                __floats2half2_rn(acc[i][j][2] * scale, acc[i][j][3] * scale);
        }
    }
}

// --- variant 3: kv up-proj epilogue -> K fp16 [bh][s][d] / V fp16 [bh][d][s] ---
// A row r = b*4096+s; col n (0..1023) within group g=blockIdx.z.
// head h = g*4 + (col>>8); whole 128-col CTA tile is K-half or V-half.
__global__ __launch_bounds__(256)
void gemm16_kv(const __half* __restrict__ A, int lda, long aBatch,
               const __half* __restrict__ Bm, int ldb, long bBatch,
               __half* __restrict__ Kd, __half* __restrict__ Vd, int K)
{
    extern __shared__ __align__(16) char smem[];
    uint32_t sb = smem_u32(smem);
    const int tid = threadIdx.x, lane = tid & 31, wid = tid >> 5;
    const int m0 = (wid >> 2) * 64, n0 = (wid & 3) * 32;
    const int rowBase = blockIdx.y * 128, colBase = blockIdx.x * 128;
    const int g = blockIdx.z;
    A  += (long)g * aBatch;
    Bm += (long)g * bBatch;

    GEMM16_MAINLOOP()

    const int h = g * 4 + (colBase >> 8);
    const bool isV = (colBase >> 7) & 1;
#pragma unroll
    for (int i = 0; i < 4; i++) {
        int r0 = rowBase + m0 + i * 16 + (lane >> 2);
        int b = r0 >> 12, s = r0 & 4095;
        int bh = b * H_ + h;
#pragma unroll
        for (int j = 0; j < 4; j++) {
            int col = colBase + n0 + j * 8 + (lane & 3) * 2;
            int dd = col & 127;
            if (!isV) {
                size_t o0 = ((size_t)bh * KL_ + s) * HD_ + dd;
                size_t o1 = ((size_t)bh * KL_ + s + 8) * HD_ + dd;
                *(__half2*)&Kd[o0] = __floats2half2_rn(acc[i][j][0], acc[i][j][1]);
                *(__half2*)&Kd[o1] = __floats2half2_rn(acc[i][j][2], acc[i][j][3]);
            } else {
                size_t base0 = ((size_t)bh * HD_ + dd) * KL_;
                size_t base1 = ((size_t)bh * HD_ + dd + 1) * KL_;
                Vd[base0 + s]     = __float2half(acc[i][j][0]);
                Vd[base1 + s]     = __float2half(acc[i][j][1]);
                Vd[base0 + s + 8] = __float2half(acc[i][j][2]);
                Vd[base1 + s + 8] = __float2half(acc[i][j][3]);
            }
        }
    }
}

// ---------------------------------------------------------------------------
// RMSNorm over 512 cols (q path) -> fp16. grid = B*QL, block 256.
// ---------------------------------------------------------------------------
__global__ __launch_bounds__(256) void rmsnorm_q16(
    const float* __restrict__ x, const float* __restrict__ w,
    __half* __restrict__ o)
{
    const float* p = x + (long)blockIdx.x * QLR_;
    const int t = threadIdx.x;
    float v0 = p[t], v1 = p[t + 256];
    __shared__ float red[256];
    red[t] = v0 * v0 + v1 * v1;
    __syncthreads();
    for (int s = 128; s > 0; s >>= 1) {
        if (t < s) red[t] += red[t + s];
        __syncthreads();
    }
    float inv = rsqrtf(red[0] * (1.f / QLR_) + EPS_);
    long base = (long)blockIdx.x * QLR_;
    o[base + t]       = __float2half(v0 * inv * w[t]);
    o[base + t + 256] = __float2half(v1 * inv * w[t + 256]);
}

// ---------------------------------------------------------------------------
// RMSNorm over LAT=256 per (row, group) -> fp16. grid = B*KL*G, block 256.
// ---------------------------------------------------------------------------
__global__ __launch_bounds__(256) void rmsnorm_kv16(
    const float* __restrict__ x, const float* __restrict__ w,
    __half* __restrict__ o)
{
    const int row = blockIdx.x >> 2;
    const int g   = blockIdx.x & 3;
    const long base = (long)row * (G_ * LAT_) + g * LAT_;
    const int t = threadIdx.x;
    float v = x[base + t];
    __shared__ float red[256];
    red[t] = v * v;
    __syncthreads();
    for (int s = 128; s > 0; s >>= 1) {
        if (t < s) red[t] += red[t + s];
        __syncthreads();
    }
    float inv = rsqrtf(red[0] * (1.f / LAT_) + EPS_);
    o[base + t] = __float2half(v * inv * w[g * LAT_ + t]);
}

// ---------------------------------------------------------------------------
// flash_fp16: tensor-core flash attention, single-pass fp16.
// grid (QL/64, B*H), 256 threads (8 warps). Epilogue writes attn fp16
// [b, q, h*128+d] (the Wo GEMM's A layout).
// ---------------------------------------------------------------------------
#define FQ_OFF   0            // Q  fp16 [64][136]     17408 B
#define FK_OFF   17408        // K  fp16 [2][64][136]  34816 B
#define FV_OFF   52224        // V  fp16 [2][128][72]  36864 B
#define FS_OFF   89088        // S  f32  [64][68]      17408 B
#define FP_OFF   106496       // P  fp16 [64][72]       9216 B
#define FST_OFF  115712       // m,l,corr f32 [3][64]    768 B
#define FLASH_SMEM 116480

__global__ __launch_bounds__(256)
void flash_fp16(const __half* __restrict__ Qg,
                const __half* __restrict__ Kg,
                const __half* __restrict__ Vg,
                __half* __restrict__ outF)
{
    extern __shared__ __align__(16) char smem[];
    uint32_t sb = smem_u32(smem);
    float* Ss  = (float*)(smem + FS_OFF);
    float* m_s = (float*)(smem + FST_OFF);
    float* l_s = m_s + 64;
    float* c_s = l_s + 64;

    const int tid = threadIdx.x, lane = tid & 31, wid = tid >> 5;
    const int bh = blockIdx.y;
    const int b = bh >> 4, h = bh & 15;
    const int q0 = blockIdx.x * 64;

    const __half* Qp = Qg + ((size_t)bh * QL_ + q0) * HD_;
    const __half* Kp = Kg + (size_t)bh * KL_ * HD_;
    const __half* Vp = Vg + (size_t)bh * HD_ * KL_;

    if (tid < 64) { m_s[tid] = -1e30f; l_s[tid] = 0.f; }

#pragma unroll
    for (int i = 0; i < 4; i++) {
        int idx = tid + i * 256;
        int r = idx >> 4, c = idx & 15;
        cpa16(sb + FQ_OFF + r * 272 + c * 16, Qp + (size_t)r * HD_ + c * 8);
    }

    auto load_kv = [&](int it, int s) {
        int key0 = it * 64;
#pragma unroll
        for (int i = 0; i < 4; i++) {
            int idx = tid + i * 256;
            int r = idx >> 4, c = idx & 15;
            cpa16(sb + FK_OFF + (uint32_t)(s * 17408 + r * 272 + c * 16),
                  Kp + (size_t)(key0 + r) * HD_ + c * 8);
        }
#pragma unroll
        for (int i = 0; i < 4; i++) {
            int idx = tid + i * 256;
            int r = idx >> 3, c = idx & 7;
            cpa16(sb + FV_OFF + (uint32_t)(s * 18432 + r * 144 + c * 16),
                  Vp + (size_t)r * KL_ + key0 + c * 8);
        }
        cpa_commit();
    };

    load_kv(0, 0);

    const int wm16 = (wid >> 1) * 16;
    const int sn0  = (wid & 1) * 32;
    const int on0  = (wid & 1) * 64;
    const uint32_t aLaneQ = (uint32_t)(((lane & 15) * 136 + (lane >> 4) * 8) * 2);
    const uint32_t bLaneK = (uint32_t)(((lane & 7) * 136 + ((lane >> 3) & 1) * 8) * 2);
    const uint32_t aLaneP = (uint32_t)(((lane & 15) * 72 + (lane >> 4) * 8) * 2);
    const uint32_t bLaneV = (uint32_t)(((lane & 7) * 72 + ((lane >> 3) & 1) * 8) * 2);

    uint32_t qa[8][4];
    float oacc[8][4];
#pragma unroll
    for (int j = 0; j < 8; j++)
#pragma unroll
        for (int k = 0; k < 4; k++) oacc[j][k] = 0.f;

    const int nIter = KL_ / 64;
    for (int it = 0; it < nIter; it++) {
        int s = it & 1;
        if (it + 1 < nIter) { load_kv(it + 1, s ^ 1); cpa_wait1(); }
        else                { cpa_wait0(); }
        __syncthreads();

        if (it == 0) {
#pragma unroll
            for (int kd = 0; kd < 8; kd++)
                ldsm4(qa[kd][0], qa[kd][1], qa[kd][2], qa[kd][3],
                      sb + FQ_OFF + (uint32_t)((wm16 * 136 + kd * 16) * 2) + aLaneQ);
        }

        // ---- S = Q @ K^T (warp: 16 x 32) ----
        uint32_t kst = sb + FK_OFF + (uint32_t)(s * 17408);
        float sacc[4][4];
#pragma unroll
        for (int j = 0; j < 4; j++)
#pragma unroll
            for (int k = 0; k < 4; k++) sacc[j][k] = 0.f;
#pragma unroll
        for (int kd = 0; kd < 8; kd++) {
#pragma unroll
            for (int j = 0; j < 4; j++) {
                uint32_t b0, b1;
                ldsm2(b0, b1, kst + (uint32_t)(((sn0 + j * 8) * 136 + kd * 16) * 2) + bLaneK);
                mma16816h(sacc[j], qa[kd][0], qa[kd][1], qa[kd][2], qa[kd][3], b0, b1);
            }
        }
#pragma unroll
        for (int j = 0; j < 4; j++) {
            int r = wm16 + (lane >> 2);
            int cidx = sn0 + j * 8 + (lane & 3) * 2;
            *(float2*)&Ss[r * 68 + cidx]       = make_float2(sacc[j][0], sacc[j][1]);
            *(float2*)&Ss[(r + 8) * 68 + cidx] = make_float2(sacc[j][2], sacc[j][3]);
        }
        __syncthreads();

        // ---- online softmax (4 threads per row), P fp16 ----
        {
            int row = tid >> 2, seg = tid & 3;
            float* sr = Ss + row * 68 + seg * 16;
            float tmax = sr[0];
#pragma unroll
            for (int c = 1; c < 16; c++) tmax = fmaxf(tmax, sr[c]);
            tmax = fmaxf(tmax, __shfl_xor_sync(0xffffffffu, tmax, 1));
            tmax = fmaxf(tmax, __shfl_xor_sync(0xffffffffu, tmax, 2));
            float mold = m_s[row];
            float mnew = fmaxf(mold, tmax);
            float corr = __expf(mold - mnew);
            __half* pr = (__half*)(smem + FP_OFF) + row * 72 + seg * 16;
            float sum = 0.f;
#pragma unroll
            for (int c = 0; c < 16; c++) {
                float p = __expf(sr[c] - mnew);
                __half ph = __float2half(p);
                pr[c] = ph;
                sum += __half2float(ph);   // self-normalizing: l over rounded P
            }
            sum += __shfl_xor_sync(0xffffffffu, sum, 1);
            sum += __shfl_xor_sync(0xffffffffu, sum, 2);
            if (seg == 0) {
                m_s[row] = mnew;
                l_s[row] = l_s[row] * corr + sum;
                c_s[row] = corr;
            }
        }
        __syncthreads();

        // ---- O = O*corr + P @ V (warp: 16 x 64) ----
        {
            float clo = c_s[wm16 + (lane >> 2)];
            float chi = c_s[wm16 + 8 + (lane >> 2)];
#pragma unroll
            for (int j = 0; j < 8; j++) {
                oacc[j][0] *= clo; oacc[j][1] *= clo;
                oacc[j][2] *= chi; oacc[j][3] *= chi;
            }
            uint32_t vst = sb + FV_OFF + (uint32_t)(s * 18432);
#pragma unroll
            for (int kk = 0; kk < 4; kk++) {
                uint32_t a0, a1, a2, a3;
                ldsm4(a0, a1, a2, a3,
                      sb + FP_OFF + (uint32_t)((wm16 * 72 + kk * 16) * 2) + aLaneP);
#pragma unroll
                for (int j = 0; j < 8; j++) {
                    uint32_t b0, b1;
                    ldsm2(b0, b1, vst + (uint32_t)(((on0 + j * 8) * 72 + kk * 16) * 2) + bLaneV);
                    mma16816h(oacc[j], a0, a1, a2, a3, b0, b1);
                }
            }
        }
        __syncthreads();
    }

    // epilogue: normalize, write attn fp16 [b, q, h*128 + d]
    {
        float ilo = 1.f / l_s[wm16 + (lane >> 2)];
        float ihi = 1.f / l_s[wm16 + 8 + (lane >> 2)];
        int r = q0 + wm16 + (lane >> 2);
#pragma unroll
        for (int j = 0; j < 8; j++) {
            int col = h * HD_ + on0 + j * 8 + (lane & 3) * 2;
            size_t o0 = (size_t)(b * QL_ + r) * (H_ * HD_) + col;
            size_t o1 = (size_t)(b * QL_ + r + 8) * (H_ * HD_) + col;
            *(__half2*)&outF[o0] = __floats2half2_rn(oacc[j][0] * ilo, oacc[j][1] * ilo);
            *(__half2*)&outF[o1] = __floats2half2_rn(oacc[j][2] * ihi, oacc[j][3] * ihi);
        }
    }
}

// ---------------------------------------------------------------------------
// Launch
// ---------------------------------------------------------------------------
extern "C" void kernel_launch(void* const* d_in, const int* in_sizes, int n_in,
                              void* d_out, int out_size)
{
    const float* x_q       = (const float*)d_in[0];
    const float* x_kv      = (const float*)d_in[1];
    const float* W_dQ      = (const float*)d_in[2];
    const float* q_norm_w  = (const float*)d_in[3];
    const float* W_uQ      = (const float*)d_in[4];
    const float* W_dKV     = (const float*)d_in[5];
    const float* kv_norm_w = (const float*)d_in[6];
    const float* W_ukv     = (const float*)d_in[7];
    const float* W_o       = (const float*)d_in[8];
    float* out = (float*)d_out;

    float *qlat, *ckv;
    cudaGetSymbolAddress((void**)&qlat, g_qlat);
    cudaGetSymbolAddress((void**)&ckv,  g_ckv);

    __half *xq16,*xkv16,*qn16,*ckvn16,*at16;
    __half *wdq,*wuq,*wdkv,*wukv,*wo;
    __half *qf,*kf,*vf;
    cudaGetSymbolAddress((void**)&xq16,  g_xq16);
    cudaGetSymbolAddress((void**)&xkv16, g_xkv16);
    cudaGetSymbolAddress((void**)&qn16,  g_qn16);
    cudaGetSymbolAddress((void**)&ckvn16,g_ckvn16);
    cudaGetSymbolAddress((void**)&at16,  g_at16);
    cudaGetSymbolAddress((void**)&wdq,   g_wdq16);
    cudaGetSymbolAddress((void**)&wuq,   g_wuq16);
    cudaGetSymbolAddress((void**)&wdkv,  g_wdkv16);
    cudaGetSymbolAddress((void**)&wukv,  g_wukv16);
    cudaGetSymbolAddress((void**)&wo,    g_wo16);
    cudaGetSymbolAddress((void**)&qf,    g_qf16);
    cudaGetSymbolAddress((void**)&kf,    g_kf16);
    cudaGetSymbolAddress((void**)&vf,    g_vf16);

    cudaFuncSetAttribute(gemm16,    cudaFuncAttributeMaxDynamicSharedMemorySize, GEMM_SMEM);
    cudaFuncSetAttribute(gemm16_q,  cudaFuncAttributeMaxDynamicSharedMemorySize, GEMM_SMEM);
    cudaFuncSetAttribute(gemm16_kv, cudaFuncAttributeMaxDynamicSharedMemorySize, GEMM_SMEM);
    cudaFuncSetAttribute(flash_fp16,cudaFuncAttributeMaxDynamicSharedMemorySize, FLASH_SMEM);

    const int M_q  = B_ * QL_;   // 2048
    const int M_kv = B_ * KL_;   // 8192
    dim3 t32x8(32, 8);

    // --- input casts + weight transposes (fp16) ---
    { int n4 = (M_q * HID_) / 4;  conv16<<<(n4+255)/256, 256>>>(x_q,  xq16,  n4); }
    { int n4 = (M_kv * HID_) / 4; conv16<<<(n4+255)/256, 256>>>(x_kv, xkv16, n4); }
    transpose16<<<dim3(QLR_/32, HID_/32), t32x8>>>(W_dQ, QLR_, 0, wdq, HID_, 0);
    transpose16_gather<<<dim3(2048/32, QLR_/32), t32x8>>>(W_uQ, wuq);
    transpose16<<<dim3(1024/32, HID_/32), t32x8>>>(W_dKV, 1088, 0, wdkv, HID_, 0);
    transpose16<<<dim3(1024/32, LAT_/32, G_), t32x8>>>(
        W_ukv, 1024, (long)LAT_*1024, wukv, LAT_, (long)1024*LAT_);
    transpose16<<<dim3(HID_/32, HID_/32), t32x8>>>(W_o, HID_, 0, wo, HID_, 0);

    // 1) q_lat = x_q @ W_dQ    [2048x2048] x [512x2048]^T  -> fp32
    gemm16<<<dim3(QLR_/128, M_q/128), 256, GEMM_SMEM>>>(
        xq16, HID_, wdq, HID_, qlat, QLR_, HID_);
    // 2) rmsnorm -> fp16
    rmsnorm_q16<<<M_q, 256>>>(qlat, q_norm_w, qn16);
    // 3) q fp16 = (qn @ W_uQ_gathered) * scale, laid out [bh][q][d]
    gemm16_q<<<dim3(2048/128, M_q/128), 256, GEMM_SMEM>>>(
        qn16, QLR_, wuq, QLR_, qf, QLR_);
    // 4) ckv = (x_kv @ W_dKV)[:, :1024] -> fp32
    gemm16<<<dim3(1024/128, M_kv/128), 256, GEMM_SMEM>>>(
        xkv16, HID_, wdkv, HID_, ckv, 1024, HID_);
    // 5) rmsnorm per (row, group) -> fp16
    rmsnorm_kv16<<<M_kv * G_, 256>>>(ckv, kv_norm_w, ckvn16);
    // 6) kv up-proj, fused epilogue -> K fp16 [bh][s][d] + V fp16 [bh][d][s]
    gemm16_kv<<<dim3(1024/128, M_kv/128, G_), 256, GEMM_SMEM>>>(
        ckvn16, G_*LAT_, LAT_,
        wukv, LAT_, (long)1024*LAT_,
        kf, vf, LAT_);
    // 7) fp16 flash attention -> attn fp16 [b, q, h*128+d]
    flash_fp16<<<dim3(QL_/64, B_*H_), 256, FLASH_SMEM>>>(qf, kf, vf, at16);
    // 8) out = attn @ W_o -> fp32
    gemm16<<<dim3(HID_/128, M_q/128), 256, GEMM_SMEM>>>(
        at16, H_*HD_, wo, HID_, out, HID_, H_*HD_);
}

// round 15
// speedup vs baseline: 10.2926x; 1.4969x over previous
#include <cuda_runtime.h>
#include <cuda_bf16.h>
#include <cuda_fp16.h>
#include <cstdint>

// ---------------------------------------------------------------------------
// GLACrossAttention: B=2 QL=1024 KL=4096 HID=2048 H=16 HD=128 RD=64
//                    G=4 HPG=4 QLR=512 LAT=256 EPS=1e-6
// Round 15: register-resident flash attention (FA2-style).
//   QT=128, warp = 16 rows x 64 keys: S and P live entirely in registers
//   (C-frag -> A-frag repack), softmax via shfl within 4-lane row groups,
//   3-stage K/V ring -> ONE __syncthreads per 64-key iteration.
//   GEMMs / fused epilogues unchanged from round 14 (single-pass fp16 mma).
// ---------------------------------------------------------------------------

#define B_    2
#define QL_   1024
#define KL_   4096
#define HID_  2048
#define H_    16
#define HD_   128
#define RD_   64
#define G_    4
#define QLR_  512
#define LAT_  256
#define EPS_  1e-6f

// ---------------------------------------------------------------------------
// PTX helpers (baseline PTX, legal on compute_103)
// ---------------------------------------------------------------------------
__device__ __forceinline__ uint32_t smem_u32(const void* p) {
    uint32_t a;
    asm("{ .reg .u64 t; cvta.to.shared.u64 t, %1; cvt.u32.u64 %0, t; }"
        : "=r"(a) : "l"(p));
    return a;
}
__device__ __forceinline__ void cpa16(uint32_t dst, const void* src) {
    asm volatile("cp.async.cg.shared.global [%0], [%1], 16;\n" :: "r"(dst), "l"(src));
}
__device__ __forceinline__ void cpa_commit() {
    asm volatile("cp.async.commit_group;\n" ::: "memory");
}
__device__ __forceinline__ void cpa_wait1() {
    asm volatile("cp.async.wait_group 1;\n" ::: "memory");
}
__device__ __forceinline__ void cpa_wait0() {
    asm volatile("cp.async.wait_group 0;\n" ::: "memory");
}
__device__ __forceinline__ void ldsm4(uint32_t& r0, uint32_t& r1, uint32_t& r2,
                                      uint32_t& r3, uint32_t addr) {
    asm volatile("ldmatrix.sync.aligned.m8n8.x4.shared.b16 {%0,%1,%2,%3}, [%4];"
        : "=r"(r0), "=r"(r1), "=r"(r2), "=r"(r3) : "r"(addr));
}
__device__ __forceinline__ void ldsm2(uint32_t& r0, uint32_t& r1, uint32_t addr) {
    asm volatile("ldmatrix.sync.aligned.m8n8.x2.shared.b16 {%0,%1}, [%2];"
        : "=r"(r0), "=r"(r1) : "r"(addr));
}
// D(16x8,f32) += A(16x16 fp16, row) * B(16x8 fp16, col)
__device__ __forceinline__ void mma16816h(float* c, uint32_t a0, uint32_t a1,
                                          uint32_t a2, uint32_t a3,
                                          uint32_t b0, uint32_t b1) {
    asm volatile("mma.sync.aligned.m16n8k16.row.col.f32.f16.f16.f32 "
        "{%0,%1,%2,%3}, {%4,%5,%6,%7}, {%8,%9}, {%0,%1,%2,%3};"
        : "+f"(c[0]), "+f"(c[1]), "+f"(c[2]), "+f"(c[3])
        : "r"(a0), "r"(a1), "r"(a2), "r"(a3), "r"(b0), "r"(b1));
}

// ---------------------------------------------------------------------------
// Scratch (device globals; allocation-free contract)
// ---------------------------------------------------------------------------
__device__ float g_qlat [B_*QL_*QLR_];
__device__ float g_ckv  [B_*KL_*G_*LAT_];
// fp16 activations
__device__ __half g_xq16  [B_*QL_*HID_];
__device__ __half g_xkv16 [B_*KL_*HID_];
__device__ __half g_qn16  [B_*QL_*QLR_];
__device__ __half g_ckvn16[B_*KL_*G_*LAT_];
__device__ __half g_at16  [B_*QL_*H_*HD_];
// fp16 transposed weights [N][K]
__device__ __half g_wdq16 [QLR_*HID_];
__device__ __half g_wuq16 [2048*QLR_];                 // gathered (RD cols dropped)
__device__ __half g_wdkv16[1024*HID_];
__device__ __half g_wukv16[G_*1024*LAT_];
__device__ __half g_wo16  [HID_*HID_];
// fp16 attention operands
__device__ __half g_qf16[(size_t)B_*H_*QL_*HD_];       // [bh][q][d], scale folded
__device__ __half g_kf16[(size_t)B_*H_*KL_*HD_];       // [bh][key][d]
__device__ __half g_vf16[(size_t)B_*H_*HD_*KL_];       // [bh][d][key] (transposed)

// ---------------------------------------------------------------------------
// fp32 -> fp16 cast, vectorized by 4
// ---------------------------------------------------------------------------
__global__ __launch_bounds__(256) void conv16(
    const float* __restrict__ src, __half* __restrict__ dst, int n4)
{
    int i = blockIdx.x * 256 + threadIdx.x;
    if (i >= n4) return;
    float4 v = ((const float4*)src)[i];
    ((__half2*)dst)[2*i]   = __floats2half2_rn(v.x, v.y);
    ((__half2*)dst)[2*i+1] = __floats2half2_rn(v.z, v.w);
}

// ---------------------------------------------------------------------------
// transpose: src fp32 [R, >=C] (ldS) -> dst fp16 [C, R] (ldD=R), batched
// ---------------------------------------------------------------------------
__global__ __launch_bounds__(256) void transpose16(
    const float* __restrict__ src, int ldS, long sBatch,
    __half* __restrict__ dst, int ldD, long dBatch)
{
    src += (long)blockIdx.z * sBatch;
    dst += (long)blockIdx.z * dBatch;
    __shared__ float t[32][33];
    const int tx = threadIdx.x, ty = threadIdx.y;
    const int c0 = blockIdx.x * 32, r0 = blockIdx.y * 32;
#pragma unroll
    for (int i = 0; i < 4; i++)
        t[ty + i * 8][tx] = src[(long)(r0 + ty + i * 8) * ldS + c0 + tx];
    __syncthreads();
#pragma unroll
    for (int i = 0; i < 4; i++)
        dst[(long)(c0 + ty + i * 8) * ldD + r0 + tx] = __float2half(t[tx][ty + i * 8]);
}

// ---------------------------------------------------------------------------
// transpose W_uQ keeping only used cols: dst row n'=h*128+d <- src col h*192+d.
// src [512][3072] -> dst [2048][512]. grid (2048/32, 512/32).
// ---------------------------------------------------------------------------
__global__ __launch_bounds__(256) void transpose16_gather(
    const float* __restrict__ src, __half* __restrict__ dst)
{
    __shared__ float t[32][33];
    const int tx = threadIdx.x, ty = threadIdx.y;
    const int c0 = blockIdx.x * 32, r0 = blockIdx.y * 32;
    const int scol0 = (c0 >> 7) * 192 + (c0 & 127);   // 32-block stays in one h
#pragma unroll
    for (int i = 0; i < 4; i++)
        t[ty + i * 8][tx] = src[(long)(r0 + ty + i * 8) * 3072 + scol0 + tx];
    __syncthreads();
#pragma unroll
    for (int i = 0; i < 4; i++)
        dst[(long)(c0 + ty + i * 8) * QLR_ + r0 + tx] = __float2half(t[tx][ty + i * 8]);
}

// ---------------------------------------------------------------------------
// fp16 single-pass GEMM: C[M,N] fp32 = A[M,K] @ B^T[N,K]
// Block 128x128, 8 warps (2m x 4n, warp tile 64x32), KC=32, 2-stage cp.async.
// ---------------------------------------------------------------------------
#define GSTR   40                    // smem row stride in fp16 (32 data + 8 pad)
#define G_OPB  (128*GSTR*2)          // 10240 B per operand tile
#define G_STG  (2*G_OPB)             // 20480 B per stage
#define GEMM_SMEM (2*G_STG)          // 40960 B

#define GEMM16_MAINLOOP()                                                       \
    const uint32_t aLane = (uint32_t)(((lane & 15) * GSTR + (lane >> 4) * 8) * 2); \
    const uint32_t bLane = (uint32_t)(((lane & 7) * GSTR + ((lane >> 3) & 1) * 8) * 2); \
    float acc[4][4][4];                                                         \
    _Pragma("unroll")                                                           \
    for (int i = 0; i < 4; i++)                                                 \
        _Pragma("unroll")                                                       \
        for (int j = 0; j < 4; j++)                                             \
            _Pragma("unroll")                                                   \
            for (int k = 0; k < 4; k++) acc[i][j][k] = 0.f;                     \
    const int nIter = K / 32;                                                   \
    auto load_stage = [&](int it, int s) {                                      \
        uint32_t st = sb + s * G_STG;                                           \
        int k0 = it * 32;                                                       \
        _Pragma("unroll")                                                       \
        for (int i = 0; i < 2; i++) {                                           \
            int idx = tid + i * 256;                                            \
            int r = idx >> 2, c = idx & 3;                                      \
            uint32_t so = (uint32_t)(r * (GSTR*2) + c * 16);                    \
            cpa16(st + so,         A + (size_t)(rowBase + r) * lda + k0 + c * 8); \
            cpa16(st + G_OPB + so, Bm + (size_t)(colBase + r) * ldb + k0 + c * 8); \
        }                                                                       \
        cpa_commit();                                                           \
    };                                                                          \
    load_stage(0, 0);                                                           \
    for (int it = 0; it < nIter; it++) {                                        \
        int s = it & 1;                                                         \
        if (it + 1 < nIter) { load_stage(it + 1, s ^ 1); cpa_wait1(); }         \
        else                { cpa_wait0(); }                                    \
        __syncthreads();                                                        \
        uint32_t st = sb + s * G_STG;                                           \
        _Pragma("unroll")                                                       \
        for (int kk = 0; kk < 2; kk++) {                                        \
            const int kof = kk * 16;                                            \
            uint32_t af[4][4];                                                  \
            _Pragma("unroll")                                                   \
            for (int i = 0; i < 4; i++)                                         \
                ldsm4(af[i][0], af[i][1], af[i][2], af[i][3],                   \
                      st + (uint32_t)(((m0 + i * 16) * GSTR + kof) * 2) + aLane); \
            _Pragma("unroll")                                                   \
            for (int j = 0; j < 4; j++) {                                       \
                uint32_t b0, b1;                                                \
                ldsm2(b0, b1, st + G_OPB +                                      \
                      (uint32_t)(((n0 + j * 8) * GSTR + kof) * 2) + bLane);     \
                _Pragma("unroll")                                               \
                for (int i = 0; i < 4; i++)                                     \
                    mma16816h(acc[i][j], af[i][0], af[i][1], af[i][2], af[i][3], b0, b1); \
            }                                                                   \
        }                                                                       \
        __syncthreads();                                                        \
    }

// --- variant 1: fp32 C output (qlat, ckv, final out) ---
__global__ __launch_bounds__(256)
void gemm16(const __half* __restrict__ A, int lda,
            const __half* __restrict__ Bm, int ldb,
            float* __restrict__ C, int ldc, int K)
{
    extern __shared__ __align__(16) char smem[];
    uint32_t sb = smem_u32(smem);
    const int tid = threadIdx.x, lane = tid & 31, wid = tid >> 5;
    const int m0 = (wid >> 2) * 64, n0 = (wid & 3) * 32;
    const int rowBase = blockIdx.y * 128, colBase = blockIdx.x * 128;

    GEMM16_MAINLOOP()

#pragma unroll
    for (int i = 0; i < 4; i++) {
        int r0 = rowBase + m0 + i * 16 + (lane >> 2);
#pragma unroll
        for (int j = 0; j < 4; j++) {
            int col = colBase + n0 + j * 8 + (lane & 3) * 2;
            *(float2*)&C[(size_t)r0 * ldc + col]       = make_float2(acc[i][j][0], acc[i][j][1]);
            *(float2*)&C[(size_t)(r0 + 8) * ldc + col] = make_float2(acc[i][j][2], acc[i][j][3]);
        }
    }
}

// --- variant 2: q epilogue -> fp16 [bh][q][d], softmax scale folded ---
__global__ __launch_bounds__(256)
void gemm16_q(const __half* __restrict__ A, int lda,
              const __half* __restrict__ Bm, int ldb,
              __half* __restrict__ Q, int K)
{
    extern __shared__ __align__(16) char smem[];
    uint32_t sb = smem_u32(smem);
    const int tid = threadIdx.x, lane = tid & 31, wid = tid >> 5;
    const int m0 = (wid >> 2) * 64, n0 = (wid & 3) * 32;
    const int rowBase = blockIdx.y * 128, colBase = blockIdx.x * 128;

    GEMM16_MAINLOOP()

    const float scale = 0.08838834764831845f;   // 1/sqrt(128)
    auto qmap = [](int r, int n) -> size_t {
        return ((size_t)(((r >> 10) << 4) + (n >> 7)) * QL_ + (r & 1023)) * HD_ + (n & 127);
    };
#pragma unroll
    for (int i = 0; i < 4; i++) {
        int r0 = rowBase + m0 + i * 16 + (lane >> 2);
#pragma unroll
        for (int j = 0; j < 4; j++) {
            int col = colBase + n0 + j * 8 + (lane & 3) * 2;
            *(__half2*)&Q[qmap(r0, col)] =
                __floats2half2_rn(acc[i][j][0] * scale, acc[i][j][1] * scale);
            *(__half2*)&Q[qmap(r0 + 8, col)] =
                __floats2half2_rn(acc[i][j][2] * scale, acc[i][j][3] * scale);
        }
    }
}

// --- variant 3: kv up-proj epilogue -> K fp16 [bh][s][d] / V fp16 [bh][d][s] ---
__global__ __launch_bounds__(256)
void gemm16_kv(const __half* __restrict__ A, int lda, long aBatch,
               const __half* __restrict__ Bm, int ldb, long bBatch,
               __half* __restrict__ Kd, __half* __restrict__ Vd, int K)
{
    extern __shared__ __align__(16) char smem[];
    uint32_t sb = smem_u32(smem);
    const int tid = threadIdx.x, lane = tid & 31, wid = tid >> 5;
    const int m0 = (wid >> 2) * 64, n0 = (wid & 3) * 32;
    const int rowBase = blockIdx.y * 128, colBase = blockIdx.x * 128;
    const int g = blockIdx.z;
    A  += (long)g * aBatch;
    Bm += (long)g * bBatch;

    GEMM16_MAINLOOP()

    const int h = g * 4 + (colBase >> 8);
    const bool isV = (colBase >> 7) & 1;
#pragma unroll
    for (int i = 0; i < 4; i++) {
        int r0 = rowBase + m0 + i * 16 + (lane >> 2);
        int b = r0 >> 12, s = r0 & 4095;
        int bh = b * H_ + h;
#pragma unroll
        for (int j = 0; j < 4; j++) {
            int col = colBase + n0 + j * 8 + (lane & 3) * 2;
            int dd = col & 127;
            if (!isV) {
                size_t o0 = ((size_t)bh * KL_ + s) * HD_ + dd;
                size_t o1 = ((size_t)bh * KL_ + s + 8) * HD_ + dd;
                *(__half2*)&Kd[o0] = __floats2half2_rn(acc[i][j][0], acc[i][j][1]);
                *(__half2*)&Kd[o1] = __floats2half2_rn(acc[i][j][2], acc[i][j][3]);
            } else {
                size_t base0 = ((size_t)bh * HD_ + dd) * KL_;
                size_t base1 = ((size_t)bh * HD_ + dd + 1) * KL_;
                Vd[base0 + s]     = __float2half(acc[i][j][0]);
                Vd[base1 + s]     = __float2half(acc[i][j][1]);
                Vd[base0 + s + 8] = __float2half(acc[i][j][2]);
                Vd[base1 + s + 8] = __float2half(acc[i][j][3]);
            }
        }
    }
}

// ---------------------------------------------------------------------------
// RMSNorm over 512 cols (q path) -> fp16. grid = B*QL, block 256.
// ---------------------------------------------------------------------------
__global__ __launch_bounds__(256) void rmsnorm_q16(
    const float* __restrict__ x, const float* __restrict__ w,
    __half* __restrict__ o)
{
    const float* p = x + (long)blockIdx.x * QLR_;
    const int t = threadIdx.x;
    float v0 = p[t], v1 = p[t + 256];
    __shared__ float red[256];
    red[t] = v0 * v0 + v1 * v1;
    __syncthreads();
    for (int s = 128; s > 0; s >>= 1) {
        if (t < s) red[t] += red[t + s];
        __syncthreads();
    }
    float inv = rsqrtf(red[0] * (1.f / QLR_) + EPS_);
    long base = (long)blockIdx.x * QLR_;
    o[base + t]       = __float2half(v0 * inv * w[t]);
    o[base + t + 256] = __float2half(v1 * inv * w[t + 256]);
}

// ---------------------------------------------------------------------------
// RMSNorm over LAT=256 per (row, group) -> fp16. grid = B*KL*G, block 256.
// ---------------------------------------------------------------------------
__global__ __launch_bounds__(256) void rmsnorm_kv16(
    const float* __restrict__ x, const float* __restrict__ w,
    __half* __restrict__ o)
{
    const int row = blockIdx.x >> 2;
    const int g   = blockIdx.x & 3;
    const long base = (long)row * (G_ * LAT_) + g * LAT_;
    const int t = threadIdx.x;
    float v = x[base + t];
    __shared__ float red[256];
    red[t] = v * v;
    __syncthreads();
    for (int s = 128; s > 0; s >>= 1) {
        if (t < s) red[t] += red[t + s];
        __syncthreads();
    }
    float inv = rsqrtf(red[0] * (1.f / LAT_) + EPS_);
    o[base + t] = __float2half(v * inv * w[g * LAT_ + t]);
}

// ---------------------------------------------------------------------------
// flash_fp16: register-resident flash attention (FA2-style).
// grid (QL/128, B*H), 256 threads (8 warps), warp = 16 rows x 64 keys.
// S and P never touch smem; softmax via shfl in 4-lane row groups.
// 3-stage K/V ring -> one __syncthreads per iteration.
// ---------------------------------------------------------------------------
#define FQ_OFF   0                      // Q  fp16 [128][136]      34816 B
#define FK_OFF   34816                  // K  fp16 [3][64][136]    52224 B
#define FV_OFF   (34816+52224)          // V  fp16 [3][128][72]    55296 B
#define FK_STG   17408
#define FV_STG   18432
#define FLASH_SMEM (34816+52224+55296)  // 142336 B

__global__ __launch_bounds__(256)
void flash_fp16(const __half* __restrict__ Qg,
                const __half* __restrict__ Kg,
                const __half* __restrict__ Vg,
                __half* __restrict__ outF)
{
    extern __shared__ __align__(16) char smem[];
    uint32_t sb = smem_u32(smem);

    const int tid = threadIdx.x, lane = tid & 31, wid = tid >> 5;
    const int bh = blockIdx.y;
    const int b = bh >> 4, h = bh & 15;
    const int q0 = blockIdx.x * 128;

    const __half* Qp = Qg + ((size_t)bh * QL_ + q0) * HD_;
    const __half* Kp = Kg + (size_t)bh * KL_ * HD_;
    const __half* Vp = Vg + (size_t)bh * HD_ * KL_;

    // Q tile 128x128 fp16, row stride 136 halves (272 B)
#pragma unroll
    for (int i = 0; i < 8; i++) {
        int idx = tid + i * 256;
        int r = idx >> 4, c = idx & 15;
        cpa16(sb + FQ_OFF + r * 272 + c * 16, Qp + (size_t)r * HD_ + c * 8);
    }

    auto load_kv = [&](int it) {
        int s = it % 3;
        int key0 = it * 64;
#pragma unroll
        for (int i = 0; i < 4; i++) {
            int idx = tid + i * 256;
            int r = idx >> 4, c = idx & 15;
            cpa16(sb + FK_OFF + (uint32_t)(s * FK_STG + r * 272 + c * 16),
                  Kp + (size_t)(key0 + r) * HD_ + c * 8);
        }
#pragma unroll
        for (int i = 0; i < 4; i++) {
            int idx = tid + i * 256;
            int r = idx >> 3, c = idx & 7;
            cpa16(sb + FV_OFF + (uint32_t)(s * FV_STG + r * 144 + c * 16),
                  Vp + (size_t)r * KL_ + key0 + c * 8);
        }
        cpa_commit();
    };

    load_kv(0);   // group 0: Q + K/V stage 0

    const int wm16 = wid * 16;   // warp's 16-row strip within the 128-q tile
    const uint32_t aLaneQ = (uint32_t)(((lane & 15) * 136 + (lane >> 4) * 8) * 2);
    const uint32_t bLaneK = (uint32_t)(((lane & 7) * 136 + ((lane >> 3) & 1) * 8) * 2);
    const uint32_t bLaneV = (uint32_t)(((lane & 7) * 72 + ((lane >> 3) & 1) * 8) * 2);

    uint32_t qa[8][4];           // Q frags: 16 rows x 128 d
    float oacc[16][4];           // O strip: 16 rows x 128 d
#pragma unroll
    for (int j = 0; j < 16; j++)
#pragma unroll
        for (int k = 0; k < 4; k++) oacc[j][k] = 0.f;
    float m0 = -1e30f, m1 = -1e30f, l0 = 0.f, l1 = 0.f;   // rows r, r+8

    const int nIter = KL_ / 64;
    for (int it = 0; it < nIter; it++) {
        const int s = it % 3;
        if (it + 1 < nIter) { load_kv(it + 1); cpa_wait1(); }
        else                { cpa_wait0(); }
        __syncthreads();     // stage s ready; 3-stage ring makes this the only sync

        if (it == 0) {       // Q frags persist in registers
#pragma unroll
            for (int kd = 0; kd < 8; kd++)
                ldsm4(qa[kd][0], qa[kd][1], qa[kd][2], qa[kd][3],
                      sb + FQ_OFF + (uint32_t)((wm16 * 136 + kd * 16) * 2) + aLaneQ);
        }

        // ---- S = Q @ K^T : warp strip 16 x 64, entirely in registers ----
        const uint32_t kst = sb + FK_OFF + (uint32_t)(s * FK_STG);
        float sacc[8][4];
#pragma unroll
        for (int j = 0; j < 8; j++)
#pragma unroll
            for (int k = 0; k < 4; k++) sacc[j][k] = 0.f;
#pragma unroll
        for (int kd = 0; kd < 8; kd++) {
#pragma unroll
            for (int j = 0; j < 8; j++) {
                uint32_t b0, b1;
                ldsm2(b0, b1, kst + (uint32_t)(((j * 8) * 136 + kd * 16) * 2) + bLaneK);
                mma16816h(sacc[j], qa[kd][0], qa[kd][1], qa[kd][2], qa[kd][3], b0, b1);
            }
        }

        // ---- online softmax in registers (4-lane row groups) ----
        float tm0 = -1e30f, tm1 = -1e30f;
#pragma unroll
        for (int j = 0; j < 8; j++) {
            tm0 = fmaxf(tm0, fmaxf(sacc[j][0], sacc[j][1]));
            tm1 = fmaxf(tm1, fmaxf(sacc[j][2], sacc[j][3]));
        }
        tm0 = fmaxf(tm0, __shfl_xor_sync(0xffffffffu, tm0, 1));
        tm0 = fmaxf(tm0, __shfl_xor_sync(0xffffffffu, tm0, 2));
        tm1 = fmaxf(tm1, __shfl_xor_sync(0xffffffffu, tm1, 1));
        tm1 = fmaxf(tm1, __shfl_xor_sync(0xffffffffu, tm1, 2));
        float mn0 = fmaxf(m0, tm0), mn1 = fmaxf(m1, tm1);
        float c0 = __expf(m0 - mn0), c1 = __expf(m1 - mn1);
        m0 = mn0; m1 = mn1;

        // P = exp(S - m), packed straight into A-fragments; l over rounded P
        uint32_t pa[4][4];
        float s0 = 0.f, s1 = 0.f;
#pragma unroll
        for (int kk = 0; kk < 4; kk++) {
            const int ja = 2 * kk, jb = 2 * kk + 1;
            __half2 h0 = __floats2half2_rn(__expf(sacc[ja][0] - mn0),
                                           __expf(sacc[ja][1] - mn0));
            __half2 h1 = __floats2half2_rn(__expf(sacc[ja][2] - mn1),
                                           __expf(sacc[ja][3] - mn1));
            __half2 h2 = __floats2half2_rn(__expf(sacc[jb][0] - mn0),
                                           __expf(sacc[jb][1] - mn0));
            __half2 h3 = __floats2half2_rn(__expf(sacc[jb][2] - mn1),
                                           __expf(sacc[jb][3] - mn1));
            pa[kk][0] = *(uint32_t*)&h0;
            pa[kk][1] = *(uint32_t*)&h1;
            pa[kk][2] = *(uint32_t*)&h2;
            pa[kk][3] = *(uint32_t*)&h3;
            float2 f;
            f = __half22float2(h0); s0 += f.x + f.y;
            f = __half22float2(h2); s0 += f.x + f.y;
            f = __half22float2(h1); s1 += f.x + f.y;
            f = __half22float2(h3); s1 += f.x + f.y;
        }
        s0 += __shfl_xor_sync(0xffffffffu, s0, 1);
        s0 += __shfl_xor_sync(0xffffffffu, s0, 2);
        s1 += __shfl_xor_sync(0xffffffffu, s1, 1);
        s1 += __shfl_xor_sync(0xffffffffu, s1, 2);
        l0 = l0 * c0 + s0;
        l1 = l1 * c1 + s1;

        // ---- O = O*corr + P @ V : warp strip 16 x 128 ----
#pragma unroll
        for (int j = 0; j < 16; j++) {
            oacc[j][0] *= c0; oacc[j][1] *= c0;
            oacc[j][2] *= c1; oacc[j][3] *= c1;
        }
        const uint32_t vst = sb + FV_OFF + (uint32_t)(s * FV_STG);
#pragma unroll
        for (int kk = 0; kk < 4; kk++) {
#pragma unroll
            for (int j = 0; j < 16; j++) {
                uint32_t b0, b1;
                ldsm2(b0, b1, vst + (uint32_t)(((j * 8) * 72 + kk * 16) * 2) + bLaneV);
                mma16816h(oacc[j], pa[kk][0], pa[kk][1], pa[kk][2], pa[kk][3], b0, b1);
            }
        }
        // no trailing sync: 3-stage ring tolerates <=1-body warp lag
    }

    // epilogue: normalize, write attn fp16 [b, q, h*128 + d]
    {
        float il0 = 1.f / l0, il1 = 1.f / l1;
        int r = q0 + wm16 + (lane >> 2);
#pragma unroll
        for (int j = 0; j < 16; j++) {
            int col = h * HD_ + j * 8 + (lane & 3) * 2;
            size_t o0 = (size_t)(b * QL_ + r) * (H_ * HD_) + col;
            size_t o1 = (size_t)(b * QL_ + r + 8) * (H_ * HD_) + col;
            *(__half2*)&outF[o0] = __floats2half2_rn(oacc[j][0] * il0, oacc[j][1] * il0);
            *(__half2*)&outF[o1] = __floats2half2_rn(oacc[j][2] * il1, oacc[j][3] * il1);
        }
    }
}

// ---------------------------------------------------------------------------
// Launch
// ---------------------------------------------------------------------------
extern "C" void kernel_launch(void* const* d_in, const int* in_sizes, int n_in,
                              void* d_out, int out_size)
{
    const float* x_q       = (const float*)d_in[0];
    const float* x_kv      = (const float*)d_in[1];
    const float* W_dQ      = (const float*)d_in[2];
    const float* q_norm_w  = (const float*)d_in[3];
    const float* W_uQ      = (const float*)d_in[4];
    const float* W_dKV     = (const float*)d_in[5];
    const float* kv_norm_w = (const float*)d_in[6];
    const float* W_ukv     = (const float*)d_in[7];
    const float* W_o       = (const float*)d_in[8];
    float* out = (float*)d_out;

    float *qlat, *ckv;
    cudaGetSymbolAddress((void**)&qlat, g_qlat);
    cudaGetSymbolAddress((void**)&ckv,  g_ckv);

    __half *xq16,*xkv16,*qn16,*ckvn16,*at16;
    __half *wdq,*wuq,*wdkv,*wukv,*wo;
    __half *qf,*kf,*vf;
    cudaGetSymbolAddress((void**)&xq16,  g_xq16);
    cudaGetSymbolAddress((void**)&xkv16, g_xkv16);
    cudaGetSymbolAddress((void**)&qn16,  g_qn16);
    cudaGetSymbolAddress((void**)&ckvn16,g_ckvn16);
    cudaGetSymbolAddress((void**)&at16,  g_at16);
    cudaGetSymbolAddress((void**)&wdq,   g_wdq16);
    cudaGetSymbolAddress((void**)&wuq,   g_wuq16);
    cudaGetSymbolAddress((void**)&wdkv,  g_wdkv16);
    cudaGetSymbolAddress((void**)&wukv,  g_wukv16);
    cudaGetSymbolAddress((void**)&wo,    g_wo16);
    cudaGetSymbolAddress((void**)&qf,    g_qf16);
    cudaGetSymbolAddress((void**)&kf,    g_kf16);
    cudaGetSymbolAddress((void**)&vf,    g_vf16);

    cudaFuncSetAttribute(gemm16,    cudaFuncAttributeMaxDynamicSharedMemorySize, GEMM_SMEM);
    cudaFuncSetAttribute(gemm16_q,  cudaFuncAttributeMaxDynamicSharedMemorySize, GEMM_SMEM);
    cudaFuncSetAttribute(gemm16_kv, cudaFuncAttributeMaxDynamicSharedMemorySize, GEMM_SMEM);
    cudaFuncSetAttribute(flash_fp16,cudaFuncAttributeMaxDynamicSharedMemorySize, FLASH_SMEM);

    const int M_q  = B_ * QL_;   // 2048
    const int M_kv = B_ * KL_;   // 8192
    dim3 t32x8(32, 8);

    // --- input casts + weight transposes (fp16) ---
    { int n4 = (M_q * HID_) / 4;  conv16<<<(n4+255)/256, 256>>>(x_q,  xq16,  n4); }
    { int n4 = (M_kv * HID_) / 4; conv16<<<(n4+255)/256, 256>>>(x_kv, xkv16, n4); }
    transpose16<<<dim3(QLR_/32, HID_/32), t32x8>>>(W_dQ, QLR_, 0, wdq, HID_, 0);
    transpose16_gather<<<dim3(2048/32, QLR_/32), t32x8>>>(W_uQ, wuq);
    transpose16<<<dim3(1024/32, HID_/32), t32x8>>>(W_dKV, 1088, 0, wdkv, HID_, 0);
    transpose16<<<dim3(1024/32, LAT_/32, G_), t32x8>>>(
        W_ukv, 1024, (long)LAT_*1024, wukv, LAT_, (long)1024*LAT_);
    transpose16<<<dim3(HID_/32, HID_/32), t32x8>>>(W_o, HID_, 0, wo, HID_, 0);

    // 1) q_lat = x_q @ W_dQ -> fp32
    gemm16<<<dim3(QLR_/128, M_q/128), 256, GEMM_SMEM>>>(
        xq16, HID_, wdq, HID_, qlat, QLR_, HID_);
    // 2) rmsnorm -> fp16
    rmsnorm_q16<<<M_q, 256>>>(qlat, q_norm_w, qn16);
    // 3) q fp16 = (qn @ W_uQ_gathered) * scale, laid out [bh][q][d]
    gemm16_q<<<dim3(2048/128, M_q/128), 256, GEMM_SMEM>>>(
        qn16, QLR_, wuq, QLR_, qf, QLR_);
    // 4) ckv = (x_kv @ W_dKV)[:, :1024] -> fp32
    gemm16<<<dim3(1024/128, M_kv/128), 256, GEMM_SMEM>>>(
        xkv16, HID_, wdkv, HID_, ckv, 1024, HID_);
    // 5) rmsnorm per (row, group) -> fp16
    rmsnorm_kv16<<<M_kv * G_, 256>>>(ckv, kv_norm_w, ckvn16);
    // 6) kv up-proj, fused epilogue -> K fp16 [bh][s][d] + V fp16 [bh][d][s]
    gemm16_kv<<<dim3(1024/128, M_kv/128, G_), 256, GEMM_SMEM>>>(
        ckvn16, G_*LAT_, LAT_,
        wukv, LAT_, (long)1024*LAT_,
        kf, vf, LAT_);
    // 7) register-resident fp16 flash attention -> attn fp16 [b, q, h*128+d]
    flash_fp16<<<dim3(QL_/128, B_*H_), 256, FLASH_SMEM>>>(qf, kf, vf, at16);
    // 8) out = attn @ W_o -> fp32
    gemm16<<<dim3(HID_/128, M_q/128), 256, GEMM_SMEM>>>(
        at16, H_*HD_, wo, HID_, out, HID_, H_*HD_);
}

// round 17
// speedup vs baseline: 11.1666x; 1.0849x over previous
#include <cuda_runtime.h>
#include <cuda_bf16.h>
#include <cuda_fp16.h>
#include <cstdint>

// ---------------------------------------------------------------------------
// GLACrossAttention: B=2 QL=1024 KL=4096 HID=2048 H=16 HD=128 RD=64
//                    G=4 HPG=4 QLR=512 LAT=256 EPS=1e-6
// Round 17: resubmit of round 16 (bench died to broker infra failure, same
//           signature as round 5; code audited clean - no ring race, ldsm4
//           lane mapping verified). Issue-efficiency experiment:
//   - ldmatrix x4 for B/K/V operand fragments (2 n8-tiles per ldsm)
//   - GEMM: 3-stage cp.async ring, ONE __syncthreads per 32-k iteration
//   Discriminates HMMA-pipe-bound vs issue/LDSM-bound mainloops.
// ---------------------------------------------------------------------------

#define B_    2
#define QL_   1024
#define KL_   4096
#define HID_  2048
#define H_    16
#define HD_   128
#define RD_   64
#define G_    4
#define QLR_  512
#define LAT_  256
#define EPS_  1e-6f

// ---------------------------------------------------------------------------
// PTX helpers (baseline PTX, legal on compute_103)
// ---------------------------------------------------------------------------
__device__ __forceinline__ uint32_t smem_u32(const void* p) {
    uint32_t a;
    asm("{ .reg .u64 t; cvta.to.shared.u64 t, %1; cvt.u32.u64 %0, t; }"
        : "=r"(a) : "l"(p));
    return a;
}
__device__ __forceinline__ void cpa16(uint32_t dst, const void* src) {
    asm volatile("cp.async.cg.shared.global [%0], [%1], 16;\n" :: "r"(dst), "l"(src));
}
__device__ __forceinline__ void cpa_commit() {
    asm volatile("cp.async.commit_group;\n" ::: "memory");
}
__device__ __forceinline__ void cpa_wait1() {
    asm volatile("cp.async.wait_group 1;\n" ::: "memory");
}
__device__ __forceinline__ void cpa_wait0() {
    asm volatile("cp.async.wait_group 0;\n" ::: "memory");
}
__device__ __forceinline__ void ldsm4(uint32_t& r0, uint32_t& r1, uint32_t& r2,
                                      uint32_t& r3, uint32_t addr) {
    asm volatile("ldmatrix.sync.aligned.m8n8.x4.shared.b16 {%0,%1,%2,%3}, [%4];"
        : "=r"(r0), "=r"(r1), "=r"(r2), "=r"(r3) : "r"(addr));
}
// D(16x8,f32) += A(16x16 fp16, row) * B(16x8 fp16, col)
__device__ __forceinline__ void mma16816h(float* c, uint32_t a0, uint32_t a1,
                                          uint32_t a2, uint32_t a3,
                                          uint32_t b0, uint32_t b1) {
    asm volatile("mma.sync.aligned.m16n8k16.row.col.f32.f16.f16.f32 "
        "{%0,%1,%2,%3}, {%4,%5,%6,%7}, {%8,%9}, {%0,%1,%2,%3};"
        : "+f"(c[0]), "+f"(c[1]), "+f"(c[2]), "+f"(c[3])
        : "r"(a0), "r"(a1), "r"(a2), "r"(a3), "r"(b0), "r"(b1));
}

// ---------------------------------------------------------------------------
// Scratch (device globals; allocation-free contract)
// ---------------------------------------------------------------------------
__device__ float g_qlat [B_*QL_*QLR_];
__device__ float g_ckv  [B_*KL_*G_*LAT_];
// fp16 activations
__device__ __half g_xq16  [B_*QL_*HID_];
__device__ __half g_xkv16 [B_*KL_*HID_];
__device__ __half g_qn16  [B_*QL_*QLR_];
__device__ __half g_ckvn16[B_*KL_*G_*LAT_];
__device__ __half g_at16  [B_*QL_*H_*HD_];
// fp16 transposed weights [N][K]
__device__ __half g_wdq16 [QLR_*HID_];
__device__ __half g_wuq16 [2048*QLR_];                 // gathered (RD cols dropped)
__device__ __half g_wdkv16[1024*HID_];
__device__ __half g_wukv16[G_*1024*LAT_];
__device__ __half g_wo16  [HID_*HID_];
// fp16 attention operands
__device__ __half g_qf16[(size_t)B_*H_*QL_*HD_];       // [bh][q][d], scale folded
__device__ __half g_kf16[(size_t)B_*H_*KL_*HD_];       // [bh][key][d]
__device__ __half g_vf16[(size_t)B_*H_*HD_*KL_];       // [bh][d][key] (transposed)

// ---------------------------------------------------------------------------
// fp32 -> fp16 cast, vectorized by 4
// ---------------------------------------------------------------------------
__global__ __launch_bounds__(256) void conv16(
    const float* __restrict__ src, __half* __restrict__ dst, int n4)
{
    int i = blockIdx.x * 256 + threadIdx.x;
    if (i >= n4) return;
    float4 v = ((const float4*)src)[i];
    ((__half2*)dst)[2*i]   = __floats2half2_rn(v.x, v.y);
    ((__half2*)dst)[2*i+1] = __floats2half2_rn(v.z, v.w);
}

// ---------------------------------------------------------------------------
// transpose: src fp32 [R, >=C] (ldS) -> dst fp16 [C, R] (ldD=R), batched
// ---------------------------------------------------------------------------
__global__ __launch_bounds__(256) void transpose16(
    const float* __restrict__ src, int ldS, long sBatch,
    __half* __restrict__ dst, int ldD, long dBatch)
{
    src += (long)blockIdx.z * sBatch;
    dst += (long)blockIdx.z * dBatch;
    __shared__ float t[32][33];
    const int tx = threadIdx.x, ty = threadIdx.y;
    const int c0 = blockIdx.x * 32, r0 = blockIdx.y * 32;
#pragma unroll
    for (int i = 0; i < 4; i++)
        t[ty + i * 8][tx] = src[(long)(r0 + ty + i * 8) * ldS + c0 + tx];
    __syncthreads();
#pragma unroll
    for (int i = 0; i < 4; i++)
        dst[(long)(c0 + ty + i * 8) * ldD + r0 + tx] = __float2half(t[tx][ty + i * 8]);
}

// ---------------------------------------------------------------------------
// transpose W_uQ keeping only used cols: dst row n'=h*128+d <- src col h*192+d.
// src [512][3072] -> dst [2048][512]. grid (2048/32, 512/32).
// ---------------------------------------------------------------------------
__global__ __launch_bounds__(256) void transpose16_gather(
    const float* __restrict__ src, __half* __restrict__ dst)
{
    __shared__ float t[32][33];
    const int tx = threadIdx.x, ty = threadIdx.y;
    const int c0 = blockIdx.x * 32, r0 = blockIdx.y * 32;
    const int scol0 = (c0 >> 7) * 192 + (c0 & 127);   // 32-block stays in one h
#pragma unroll
    for (int i = 0; i < 4; i++)
        t[ty + i * 8][tx] = src[(long)(r0 + ty + i * 8) * 3072 + scol0 + tx];
    __syncthreads();
#pragma unroll
    for (int i = 0; i < 4; i++)
        dst[(long)(c0 + ty + i * 8) * QLR_ + r0 + tx] = __float2half(t[tx][ty + i * 8]);
}

// ---------------------------------------------------------------------------
// fp16 single-pass GEMM: C[M,N] fp32 = A[M,K] @ B^T[N,K]
// Block 128x128, 8 warps (2m x 4n, warp tile 64x32), KC=32,
// 3-stage cp.async ring, ONE __syncthreads per iteration.
// B fragments via ldmatrix x4 (two n8 tiles per instruction).
// ---------------------------------------------------------------------------
#define GSTR   40                    // smem row stride in fp16 (32 data + 8 pad)
#define G_OPB  (128*GSTR*2)          // 10240 B per operand tile
#define G_STG  (2*G_OPB)             // 20480 B per stage
#define GEMM_SMEM (3*G_STG)          // 61440 B

#define GEMM16_MAINLOOP()                                                       \
    const uint32_t aLane = (uint32_t)(((lane & 15) * GSTR + (lane >> 4) * 8) * 2); \
    const uint32_t bLane4 = (uint32_t)((((lane & 7) + ((lane >> 4) & 1) * 8) * GSTR) * 2 \
                                       + ((lane >> 3) & 1) * 16);               \
    float acc[4][4][4];                                                         \
    _Pragma("unroll")                                                           \
    for (int i = 0; i < 4; i++)                                                 \
        _Pragma("unroll")                                                       \
        for (int j = 0; j < 4; j++)                                             \
            _Pragma("unroll")                                                   \
            for (int k = 0; k < 4; k++) acc[i][j][k] = 0.f;                     \
    const int nIter = K / 32;                                                   \
    auto load_stage = [&](int it, int s) {                                      \
        uint32_t st = sb + s * G_STG;                                           \
        int k0 = it * 32;                                                       \
        _Pragma("unroll")                                                       \
        for (int i = 0; i < 2; i++) {                                           \
            int idx = tid + i * 256;                                            \
            int r = idx >> 2, c = idx & 3;                                      \
            uint32_t so = (uint32_t)(r * (GSTR*2) + c * 16);                    \
            cpa16(st + so,         A + (size_t)(rowBase + r) * lda + k0 + c * 8); \
            cpa16(st + G_OPB + so, Bm + (size_t)(colBase + r) * ldb + k0 + c * 8); \
        }                                                                       \
        cpa_commit();                                                           \
    };                                                                          \
    load_stage(0, 0);                                                           \
    for (int it = 0; it < nIter; it++) {                                        \
        int s = it % 3;                                                         \
        if (it + 1 < nIter) { load_stage(it + 1, (it + 1) % 3); cpa_wait1(); }  \
        else                { cpa_wait0(); }                                    \
        __syncthreads();       /* 3-stage ring: single barrier per iter */      \
        uint32_t st = sb + s * G_STG;                                           \
        _Pragma("unroll")                                                       \
        for (int kk = 0; kk < 2; kk++) {                                        \
            const int kof = kk * 16;                                            \
            uint32_t af[4][4];                                                  \
            _Pragma("unroll")                                                   \
            for (int i = 0; i < 4; i++)                                         \
                ldsm4(af[i][0], af[i][1], af[i][2], af[i][3],                   \
                      st + (uint32_t)(((m0 + i * 16) * GSTR + kof) * 2) + aLane); \
            _Pragma("unroll")                                                   \
            for (int jp = 0; jp < 2; jp++) {                                    \
                uint32_t b0, b1, b2, b3;                                        \
                ldsm4(b0, b1, b2, b3, st + G_OPB +                              \
                      (uint32_t)(((n0 + jp * 16) * GSTR + kof) * 2) + bLane4);  \
                _Pragma("unroll")                                               \
                for (int i = 0; i < 4; i++) {                                   \
                    mma16816h(acc[i][jp*2],   af[i][0], af[i][1], af[i][2], af[i][3], b0, b1); \
                    mma16816h(acc[i][jp*2+1], af[i][0], af[i][1], af[i][2], af[i][3], b2, b3); \
                }                                                               \
            }                                                                   \
        }                                                                       \
    }

// --- variant 1: fp32 C output (qlat, ckv, final out) ---
__global__ __launch_bounds__(256)
void gemm16(const __half* __restrict__ A, int lda,
            const __half* __restrict__ Bm, int ldb,
            float* __restrict__ C, int ldc, int K)
{
    extern __shared__ __align__(16) char smem[];
    uint32_t sb = smem_u32(smem);
    const int tid = threadIdx.x, lane = tid & 31, wid = tid >> 5;
    const int m0 = (wid >> 2) * 64, n0 = (wid & 3) * 32;
    const int rowBase = blockIdx.y * 128, colBase = blockIdx.x * 128;

    GEMM16_MAINLOOP()

#pragma unroll
    for (int i = 0; i < 4; i++) {
        int r0 = rowBase + m0 + i * 16 + (lane >> 2);
#pragma unroll
        for (int j = 0; j < 4; j++) {
            int col = colBase + n0 + j * 8 + (lane & 3) * 2;
            *(float2*)&C[(size_t)r0 * ldc + col]       = make_float2(acc[i][j][0], acc[i][j][1]);
            *(float2*)&C[(size_t)(r0 + 8) * ldc + col] = make_float2(acc[i][j][2], acc[i][j][3]);
        }
    }
}

// --- variant 2: q epilogue -> fp16 [bh][q][d], softmax scale folded ---
__global__ __launch_bounds__(256)
void gemm16_q(const __half* __restrict__ A, int lda,
              const __half* __restrict__ Bm, int ldb,
              __half* __restrict__ Q, int K)
{
    extern __shared__ __align__(16) char smem[];
    uint32_t sb = smem_u32(smem);
    const int tid = threadIdx.x, lane = tid & 31, wid = tid >> 5;
    const int m0 = (wid >> 2) * 64, n0 = (wid & 3) * 32;
    const int rowBase = blockIdx.y * 128, colBase = blockIdx.x * 128;

    GEMM16_MAINLOOP()

    const float scale = 0.08838834764831845f;   // 1/sqrt(128)
    auto qmap = [](int r, int n) -> size_t {
        return ((size_t)(((r >> 10) << 4) + (n >> 7)) * QL_ + (r & 1023)) * HD_ + (n & 127);
    };
#pragma unroll
    for (int i = 0; i < 4; i++) {
        int r0 = rowBase + m0 + i * 16 + (lane >> 2);
#pragma unroll
        for (int j = 0; j < 4; j++) {
            int col = colBase + n0 + j * 8 + (lane & 3) * 2;
            *(__half2*)&Q[qmap(r0, col)] =
                __floats2half2_rn(acc[i][j][0] * scale, acc[i][j][1] * scale);
            *(__half2*)&Q[qmap(r0 + 8, col)] =
                __floats2half2_rn(acc[i][j][2] * scale, acc[i][j][3] * scale);
        }
    }
}

// --- variant 3: kv up-proj epilogue -> K fp16 [bh][s][d] / V fp16 [bh][d][s] ---
__global__ __launch_bounds__(256)
void gemm16_kv(const __half* __restrict__ A, int lda, long aBatch,
               const __half* __restrict__ Bm, int ldb, long bBatch,
               __half* __restrict__ Kd, __half* __restrict__ Vd, int K)
{
    extern __shared__ __align__(16) char smem[];
    uint32_t sb = smem_u32(smem);
    const int tid = threadIdx.x, lane = tid & 31, wid = tid >> 5;
    const int m0 = (wid >> 2) * 64, n0 = (wid & 3) * 32;
    const int rowBase = blockIdx.y * 128, colBase = blockIdx.x * 128;
    const int g = blockIdx.z;
    A  += (long)g * aBatch;
    Bm += (long)g * bBatch;

    GEMM16_MAINLOOP()

    const int h = g * 4 + (colBase >> 8);
    const bool isV = (colBase >> 7) & 1;
#pragma unroll
    for (int i = 0; i < 4; i++) {
        int r0 = rowBase + m0 + i * 16 + (lane >> 2);
        int b = r0 >> 12, s = r0 & 4095;
        int bh = b * H_ + h;
#pragma unroll
        for (int j = 0; j < 4; j++) {
            int col = colBase + n0 + j * 8 + (lane & 3) * 2;
            int dd = col & 127;
            if (!isV) {
                size_t o0 = ((size_t)bh * KL_ + s) * HD_ + dd;
                size_t o1 = ((size_t)bh * KL_ + s + 8) * HD_ + dd;
                *(__half2*)&Kd[o0] = __floats2half2_rn(acc[i][j][0], acc[i][j][1]);
                *(__half2*)&Kd[o1] = __floats2half2_rn(acc[i][j][2], acc[i][j][3]);
            } else {
                size_t base0 = ((size_t)bh * HD_ + dd) * KL_;
                size_t base1 = ((size_t)bh * HD_ + dd + 1) * KL_;
                Vd[base0 + s]     = __float2half(acc[i][j][0]);
                Vd[base1 + s]     = __float2half(acc[i][j][1]);
                Vd[base0 + s + 8] = __float2half(acc[i][j][2]);
                Vd[base1 + s + 8] = __float2half(acc[i][j][3]);
            }
        }
    }
}

// ---------------------------------------------------------------------------
// RMSNorm over 512 cols (q path) -> fp16. grid = B*QL, block 256.
// ---------------------------------------------------------------------------
__global__ __launch_bounds__(256) void rmsnorm_q16(
    const float* __restrict__ x, const float* __restrict__ w,
    __half* __restrict__ o)
{
    const float* p = x + (long)blockIdx.x * QLR_;
    const int t = threadIdx.x;
    float v0 = p[t], v1 = p[t + 256];
    __shared__ float red[256];
    red[t] = v0 * v0 + v1 * v1;
    __syncthreads();
    for (int s = 128; s > 0; s >>= 1) {
        if (t < s) red[t] += red[t + s];
        __syncthreads();
    }
    float inv = rsqrtf(red[0] * (1.f / QLR_) + EPS_);
    long base = (long)blockIdx.x * QLR_;
    o[base + t]       = __float2half(v0 * inv * w[t]);
    o[base + t + 256] = __float2half(v1 * inv * w[t + 256]);
}

// ---------------------------------------------------------------------------
// RMSNorm over LAT=256 per (row, group) -> fp16. grid = B*KL*G, block 256.
// ---------------------------------------------------------------------------
__global__ __launch_bounds__(256) void rmsnorm_kv16(
    const float* __restrict__ x, const float* __restrict__ w,
    __half* __restrict__ o)
{
    const int row = blockIdx.x >> 2;
    const int g   = blockIdx.x & 3;
    const long base = (long)row * (G_ * LAT_) + g * LAT_;
    const int t = threadIdx.x;
    float v = x[base + t];
    __shared__ float red[256];
    red[t] = v * v;
    __syncthreads();
    for (int s = 128; s > 0; s >>= 1) {
        if (t < s) red[t] += red[t + s];
        __syncthreads();
    }
    float inv = rsqrtf(red[0] * (1.f / LAT_) + EPS_);
    o[base + t] = __float2half(v * inv * w[g * LAT_ + t]);
}

// ---------------------------------------------------------------------------
// flash_fp16: register-resident flash attention (FA2-style).
// grid (QL/128, B*H), 256 threads (8 warps), warp = 16 rows x 64 keys.
// S and P never touch smem; softmax via shfl in 4-lane row groups.
// 3-stage K/V ring -> one __syncthreads per iteration.
// K/V fragments via ldmatrix x4 (two n8 tiles per instruction).
// ---------------------------------------------------------------------------
#define FQ_OFF   0                      // Q  fp16 [128][136]      34816 B
#define FK_OFF   34816                  // K  fp16 [3][64][136]    52224 B
#define FV_OFF   (34816+52224)          // V  fp16 [3][128][72]    55296 B
#define FK_STG   17408
#define FV_STG   18432
#define FLASH_SMEM (34816+52224+55296)  // 142336 B

__global__ __launch_bounds__(256)
void flash_fp16(const __half* __restrict__ Qg,
                const __half* __restrict__ Kg,
                const __half* __restrict__ Vg,
                __half* __restrict__ outF)
{
    extern __shared__ __align__(16) char smem[];
    uint32_t sb = smem_u32(smem);

    const int tid = threadIdx.x, lane = tid & 31, wid = tid >> 5;
    const int bh = blockIdx.y;
    const int b = bh >> 4, h = bh & 15;
    const int q0 = blockIdx.x * 128;

    const __half* Qp = Qg + ((size_t)bh * QL_ + q0) * HD_;
    const __half* Kp = Kg + (size_t)bh * KL_ * HD_;
    const __half* Vp = Vg + (size_t)bh * HD_ * KL_;

    // Q tile 128x128 fp16, row stride 136 halves (272 B)
#pragma unroll
    for (int i = 0; i < 8; i++) {
        int idx = tid + i * 256;
        int r = idx >> 4, c = idx & 15;
        cpa16(sb + FQ_OFF + r * 272 + c * 16, Qp + (size_t)r * HD_ + c * 8);
    }

    auto load_kv = [&](int it) {
        int s = it % 3;
        int key0 = it * 64;
#pragma unroll
        for (int i = 0; i < 4; i++) {
            int idx = tid + i * 256;
            int r = idx >> 4, c = idx & 15;
            cpa16(sb + FK_OFF + (uint32_t)(s * FK_STG + r * 272 + c * 16),
                  Kp + (size_t)(key0 + r) * HD_ + c * 8);
        }
#pragma unroll
        for (int i = 0; i < 4; i++) {
            int idx = tid + i * 256;
            int r = idx >> 3, c = idx & 7;
            cpa16(sb + FV_OFF + (uint32_t)(s * FV_STG + r * 144 + c * 16),
                  Vp + (size_t)r * KL_ + key0 + c * 8);
        }
        cpa_commit();
    };

    load_kv(0);   // group 0: Q + K/V stage 0

    const int wm16 = wid * 16;   // warp's 16-row strip within the 128-q tile
    const uint32_t aLaneQ  = (uint32_t)(((lane & 15) * 136 + (lane >> 4) * 8) * 2);
    const uint32_t bLaneK4 = (uint32_t)((((lane & 7) + ((lane >> 4) & 1) * 8) * 136) * 2
                                        + ((lane >> 3) & 1) * 16);
    const uint32_t bLaneV4 = (uint32_t)((((lane & 7) + ((lane >> 4) & 1) * 8) * 72) * 2
                                        + ((lane >> 3) & 1) * 16);

    uint32_t qa[8][4];           // Q frags: 16 rows x 128 d
    float oacc[16][4];           // O strip: 16 rows x 128 d
#pragma unroll
    for (int j = 0; j < 16; j++)
#pragma unroll
        for (int k = 0; k < 4; k++) oacc[j][k] = 0.f;
    float m0 = -1e30f, m1 = -1e30f, l0 = 0.f, l1 = 0.f;   // rows r, r+8

    const int nIter = KL_ / 64;
    for (int it = 0; it < nIter; it++) {
        const int s = it % 3;
        if (it + 1 < nIter) { load_kv(it + 1); cpa_wait1(); }
        else                { cpa_wait0(); }
        __syncthreads();     // stage s ready; 3-stage ring makes this the only sync

        if (it == 0) {       // Q frags persist in registers
#pragma unroll
            for (int kd = 0; kd < 8; kd++)
                ldsm4(qa[kd][0], qa[kd][1], qa[kd][2], qa[kd][3],
                      sb + FQ_OFF + (uint32_t)((wm16 * 136 + kd * 16) * 2) + aLaneQ);
        }

        // ---- S = Q @ K^T : warp strip 16 x 64, entirely in registers ----
        const uint32_t kst = sb + FK_OFF + (uint32_t)(s * FK_STG);
        float sacc[8][4];
#pragma unroll
        for (int j = 0; j < 8; j++)
#pragma unroll
            for (int k = 0; k < 4; k++) sacc[j][k] = 0.f;
#pragma unroll
        for (int kd = 0; kd < 8; kd++) {
#pragma unroll
            for (int jp = 0; jp < 4; jp++) {
                uint32_t b0, b1, b2, b3;
                ldsm4(b0, b1, b2, b3,
                      kst + (uint32_t)(((jp * 16) * 136 + kd * 16) * 2) + bLaneK4);
                mma16816h(sacc[jp*2],   qa[kd][0], qa[kd][1], qa[kd][2], qa[kd][3], b0, b1);
                mma16816h(sacc[jp*2+1], qa[kd][0], qa[kd][1], qa[kd][2], qa[kd][3], b2, b3);
            }
        }

        // ---- online softmax in registers (4-lane row groups) ----
        float tm0 = -1e30f, tm1 = -1e30f;
#pragma unroll
        for (int j = 0; j < 8; j++) {
            tm0 = fmaxf(tm0, fmaxf(sacc[j][0], sacc[j][1]));
            tm1 = fmaxf(tm1, fmaxf(sacc[j][2], sacc[j][3]));
        }
        tm0 = fmaxf(tm0, __shfl_xor_sync(0xffffffffu, tm0, 1));
        tm0 = fmaxf(tm0, __shfl_xor_sync(0xffffffffu, tm0, 2));
        tm1 = fmaxf(tm1, __shfl_xor_sync(0xffffffffu, tm1, 1));
        tm1 = fmaxf(tm1, __shfl_xor_sync(0xffffffffu, tm1, 2));
        float mn0 = fmaxf(m0, tm0), mn1 = fmaxf(m1, tm1);
        float c0 = __expf(m0 - mn0), c1 = __expf(m1 - mn1);
        m0 = mn0; m1 = mn1;

        // P = exp(S - m), packed straight into A-fragments; l over rounded P
        uint32_t pa[4][4];
        float s0 = 0.f, s1 = 0.f;
#pragma unroll
        for (int kk = 0; kk < 4; kk++) {
            const int ja = 2 * kk, jb = 2 * kk + 1;
            __half2 h0 = __floats2half2_rn(__expf(sacc[ja][0] - mn0),
                                           __expf(sacc[ja][1] - mn0));
            __half2 h1 = __floats2half2_rn(__expf(sacc[ja][2] - mn1),
                                           __expf(sacc[ja][3] - mn1));
            __half2 h2 = __floats2half2_rn(__expf(sacc[jb][0] - mn0),
                                           __expf(sacc[jb][1] - mn0));
            __half2 h3 = __floats2half2_rn(__expf(sacc[jb][2] - mn1),
                                           __expf(sacc[jb][3] - mn1));
            pa[kk][0] = *(uint32_t*)&h0;
            pa[kk][1] = *(uint32_t*)&h1;
            pa[kk][2] = *(uint32_t*)&h2;
            pa[kk][3] = *(uint32_t*)&h3;
            float2 f;
            f = __half22float2(h0); s0 += f.x + f.y;
            f = __half22float2(h2); s0 += f.x + f.y;
            f = __half22float2(h1); s1 += f.x + f.y;
            f = __half22float2(h3); s1 += f.x + f.y;
        }
        s0 += __shfl_xor_sync(0xffffffffu, s0, 1);
        s0 += __shfl_xor_sync(0xffffffffu, s0, 2);
        s1 += __shfl_xor_sync(0xffffffffu, s1, 1);
        s1 += __shfl_xor_sync(0xffffffffu, s1, 2);
        l0 = l0 * c0 + s0;
        l1 = l1 * c1 + s1;

        // ---- O = O*corr + P @ V : warp strip 16 x 128 ----
#pragma unroll
        for (int j = 0; j < 16; j++) {
            oacc[j][0] *= c0; oacc[j][1] *= c0;
            oacc[j][2] *= c1; oacc[j][3] *= c1;
        }
        const uint32_t vst = sb + FV_OFF + (uint32_t)(s * FV_STG);
#pragma unroll
        for (int kk = 0; kk < 4; kk++) {
#pragma unroll
            for (int jp = 0; jp < 8; jp++) {
                uint32_t b0, b1, b2, b3;
                ldsm4(b0, b1, b2, b3,
                      vst + (uint32_t)(((jp * 16) * 72 + kk * 16) * 2) + bLaneV4);
                mma16816h(oacc[jp*2],   pa[kk][0], pa[kk][1], pa[kk][2], pa[kk][3], b0, b1);
                mma16816h(oacc[jp*2+1], pa[kk][0], pa[kk][1], pa[kk][2], pa[kk][3], b2, b3);
            }
        }
        // no trailing sync: 3-stage ring tolerates <=1-body warp lag
    }

    // epilogue: normalize, write attn fp16 [b, q, h*128 + d]
    {
        float il0 = 1.f / l0, il1 = 1.f / l1;
        int r = q0 + wm16 + (lane >> 2);
#pragma unroll
        for (int j = 0; j < 16; j++) {
            int col = h * HD_ + j * 8 + (lane & 3) * 2;
            size_t o0 = (size_t)(b * QL_ + r) * (H_ * HD_) + col;
            size_t o1 = (size_t)(b * QL_ + r + 8) * (H_ * HD_) + col;
            *(__half2*)&outF[o0] = __floats2half2_rn(oacc[j][0] * il0, oacc[j][1] * il0);
            *(__half2*)&outF[o1] = __floats2half2_rn(oacc[j][2] * il1, oacc[j][3] * il1);
        }
    }
}

// ---------------------------------------------------------------------------
// Launch
// ---------------------------------------------------------------------------
extern "C" void kernel_launch(void* const* d_in, const int* in_sizes, int n_in,
                              void* d_out, int out_size)
{
    const float* x_q       = (const float*)d_in[0];
    const float* x_kv      = (const float*)d_in[1];
    const float* W_dQ      = (const float*)d_in[2];
    const float* q_norm_w  = (const float*)d_in[3];
    const float* W_uQ      = (const float*)d_in[4];
    const float* W_dKV     = (const float*)d_in[5];
    const float* kv_norm_w = (const float*)d_in[6];
    const float* W_ukv     = (const float*)d_in[7];
    const float* W_o       = (const float*)d_in[8];
    float* out = (float*)d_out;

    float *qlat, *ckv;
    cudaGetSymbolAddress((void**)&qlat, g_qlat);
    cudaGetSymbolAddress((void**)&ckv,  g_ckv);

    __half *xq16,*xkv16,*qn16,*ckvn16,*at16;
    __half *wdq,*wuq,*wdkv,*wukv,*wo;
    __half *qf,*kf,*vf;
    cudaGetSymbolAddress((void**)&xq16,  g_xq16);
    cudaGetSymbolAddress((void**)&xkv16, g_xkv16);
    cudaGetSymbolAddress((void**)&qn16,  g_qn16);
    cudaGetSymbolAddress((void**)&ckvn16,g_ckvn16);
    cudaGetSymbolAddress((void**)&at16,  g_at16);
    cudaGetSymbolAddress((void**)&wdq,   g_wdq16);
    cudaGetSymbolAddress((void**)&wuq,   g_wuq16);
    cudaGetSymbolAddress((void**)&wdkv,  g_wdkv16);
    cudaGetSymbolAddress((void**)&wukv,  g_wukv16);
    cudaGetSymbolAddress((void**)&wo,    g_wo16);
    cudaGetSymbolAddress((void**)&qf,    g_qf16);
    cudaGetSymbolAddress((void**)&kf,    g_kf16);
    cudaGetSymbolAddress((void**)&vf,    g_vf16);

    cudaFuncSetAttribute(gemm16,    cudaFuncAttributeMaxDynamicSharedMemorySize, GEMM_SMEM);
    cudaFuncSetAttribute(gemm16_q,  cudaFuncAttributeMaxDynamicSharedMemorySize, GEMM_SMEM);
    cudaFuncSetAttribute(gemm16_kv, cudaFuncAttributeMaxDynamicSharedMemorySize, GEMM_SMEM);
    cudaFuncSetAttribute(flash_fp16,cudaFuncAttributeMaxDynamicSharedMemorySize, FLASH_SMEM);

    const int M_q  = B_ * QL_;   // 2048
    const int M_kv = B_ * KL_;   // 8192
    dim3 t32x8(32, 8);

    // --- input casts + weight transposes (fp16) ---
    { int n4 = (M_q * HID_) / 4;  conv16<<<(n4+255)/256, 256>>>(x_q,  xq16,  n4); }
    { int n4 = (M_kv * HID_) / 4; conv16<<<(n4+255)/256, 256>>>(x_kv, xkv16, n4); }
    transpose16<<<dim3(QLR_/32, HID_/32), t32x8>>>(W_dQ, QLR_, 0, wdq, HID_, 0);
    transpose16_gather<<<dim3(2048/32, QLR_/32), t32x8>>>(W_uQ, wuq);
    transpose16<<<dim3(1024/32, HID_/32), t32x8>>>(W_dKV, 1088, 0, wdkv, HID_, 0);
    transpose16<<<dim3(1024/32, LAT_/32, G_), t32x8>>>(
        W_ukv, 1024, (long)LAT_*1024, wukv, LAT_, (long)1024*LAT_);
    transpose16<<<dim3(HID_/32, HID_/32), t32x8>>>(W_o, HID_, 0, wo, HID_, 0);

    // 1) q_lat = x_q @ W_dQ -> fp32
    gemm16<<<dim3(QLR_/128, M_q/128), 256, GEMM_SMEM>>>(
        xq16, HID_, wdq, HID_, qlat, QLR_, HID_);
    // 2) rmsnorm -> fp16
    rmsnorm_q16<<<M_q, 256>>>(qlat, q_norm_w, qn16);
    // 3) q fp16 = (qn @ W_uQ_gathered) * scale, laid out [bh][q][d]
    gemm16_q<<<dim3(2048/128, M_q/128), 256, GEMM_SMEM>>>(
        qn16, QLR_, wuq, QLR_, qf, QLR_);
    // 4) ckv = (x_kv @ W_dKV)[:, :1024] -> fp32
    gemm16<<<dim3(1024/128, M_kv/128), 256, GEMM_SMEM>>>(
        xkv16, HID_, wdkv, HID_, ckv, 1024, HID_);
    // 5) rmsnorm per (row, group) -> fp16
    rmsnorm_kv16<<<M_kv * G_, 256>>>(ckv, kv_norm_w, ckvn16);
    // 6) kv up-proj, fused epilogue -> K fp16 [bh][s][d] + V fp16 [bh][d][s]
    gemm16_kv<<<dim3(1024/128, M_kv/128, G_), 256, GEMM_SMEM>>>(
        ckvn16, G_*LAT_, LAT_,
        wukv, LAT_, (long)1024*LAT_,
        kf, vf, LAT_);
    // 7) register-resident fp16 flash attention -> attn fp16 [b, q, h*128+d]
    flash_fp16<<<dim3(QL_/128, B_*H_), 256, FLASH_SMEM>>>(qf, kf, vf, at16);
    // 8) out = attn @ W_o -> fp32
    gemm16<<<dim3(HID_/128, M_q/128), 256, GEMM_SMEM>>>(
        at16, H_*HD_, wo, HID_, out, HID_, H_*HD_);
}